// round 6
// baseline (speedup 1.0000x reference)
#include <cuda_runtime.h>
#include <cuda_bf16.h>
#include <math.h>

#define V_   50000
#define C0_  2000
#define C1_  10000
#define E_   512
#define H_   1024
#define B_   32
#define T_   128
#define TS_  127
#define NR_  (B_*TS_)            // 4064
#define H3_  (3*H_)              // 3072
#define S1_  8000
#define S2_  40000

// ---------------- device scratch (statics are the allowed scratch path) ---
__device__ float g_xp[(size_t)TS_*H3_*B_];        // [t][gate-row][b]
__device__ float g_ht[2][H_*B_];                  // [k*32+b], double buffer
__device__ float g_out[(size_t)NR_*H_];           // [n][h]
__device__ float g_headlog[(size_t)NR_*(C0_+2)];
__device__ float g_proj1[(size_t)NR_*256];
__device__ float g_proj2[(size_t)NR_*64];
__device__ float g_head_lp[NR_];
__device__ float g_pmax[2][(size_t)NR_*32];
__device__ float g_psum[2][(size_t)NR_*32];
__device__ int   g_tgt[NR_];
__device__ int   g_valid[NR_];
__device__ int   g_list1[NR_];
__device__ int   g_list2[NR_];
__device__ int   g_cnt[2];
__device__ unsigned int g_bar;
__device__ int   g_is64x, g_is64l;

__device__ __forceinline__ int geti(const int* p, int i, int is64) {
    return p[is64 ? 2*i : i];
}

// ---------------- init ---------------------------------------------------
__global__ void init_kernel(const float* __restrict__ hidden,
                            const int* __restrict__ x,
                            const int* __restrict__ len) {
    int tid = threadIdx.x;
    if (tid == 0) {
        g_cnt[0] = 0; g_cnt[1] = 0; g_bar = 0u;
        g_is64x = (x[1] == 0 && x[3] == 0 && x[5] == 0) ? 1 : 0;
        g_is64l = (len[1] == 0) ? 1 : 0;
    }
    for (int i = tid; i < B_*H_; i += 256) {
        int k = i >> 5, b = i & 31;
        g_ht[0][i] = hidden[b*H_ + k];
    }
}

// ---------------- classify / compaction ----------------------------------
__global__ void classify_kernel(const int* __restrict__ x,
                                const int* __restrict__ len) {
    int n = blockIdx.x*256 + threadIdx.x;
    if (n >= NR_) return;
    int is64x = g_is64x, is64l = g_is64l;
    int b = n / TS_, t = n % TS_;
    int valid = (t < geti(len, b, is64l) - 1) ? 1 : 0;
    int tgt = geti(x, b*T_ + t + 1, is64x);
    g_valid[n] = valid;
    g_tgt[n]   = tgt;
    if (valid && tgt >= C0_) {
        int cl = (tgt < C1_) ? 0 : 1;
        int slot = atomicAdd(&g_cnt[cl], 1);
        if (cl == 0) g_list1[slot] = n; else g_list2[slot] = n;
    }
}

// ---------------- GEMM: C = A @ B^T --------------------------------------
// MODE 0: A row m (m=t*32+b) = emb[x[b][t]], K=512 -> g_xp[t][n][b] + b_ih[n]
// MODE 1: A=g_out K=1024 -> g_headlog (N=2002)   [tile-skip padding]
// MODE 2: A=g_out -> g_proj1 (N=256)             [tile-skip]
// MODE 3: A=g_out -> g_proj2 (N=64)              [tile-skip]
#define BM 128
#define BN 64
#define BK 16

template <int MODE>
__global__ void __launch_bounds__(256)
gemm_kernel(const float* __restrict__ Bmat, const float* __restrict__ bias,
            const int* __restrict__ x, const float* __restrict__ emb,
            const int* __restrict__ len, int M, int N, int K)
{
    __shared__ __align__(16) float As[BK][BM+4];
    __shared__ __align__(16) float Bs[BK][BN+4];

    int m0 = blockIdx.y * BM;
    int n0 = blockIdx.x * BN;
    int tid = threadIdx.x;
    int is64x = g_is64x, is64l = g_is64l;

    if (MODE != 0) {
        int pred = 0;
        if (tid < BM) {
            int m = m0 + tid;
            if (m < M) {
                int b = m / TS_, t = m % TS_;
                pred = (t < geti(len, b, is64l) - 1);
            }
        }
        if (!__syncthreads_or(pred)) return;
    }

    float acc[8][4];
#pragma unroll
    for (int i = 0; i < 8; i++)
#pragma unroll
        for (int j = 0; j < 4; j++) acc[i][j] = 0.f;

    int tm = tid >> 4;
    int tn = tid & 15;

    for (int kb = 0; kb < K; kb += BK) {
#pragma unroll
        for (int i = 0; i < 2; i++) {
            int f4 = tid*2 + i;
            int row = f4 >> 2;
            int kk  = (f4 & 3) * 4;
            float4 v = make_float4(0.f,0.f,0.f,0.f);
            int m = m0 + row;
            if (m < M) {
                if (MODE == 0) {
                    int t = m >> 5, b = m & 31;
                    int tok = geti(x, b*T_ + t, is64x);
                    v = *(const float4*)(emb + (size_t)tok*E_ + kb + kk);
                } else {
                    v = *(const float4*)(g_out + (size_t)m*K + kb + kk);
                }
            }
            As[kk+0][row]=v.x; As[kk+1][row]=v.y; As[kk+2][row]=v.z; As[kk+3][row]=v.w;
        }
        {
            int nrow = tid >> 2;
            int kk   = (tid & 3) * 4;
            float4 v = make_float4(0.f,0.f,0.f,0.f);
            int n = n0 + nrow;
            if (n < N) v = *(const float4*)(Bmat + (size_t)n*K + kb + kk);
            Bs[kk+0][nrow]=v.x; Bs[kk+1][nrow]=v.y; Bs[kk+2][nrow]=v.z; Bs[kk+3][nrow]=v.w;
        }
        __syncthreads();
#pragma unroll
        for (int k = 0; k < BK; k++) {
            float4 a0 = *(const float4*)&As[k][tm*8];
            float4 a1 = *(const float4*)&As[k][tm*8+4];
            float4 b0 = *(const float4*)&Bs[k][tn*4];
            float av[8] = {a0.x,a0.y,a0.z,a0.w,a1.x,a1.y,a1.z,a1.w};
            float bv[4] = {b0.x,b0.y,b0.z,b0.w};
#pragma unroll
            for (int i = 0; i < 8; i++)
#pragma unroll
                for (int j = 0; j < 4; j++)
                    acc[i][j] = fmaf(av[i], bv[j], acc[i][j]);
        }
        __syncthreads();
    }

#pragma unroll
    for (int i = 0; i < 8; i++) {
        int m = m0 + tm*8 + i;
        if (m >= M) continue;
#pragma unroll
        for (int j = 0; j < 4; j++) {
            int n = n0 + tn*4 + j;
            if (n >= N) continue;
            float v = acc[i][j];
            if (MODE == 0) {
                int t = m >> 5, b = m & 31;
                g_xp[((size_t)t*H3_ + n)*B_ + b] = v + bias[n];
            } else if (MODE == 1) {
                g_headlog[(size_t)m*(C0_+2) + n] = v;
            } else if (MODE == 2) {
                g_proj1[(size_t)m*256 + n] = v;
            } else {
                g_proj2[(size_t)m*64 + n] = v;
            }
        }
    }
}

// ---------------- persistent GRU (128 blocks, grid barrier) --------------
__global__ void __launch_bounds__(256)
gru_kernel(const float* __restrict__ whh, const float* __restrict__ bhh,
           const int* __restrict__ len)
{
    extern __shared__ float hs[];            // [1024][32] = 128 KB
    int tid = threadIdx.x;
    int kl  = tid >> 5;                      // 0..7
    int b   = tid & 31;
    int j   = blockIdx.x*8 + kl;             // hidden column
    int len1 = geti(len, b, g_is64l) - 1;

    const float* wr = whh + (size_t)j*H_;
    const float* wz = whh + (size_t)(H_  + j)*H_;
    const float* wn = whh + (size_t)(2*H_+ j)*H_;
    float bR = bhh[j], bZ = bhh[H_+j], bN = bhh[2*H_+j];

    for (int t = 0; t < TS_; t++) {
        const float* hg = g_ht[t & 1];
        for (int i = tid*4; i < H_*B_; i += 1024)
            *(float4*)&hs[i] = *(const float4*)&hg[i];
        __syncthreads();

        float ar = bR, az = bZ, an = bN;
#pragma unroll 8
        for (int i = 0; i < H_; i += 4) {
            float4 w0 = *(const float4*)(wr + i);
            float4 w1 = *(const float4*)(wz + i);
            float4 w2 = *(const float4*)(wn + i);
            float h0 = hs[(i+0)*32+b], h1 = hs[(i+1)*32+b];
            float h2 = hs[(i+2)*32+b], h3 = hs[(i+3)*32+b];
            ar = fmaf(w0.x,h0, fmaf(w0.y,h1, fmaf(w0.z,h2, fmaf(w0.w,h3, ar))));
            az = fmaf(w1.x,h0, fmaf(w1.y,h1, fmaf(w1.z,h2, fmaf(w1.w,h3, az))));
            an = fmaf(w2.x,h0, fmaf(w2.y,h1, fmaf(w2.z,h2, fmaf(w2.w,h3, an))));
        }

        const float* xpb = g_xp + (size_t)t*H3_*B_;
        float xr = xpb[(size_t)(      j)*B_ + b];
        float xz = xpb[(size_t)(H_  + j)*B_ + b];
        float xn = xpb[(size_t)(2*H_+ j)*B_ + b];

        float r  = 1.f / (1.f + expf(-(xr + ar)));
        float z  = 1.f / (1.f + expf(-(xz + az)));
        float nn = tanhf(xn + r*an);
        float hp = hs[j*32 + b];
        float hnew = (1.f - z)*nn + z*hp;

        int valid = (t < len1);
        float hout = valid ? hnew : hp;
        g_ht[(t+1) & 1][j*32 + b] = hout;
        g_out[(size_t)(b*TS_ + t)*H_ + j] = valid ? hnew : 0.f;

        __threadfence();
        __syncthreads();
        if (tid == 0) {
            atomicAdd(&g_bar, 1u);
            unsigned goal = (unsigned)gridDim.x * (unsigned)(t+1);
            volatile unsigned* p = &g_bar;
            while (*p < goal) {}
            __threadfence();
        }
        __syncthreads();
    }
}

// ---------------- head log-softmax (per valid row) ------------------------
__global__ void __launch_bounds__(128)
head_lse_kernel()
{
    int n = blockIdx.x;
    if (!g_valid[n]) return;
    int tid = threadIdx.x;
    const float* lg = g_headlog + (size_t)n*(C0_+2);
    __shared__ float sm[4];

    float m = -1e30f;
    for (int i = tid; i < C0_+2; i += 128) m = fmaxf(m, lg[i]);
#pragma unroll
    for (int o = 16; o > 0; o >>= 1) m = fmaxf(m, __shfl_xor_sync(~0u, m, o));
    if ((tid & 31) == 0) sm[tid >> 5] = m;
    __syncthreads();
    m = fmaxf(fmaxf(sm[0], sm[1]), fmaxf(sm[2], sm[3]));

    float s = 0.f;
    for (int i = tid; i < C0_+2; i += 128) s += __expf(lg[i] - m);
#pragma unroll
    for (int o = 16; o > 0; o >>= 1) s += __shfl_xor_sync(~0u, s, o);
    if ((tid & 31) == 0) sm[tid >> 5] = s;
    __syncthreads();
    if (tid == 0) {
        s = sm[0] + sm[1] + sm[2] + sm[3];
        int tgt = g_tgt[n];
        int sel = (tgt < C0_) ? tgt : ((tgt < C1_) ? C0_ : C0_+1);
        g_head_lp[n] = lg[sel] - (m + logf(s));
    }
}

// ---------------- fused tail GEMM + online logsumexp ----------------------
// 64 compacted rows x one s-slab; per-slab (max,sum) partials.
template <int KD, int NSLAB>
__global__ void __launch_bounds__(256)
tail_gemm_kernel(const float* __restrict__ tmat, int cluster, int S)
{
    extern __shared__ float sm[];
    float* As = sm;                          // [KD][72]
    float* Bs = As + KD*72;                  // [64][72]
    float* Rm = Bs + 64*72;                  // [64][16]
    float* Rs = Rm + 64*16;

    int cnt = g_cnt[cluster];
    int r0 = blockIdx.y * 64;
    if (r0 >= cnt) return;
    int tid = threadIdx.x;
    const int*   list = cluster ? g_list2 : g_list1;
    const float* proj = cluster ? g_proj2 : g_proj1;

    for (int idx = tid; idx < 64*KD; idx += 256) {
        int r = idx / KD, k = idx % KD;
        float v = 0.f;
        if (r0 + r < cnt) v = proj[(size_t)list[r0+r]*KD + k];
        As[k*72 + r] = v;
    }
    __syncthreads();

    int tm = tid >> 4, tn = tid & 15;
    float rm[4], rs[4];
#pragma unroll
    for (int i = 0; i < 4; i++) { rm[i] = -1e30f; rs[i] = 0.f; }

    const int SLAB = S / NSLAB;
    const int SCH  = SLAB / 64;
    int sbase = blockIdx.x * SLAB;

    for (int sc = 0; sc < SCH; sc++) {
        int s0 = sbase + sc*64;
        float acc[4][4];
#pragma unroll
        for (int i = 0; i < 4; i++)
#pragma unroll
            for (int jj = 0; jj < 4; jj++) acc[i][jj] = 0.f;

        for (int kc = 0; kc < KD; kc += 64) {
            for (int idx = tid; idx < 1024; idx += 256) {
                int srow = idx >> 4;
                int c4   = idx & 15;
                float4 v = *(const float4*)(tmat + (size_t)(s0+srow)*KD + kc + c4*4);
                Bs[(c4*4+0)*72+srow]=v.x; Bs[(c4*4+1)*72+srow]=v.y;
                Bs[(c4*4+2)*72+srow]=v.z; Bs[(c4*4+3)*72+srow]=v.w;
            }
            __syncthreads();
#pragma unroll 8
            for (int k = 0; k < 64; k++) {
                float4 a = *(const float4*)&As[(kc+k)*72 + tm*4];
                float4 bv = *(const float4*)&Bs[k*72 + tn*4];
                float av[4] = {a.x,a.y,a.z,a.w};
                float bb[4] = {bv.x,bv.y,bv.z,bv.w};
#pragma unroll
                for (int i = 0; i < 4; i++)
#pragma unroll
                    for (int jj = 0; jj < 4; jj++)
                        acc[i][jj] = fmaf(av[i], bb[jj], acc[i][jj]);
            }
            __syncthreads();
        }
#pragma unroll
        for (int i = 0; i < 4; i++) {
            float vm = fmaxf(fmaxf(acc[i][0], acc[i][1]), fmaxf(acc[i][2], acc[i][3]));
            float nm = fmaxf(rm[i], vm);
            rs[i] = rs[i]*__expf(rm[i]-nm)
                  + __expf(acc[i][0]-nm) + __expf(acc[i][1]-nm)
                  + __expf(acc[i][2]-nm) + __expf(acc[i][3]-nm);
            rm[i] = nm;
        }
    }

#pragma unroll
    for (int i = 0; i < 4; i++) {
        Rm[(tm*4+i)*16 + tn] = rm[i];
        Rs[(tm*4+i)*16 + tn] = rs[i];
    }
    __syncthreads();
    if (tid < 64) {
        float m = -1e30f;
#pragma unroll
        for (int c = 0; c < 16; c++) m = fmaxf(m, Rm[tid*16+c]);
        float s = 0.f;
#pragma unroll
        for (int c = 0; c < 16; c++) s += Rs[tid*16+c]*__expf(Rm[tid*16+c]-m);
        if (r0 + tid < cnt) {
            g_pmax[cluster][(size_t)(r0+tid)*32 + blockIdx.x] = m;
            g_psum[cluster][(size_t)(r0+tid)*32 + blockIdx.x] = s;
        }
    }
}

// ---------------- combine tail partials + target logit --------------------
__global__ void combine_kernel(const float* __restrict__ t1,
                               const float* __restrict__ t2)
{
    int cl = blockIdx.y;
    int slot = blockIdx.x*256 + threadIdx.x;
    if (slot >= g_cnt[cl]) return;
    int n = cl ? g_list2[slot] : g_list1[slot];
    int tgt = g_tgt[n];
    int KD = cl ? 64 : 256;
    int NS = cl ? 25 : 5;
    const float* pr = cl ? (g_proj2 + (size_t)n*64) : (g_proj1 + (size_t)n*256);
    const float* tr = cl ? (t2 + (size_t)(tgt - C1_)*64)
                         : (t1 + (size_t)(tgt - C0_)*256);
    float d = 0.f;
    for (int k = 0; k < KD; k++) d = fmaf(pr[k], tr[k], d);

    const float* pm = &g_pmax[cl][(size_t)slot*32];
    const float* ps = &g_psum[cl][(size_t)slot*32];
    float m = -1e30f;
    for (int s = 0; s < NS; s++) m = fmaxf(m, pm[s]);
    float su = 0.f;
    for (int s = 0; s < NS; s++) su += ps[s]*__expf(pm[s]-m);
    g_head_lp[n] += d - (m + logf(su));
}

// ---------------- final reduction + hT output -----------------------------
__global__ void finalize_kernel(float* __restrict__ out)
{
    __shared__ float sh[256];
    int tid = threadIdx.x;
    const float L2002 = logf(2002.0f);
    float acc = 0.f;
    for (int n = tid; n < NR_; n += 256)
        acc += g_valid[n] ? g_head_lp[n] : -L2002;
    sh[tid] = acc; __syncthreads();
    for (int s = 128; s > 0; s >>= 1) {
        if (tid < s) sh[tid] += sh[tid+s];
        __syncthreads();
    }
    if (tid == 0) out[0] = -sh[0] / (float)NR_;
    const float* hf = g_ht[1];        // after 127 steps
    for (int i = tid; i < H_*B_; i += 256) {
        int k = i >> 5, b = i & 31;
        out[1 + b*H_ + k] = hf[i];
    }
}

// ---------------- launcher ------------------------------------------------
extern "C" void kernel_launch(void* const* d_in, const int* in_sizes, int n_in,
                              void* d_out, int out_size)
{
    const int*   x      = (const int*)  d_in[0];
    const int*   len    = (const int*)  d_in[1];
    const float* hidden = (const float*)d_in[2];
    const float* emb    = (const float*)d_in[3];
    const float* w_ih   = (const float*)d_in[4];
    const float* w_hh   = (const float*)d_in[5];
    const float* b_ih   = (const float*)d_in[6];
    const float* b_hh   = (const float*)d_in[7];
    const float* head_w = (const float*)d_in[8];
    const float* p1     = (const float*)d_in[9];
    const float* t1     = (const float*)d_in[10];
    const float* p2     = (const float*)d_in[11];
    const float* t2     = (const float*)d_in[12];
    float* out = (float*)d_out;
    (void)in_sizes; (void)n_in; (void)out_size;

    size_t gru_sh  = (size_t)H_*B_*sizeof(float);                    // 128 KB
    size_t sh_t1   = (size_t)(256*72 + 64*72 + 2*64*16)*sizeof(float); // ~98 KB
    size_t sh_t2   = (size_t)( 64*72 + 64*72 + 2*64*16)*sizeof(float); // ~44 KB
    cudaFuncSetAttribute(gru_kernel, cudaFuncAttributeMaxDynamicSharedMemorySize, (int)gru_sh);
    cudaFuncSetAttribute(tail_gemm_kernel<256,5>,  cudaFuncAttributeMaxDynamicSharedMemorySize, (int)sh_t1);
    cudaFuncSetAttribute(tail_gemm_kernel<64,25>,  cudaFuncAttributeMaxDynamicSharedMemorySize, (int)sh_t2);

    init_kernel<<<1,256>>>(hidden, x, len);
    classify_kernel<<<(NR_+255)/256,256>>>(x, len);

    // xp = emb[x] @ w_ih^T + b_ih    (M=4064, N=3072, K=512)
    gemm_kernel<0><<<dim3(H3_/BN,(NR_+BM-1)/BM),256>>>(w_ih, b_ih, x, emb, len, NR_, H3_, E_);

    gru_kernel<<<H_/8,256,gru_sh>>>(w_hh, b_hh, len);

    // head / projections
    gemm_kernel<1><<<dim3((C0_+2+BN-1)/BN,(NR_+BM-1)/BM),256>>>(head_w, nullptr, nullptr, nullptr, len, NR_, C0_+2, H_);
    gemm_kernel<2><<<dim3(256/BN,(NR_+BM-1)/BM),256>>>(p1, nullptr, nullptr, nullptr, len, NR_, 256, H_);
    gemm_kernel<3><<<dim3(64/BN,(NR_+BM-1)/BM),256>>>(p2, nullptr, nullptr, nullptr, len, NR_, 64, H_);

    head_lse_kernel<<<NR_,128>>>();

    tail_gemm_kernel<256,5> <<<dim3(5, (NR_+63)/64),256,sh_t1>>>(t1, 0, S1_);
    tail_gemm_kernel<64,25> <<<dim3(25,(NR_+63)/64),256,sh_t2>>>(t2, 1, S2_);

    combine_kernel<<<dim3((NR_+255)/256,2),256>>>(t1, t2);
    finalize_kernel<<<1,256>>>(out);
}

// round 7
// speedup vs baseline: 1.0389x; 1.0389x over previous
#include <cuda_runtime.h>
#include <cuda_bf16.h>
#include <math.h>

#define V_   50000
#define C0_  2000
#define C1_  10000
#define E_   512
#define H_   1024
#define B_   32
#define T_   128
#define TS_  127
#define NR_  (B_*TS_)            // 4064
#define H3_  (3*H_)              // 3072
#define S1_  8000
#define S2_  40000

// ---------------- device scratch (statics are the allowed scratch path) ---
__device__ float g_xp[(size_t)TS_*H3_*B_];        // [t][gate-row][b]
__device__ float g_ht[2][H_*B_];                  // [k*32+b], double buffer
__device__ float g_out[(size_t)NR_*H_];           // [n][h]
__device__ float g_headlog[(size_t)NR_*(C0_+2)];
__device__ float g_proj1[(size_t)NR_*256];
__device__ float g_proj2[(size_t)NR_*64];
__device__ float g_head_lp[NR_];
__device__ float g_pmax[2][(size_t)NR_*32];
__device__ float g_psum[2][(size_t)NR_*32];
__device__ int   g_tgt[NR_];
__device__ int   g_valid[NR_];
__device__ int   g_list1[NR_];
__device__ int   g_list2[NR_];
__device__ int   g_cnt[2];
__device__ unsigned int g_bar;
__device__ int   g_is64x, g_is64l;

__device__ __forceinline__ int geti(const int* p, int i, int is64) {
    return p[is64 ? 2*i : i];
}

// ---------------- init ---------------------------------------------------
__global__ void init_kernel(const float* __restrict__ hidden,
                            const int* __restrict__ x,
                            const int* __restrict__ len) {
    int tid = threadIdx.x;
    if (tid == 0) {
        g_cnt[0] = 0; g_cnt[1] = 0; g_bar = 0u;
        g_is64x = (x[1] == 0 && x[3] == 0 && x[5] == 0) ? 1 : 0;
        g_is64l = (len[1] == 0) ? 1 : 0;
    }
    for (int i = tid; i < B_*H_; i += 256) {
        int k = i >> 5, b = i & 31;
        g_ht[0][i] = hidden[b*H_ + k];
    }
}

// ---------------- classify / compaction ----------------------------------
__global__ void classify_kernel(const int* __restrict__ x,
                                const int* __restrict__ len) {
    int n = blockIdx.x*256 + threadIdx.x;
    if (n >= NR_) return;
    int is64x = g_is64x, is64l = g_is64l;
    int b = n / TS_, t = n % TS_;
    int valid = (t < geti(len, b, is64l) - 1) ? 1 : 0;
    int tgt = geti(x, b*T_ + t + 1, is64x);
    g_valid[n] = valid;
    g_tgt[n]   = tgt;
    if (valid && tgt >= C0_) {
        int cl = (tgt < C1_) ? 0 : 1;
        int slot = atomicAdd(&g_cnt[cl], 1);
        if (cl == 0) g_list1[slot] = n; else g_list2[slot] = n;
    }
}

// ---------------- GEMM: C = A @ B^T --------------------------------------
// MODE 0: A row m (m=t*32+b) = emb[x[b][t]], K=512 -> g_xp[t][n][b] + b_ih[n]
// MODE 1: A=g_out K=1024 -> g_headlog (N=2002)   [tile-skip padding]
// MODE 2: A=g_out -> g_proj1 (N=256)             [tile-skip]
// MODE 3: A=g_out -> g_proj2 (N=64)              [tile-skip]
#define BM 128
#define BN 64
#define BK 16

template <int MODE>
__global__ void __launch_bounds__(256)
gemm_kernel(const float* __restrict__ Bmat, const float* __restrict__ bias,
            const int* __restrict__ x, const float* __restrict__ emb,
            const int* __restrict__ len, int M, int N, int K)
{
    __shared__ __align__(16) float As[BK][BM+4];
    __shared__ __align__(16) float Bs[BK][BN+4];

    int m0 = blockIdx.y * BM;
    int n0 = blockIdx.x * BN;
    int tid = threadIdx.x;
    int is64x = g_is64x, is64l = g_is64l;

    if (MODE != 0) {
        int pred = 0;
        if (tid < BM) {
            int m = m0 + tid;
            if (m < M) {
                int b = m / TS_, t = m % TS_;
                pred = (t < geti(len, b, is64l) - 1);
            }
        }
        if (!__syncthreads_or(pred)) return;
    }

    float acc[8][4];
#pragma unroll
    for (int i = 0; i < 8; i++)
#pragma unroll
        for (int j = 0; j < 4; j++) acc[i][j] = 0.f;

    int tm = tid >> 4;
    int tn = tid & 15;

    for (int kb = 0; kb < K; kb += BK) {
#pragma unroll
        for (int i = 0; i < 2; i++) {
            int f4 = tid*2 + i;
            int row = f4 >> 2;
            int kk  = (f4 & 3) * 4;
            float4 v = make_float4(0.f,0.f,0.f,0.f);
            int m = m0 + row;
            if (m < M) {
                if (MODE == 0) {
                    int t = m >> 5, b = m & 31;
                    int tok = geti(x, b*T_ + t, is64x);
                    v = *(const float4*)(emb + (size_t)tok*E_ + kb + kk);
                } else {
                    v = *(const float4*)(g_out + (size_t)m*K + kb + kk);
                }
            }
            As[kk+0][row]=v.x; As[kk+1][row]=v.y; As[kk+2][row]=v.z; As[kk+3][row]=v.w;
        }
        {
            int nrow = tid >> 2;
            int kk   = (tid & 3) * 4;
            float4 v = make_float4(0.f,0.f,0.f,0.f);
            int n = n0 + nrow;
            if (n < N) v = *(const float4*)(Bmat + (size_t)n*K + kb + kk);
            Bs[kk+0][nrow]=v.x; Bs[kk+1][nrow]=v.y; Bs[kk+2][nrow]=v.z; Bs[kk+3][nrow]=v.w;
        }
        __syncthreads();
#pragma unroll
        for (int k = 0; k < BK; k++) {
            float4 a0 = *(const float4*)&As[k][tm*8];
            float4 a1 = *(const float4*)&As[k][tm*8+4];
            float4 b0 = *(const float4*)&Bs[k][tn*4];
            float av[8] = {a0.x,a0.y,a0.z,a0.w,a1.x,a1.y,a1.z,a1.w};
            float bv[4] = {b0.x,b0.y,b0.z,b0.w};
#pragma unroll
            for (int i = 0; i < 8; i++)
#pragma unroll
                for (int j = 0; j < 4; j++)
                    acc[i][j] = fmaf(av[i], bv[j], acc[i][j]);
        }
        __syncthreads();
    }

#pragma unroll
    for (int i = 0; i < 8; i++) {
        int m = m0 + tm*8 + i;
        if (m >= M) continue;
#pragma unroll
        for (int j = 0; j < 4; j++) {
            int n = n0 + tn*4 + j;
            if (n >= N) continue;
            float v = acc[i][j];
            if (MODE == 0) {
                int t = m >> 5, b = m & 31;
                g_xp[((size_t)t*H3_ + n)*B_ + b] = v + bias[n];
            } else if (MODE == 1) {
                g_headlog[(size_t)m*(C0_+2) + n] = v;
            } else if (MODE == 2) {
                g_proj1[(size_t)m*256 + n] = v;
            } else {
                g_proj2[(size_t)m*64 + n] = v;
            }
        }
    }
}

// ---------------- persistent GRU (128 blocks, grid barrier) --------------
__global__ void __launch_bounds__(256)
gru_kernel(const float* __restrict__ whh, const float* __restrict__ bhh,
           const int* __restrict__ len)
{
    extern __shared__ float hs[];            // [1024][32] = 128 KB
    int tid = threadIdx.x;
    int kl  = tid >> 5;                      // 0..7
    int b   = tid & 31;
    int j   = blockIdx.x*8 + kl;             // hidden column
    int len1 = geti(len, b, g_is64l) - 1;

    const float* wr = whh + (size_t)j*H_;
    const float* wz = whh + (size_t)(H_  + j)*H_;
    const float* wn = whh + (size_t)(2*H_+ j)*H_;
    float bR = bhh[j], bZ = bhh[H_+j], bN = bhh[2*H_+j];

    for (int t = 0; t < TS_; t++) {
        const float* hg = g_ht[t & 1];
        for (int i = tid*4; i < H_*B_; i += 1024)
            *(float4*)&hs[i] = *(const float4*)&hg[i];
        __syncthreads();

        float ar = bR, az = bZ, an = bN;
#pragma unroll 8
        for (int i = 0; i < H_; i += 4) {
            float4 w0 = *(const float4*)(wr + i);
            float4 w1 = *(const float4*)(wz + i);
            float4 w2 = *(const float4*)(wn + i);
            float h0 = hs[(i+0)*32+b], h1 = hs[(i+1)*32+b];
            float h2 = hs[(i+2)*32+b], h3 = hs[(i+3)*32+b];
            ar = fmaf(w0.x,h0, fmaf(w0.y,h1, fmaf(w0.z,h2, fmaf(w0.w,h3, ar))));
            az = fmaf(w1.x,h0, fmaf(w1.y,h1, fmaf(w1.z,h2, fmaf(w1.w,h3, az))));
            an = fmaf(w2.x,h0, fmaf(w2.y,h1, fmaf(w2.z,h2, fmaf(w2.w,h3, an))));
        }

        const float* xpb = g_xp + (size_t)t*H3_*B_;
        float xr = xpb[(size_t)(      j)*B_ + b];
        float xz = xpb[(size_t)(H_  + j)*B_ + b];
        float xn = xpb[(size_t)(2*H_+ j)*B_ + b];

        float r  = 1.f / (1.f + expf(-(xr + ar)));
        float z  = 1.f / (1.f + expf(-(xz + az)));
        float nn = tanhf(xn + r*an);
        float hp = hs[j*32 + b];
        float hnew = (1.f - z)*nn + z*hp;

        int valid = (t < len1);
        float hout = valid ? hnew : hp;
        g_ht[(t+1) & 1][j*32 + b] = hout;
        g_out[(size_t)(b*TS_ + t)*H_ + j] = valid ? hnew : 0.f;

        __threadfence();
        __syncthreads();
        if (tid == 0) {
            atomicAdd(&g_bar, 1u);
            unsigned goal = (unsigned)gridDim.x * (unsigned)(t+1);
            volatile unsigned* p = &g_bar;
            while (*p < goal) {}
            __threadfence();
        }
        __syncthreads();
    }
}

// ---------------- head log-softmax (per valid row) ------------------------
__global__ void __launch_bounds__(128)
head_lse_kernel()
{
    int n = blockIdx.x;
    if (!g_valid[n]) return;
    int tid = threadIdx.x;
    const float* lg = g_headlog + (size_t)n*(C0_+2);
    __shared__ float sm[4];

    float m = -1e30f;
    for (int i = tid; i < C0_+2; i += 128) m = fmaxf(m, lg[i]);
#pragma unroll
    for (int o = 16; o > 0; o >>= 1) m = fmaxf(m, __shfl_xor_sync(~0u, m, o));
    if ((tid & 31) == 0) sm[tid >> 5] = m;
    __syncthreads();
    m = fmaxf(fmaxf(sm[0], sm[1]), fmaxf(sm[2], sm[3]));

    float s = 0.f;
    for (int i = tid; i < C0_+2; i += 128) s += __expf(lg[i] - m);
#pragma unroll
    for (int o = 16; o > 0; o >>= 1) s += __shfl_xor_sync(~0u, s, o);
    if ((tid & 31) == 0) sm[tid >> 5] = s;
    __syncthreads();
    if (tid == 0) {
        s = sm[0] + sm[1] + sm[2] + sm[3];
        int tgt = g_tgt[n];
        int sel = (tgt < C0_) ? tgt : ((tgt < C1_) ? C0_ : C0_+1);
        g_head_lp[n] = lg[sel] - (m + logf(s));
    }
}

// ---------------- fused tail GEMM + online logsumexp ----------------------
// 64 compacted rows x one s-slab; per-slab (max,sum) partials.
template <int KD, int NSLAB>
__global__ void __launch_bounds__(256)
tail_gemm_kernel(const float* __restrict__ tmat, int cluster, int S)
{
    extern __shared__ float sm[];
    float* As = sm;                          // [KD][72]
    float* Bs = As + KD*72;                  // [64][72]
    float* Rm = Bs + 64*72;                  // [64][16]
    float* Rs = Rm + 64*16;

    int cnt = g_cnt[cluster];
    int r0 = blockIdx.y * 64;
    if (r0 >= cnt) return;
    int tid = threadIdx.x;
    const int*   list = cluster ? g_list2 : g_list1;
    const float* proj = cluster ? g_proj2 : g_proj1;

    for (int idx = tid; idx < 64*KD; idx += 256) {
        int r = idx / KD, k = idx % KD;
        float v = 0.f;
        if (r0 + r < cnt) v = proj[(size_t)list[r0+r]*KD + k];
        As[k*72 + r] = v;
    }
    __syncthreads();

    int tm = tid >> 4, tn = tid & 15;
    float rm[4], rs[4];
#pragma unroll
    for (int i = 0; i < 4; i++) { rm[i] = -1e30f; rs[i] = 0.f; }

    const int SLAB = S / NSLAB;
    const int SCH  = SLAB / 64;
    int sbase = blockIdx.x * SLAB;

    for (int sc = 0; sc < SCH; sc++) {
        int s0 = sbase + sc*64;
        float acc[4][4];
#pragma unroll
        for (int i = 0; i < 4; i++)
#pragma unroll
            for (int jj = 0; jj < 4; jj++) acc[i][jj] = 0.f;

        for (int kc = 0; kc < KD; kc += 64) {
            for (int idx = tid; idx < 1024; idx += 256) {
                int srow = idx >> 4;
                int c4   = idx & 15;
                float4 v = *(const float4*)(tmat + (size_t)(s0+srow)*KD + kc + c4*4);
                Bs[(c4*4+0)*72+srow]=v.x; Bs[(c4*4+1)*72+srow]=v.y;
                Bs[(c4*4+2)*72+srow]=v.z; Bs[(c4*4+3)*72+srow]=v.w;
            }
            __syncthreads();
#pragma unroll 8
            for (int k = 0; k < 64; k++) {
                float4 a = *(const float4*)&As[(kc+k)*72 + tm*4];
                float4 bv = *(const float4*)&Bs[k*72 + tn*4];
                float av[4] = {a.x,a.y,a.z,a.w};
                float bb[4] = {bv.x,bv.y,bv.z,bv.w};
#pragma unroll
                for (int i = 0; i < 4; i++)
#pragma unroll
                    for (int jj = 0; jj < 4; jj++)
                        acc[i][jj] = fmaf(av[i], bb[jj], acc[i][jj]);
            }
            __syncthreads();
        }
#pragma unroll
        for (int i = 0; i < 4; i++) {
            float vm = fmaxf(fmaxf(acc[i][0], acc[i][1]), fmaxf(acc[i][2], acc[i][3]));
            float nm = fmaxf(rm[i], vm);
            rs[i] = rs[i]*__expf(rm[i]-nm)
                  + __expf(acc[i][0]-nm) + __expf(acc[i][1]-nm)
                  + __expf(acc[i][2]-nm) + __expf(acc[i][3]-nm);
            rm[i] = nm;
        }
    }

#pragma unroll
    for (int i = 0; i < 4; i++) {
        Rm[(tm*4+i)*16 + tn] = rm[i];
        Rs[(tm*4+i)*16 + tn] = rs[i];
    }
    __syncthreads();
    if (tid < 64) {
        float m = -1e30f;
#pragma unroll
        for (int c = 0; c < 16; c++) m = fmaxf(m, Rm[tid*16+c]);
        float s = 0.f;
#pragma unroll
        for (int c = 0; c < 16; c++) s += Rs[tid*16+c]*__expf(Rm[tid*16+c]-m);
        if (r0 + tid < cnt) {
            g_pmax[cluster][(size_t)(r0+tid)*32 + blockIdx.x] = m;
            g_psum[cluster][(size_t)(r0+tid)*32 + blockIdx.x] = s;
        }
    }
}

// ---------------- combine tail partials + target logit --------------------
__global__ void combine_kernel(const float* __restrict__ t1,
                               const float* __restrict__ t2)
{
    int cl = blockIdx.y;
    int slot = blockIdx.x*256 + threadIdx.x;
    if (slot >= g_cnt[cl]) return;
    int n = cl ? g_list2[slot] : g_list1[slot];
    int tgt = g_tgt[n];
    int KD = cl ? 64 : 256;
    int NS = cl ? 25 : 5;
    const float* pr = cl ? (g_proj2 + (size_t)n*64) : (g_proj1 + (size_t)n*256);
    const float* tr = cl ? (t2 + (size_t)(tgt - C1_)*64)
                         : (t1 + (size_t)(tgt - C0_)*256);
    float d = 0.f;
    for (int k = 0; k < KD; k++) d = fmaf(pr[k], tr[k], d);

    const float* pm = &g_pmax[cl][(size_t)slot*32];
    const float* ps = &g_psum[cl][(size_t)slot*32];
    float m = -1e30f;
    for (int s = 0; s < NS; s++) m = fmaxf(m, pm[s]);
    float su = 0.f;
    for (int s = 0; s < NS; s++) su += ps[s]*__expf(pm[s]-m);
    g_head_lp[n] += d - (m + logf(su));
}

// ---------------- final reduction + hT output -----------------------------
__global__ void finalize_kernel(float* __restrict__ out)
{
    __shared__ float sh[256];
    int tid = threadIdx.x;
    const float L2002 = logf(2002.0f);
    float acc = 0.f;
    for (int n = tid; n < NR_; n += 256)
        acc += g_valid[n] ? g_head_lp[n] : -L2002;
    sh[tid] = acc; __syncthreads();
    for (int s = 128; s > 0; s >>= 1) {
        if (tid < s) sh[tid] += sh[tid+s];
        __syncthreads();
    }
    if (tid == 0) out[0] = -sh[0] / (float)NR_;
    const float* hf = g_ht[1];        // after 127 steps
    for (int i = tid; i < H_*B_; i += 256) {
        int k = i >> 5, b = i & 31;
        out[1 + b*H_ + k] = hf[i];
    }
}

// ---------------- launcher ------------------------------------------------
extern "C" void kernel_launch(void* const* d_in, const int* in_sizes, int n_in,
                              void* d_out, int out_size)
{
    const int*   x      = (const int*)  d_in[0];
    const int*   len    = (const int*)  d_in[1];
    const float* hidden = (const float*)d_in[2];
    const float* emb    = (const float*)d_in[3];
    const float* w_ih   = (const float*)d_in[4];
    const float* w_hh   = (const float*)d_in[5];
    const float* b_ih   = (const float*)d_in[6];
    const float* b_hh   = (const float*)d_in[7];
    const float* head_w = (const float*)d_in[8];
    const float* p1     = (const float*)d_in[9];
    const float* t1     = (const float*)d_in[10];
    const float* p2     = (const float*)d_in[11];
    const float* t2     = (const float*)d_in[12];
    float* out = (float*)d_out;
    (void)in_sizes; (void)n_in; (void)out_size;

    size_t gru_sh  = (size_t)H_*B_*sizeof(float);                    // 128 KB
    size_t sh_t1   = (size_t)(256*72 + 64*72 + 2*64*16)*sizeof(float); // ~98 KB
    size_t sh_t2   = (size_t)( 64*72 + 64*72 + 2*64*16)*sizeof(float); // ~44 KB
    cudaFuncSetAttribute(gru_kernel, cudaFuncAttributeMaxDynamicSharedMemorySize, (int)gru_sh);
    cudaFuncSetAttribute(tail_gemm_kernel<256,5>,  cudaFuncAttributeMaxDynamicSharedMemorySize, (int)sh_t1);
    cudaFuncSetAttribute(tail_gemm_kernel<64,25>,  cudaFuncAttributeMaxDynamicSharedMemorySize, (int)sh_t2);

    init_kernel<<<1,256>>>(hidden, x, len);
    classify_kernel<<<(NR_+255)/256,256>>>(x, len);

    // xp = emb[x] @ w_ih^T + b_ih    (M=4064, N=3072, K=512)
    gemm_kernel<0><<<dim3(H3_/BN,(NR_+BM-1)/BM),256>>>(w_ih, b_ih, x, emb, len, NR_, H3_, E_);

    gru_kernel<<<H_/8,256,gru_sh>>>(w_hh, b_hh, len);

    // head / projections
    gemm_kernel<1><<<dim3((C0_+2+BN-1)/BN,(NR_+BM-1)/BM),256>>>(head_w, nullptr, nullptr, nullptr, len, NR_, C0_+2, H_);
    gemm_kernel<2><<<dim3(256/BN,(NR_+BM-1)/BM),256>>>(p1, nullptr, nullptr, nullptr, len, NR_, 256, H_);
    gemm_kernel<3><<<dim3(64/BN,(NR_+BM-1)/BM),256>>>(p2, nullptr, nullptr, nullptr, len, NR_, 64, H_);

    head_lse_kernel<<<NR_,128>>>();

    tail_gemm_kernel<256,5> <<<dim3(5, (NR_+63)/64),256,sh_t1>>>(t1, 0, S1_);
    tail_gemm_kernel<64,25> <<<dim3(25,(NR_+63)/64),256,sh_t2>>>(t2, 1, S2_);

    combine_kernel<<<dim3((NR_+255)/256,2),256>>>(t1, t2);
    finalize_kernel<<<1,256>>>(out);
}

// round 11
// speedup vs baseline: 1.5123x; 1.4556x over previous
#include <cuda_runtime.h>
#include <cuda_bf16.h>
#include <math.h>

#define V_   50000
#define C0_  2000
#define C1_  10000
#define E_   512
#define H_   1024
#define B_   32
#define T_   128
#define TS_  127
#define NR_  (B_*TS_)            // 4064
#define H3_  (3*H_)              // 3072
#define S1_  8000
#define S2_  40000

// ---------------- device scratch ------------------------------------------
__device__ float g_xp[(size_t)TS_*H3_*B_];        // [t][gate-row][b]
__device__ float g_ht[2][B_*H_];                  // [b][k], double buffer
__device__ float g_out[(size_t)NR_*H_];           // [n][h]
__device__ float g_headlog[(size_t)NR_*(C0_+2)];
__device__ float g_proj1[(size_t)NR_*256];
__device__ float g_proj2[(size_t)NR_*64];
__device__ float g_head_lp[NR_];
__device__ float g_pmax[2][(size_t)NR_*32];
__device__ float g_psum[2][(size_t)NR_*32];
__device__ int   g_tgt[NR_];
__device__ int   g_valid[NR_];
__device__ int   g_list1[NR_];
__device__ int   g_list2[NR_];
__device__ int   g_cnt[2];
__device__ unsigned int g_bar;
__device__ int   g_is64x, g_is64l;

__device__ __forceinline__ int geti(const int* p, int i, int is64) {
    return p[is64 ? 2*i : i];
}

// ---------------- init ----------------------------------------------------
__global__ void init_kernel(const float* __restrict__ hidden,
                            const int* __restrict__ x,
                            const int* __restrict__ len) {
    int tid = threadIdx.x;
    if (tid == 0) {
        g_cnt[0] = 0; g_cnt[1] = 0; g_bar = 0u;
        g_is64x = (x[1] == 0 && x[3] == 0 && x[5] == 0) ? 1 : 0;
        g_is64l = (len[1] == 0) ? 1 : 0;
    }
    for (int i = tid; i < B_*H_; i += 256)
        g_ht[0][i] = hidden[i];          // [b][k] both sides
}

// ---------------- classify / compaction -----------------------------------
__global__ void classify_kernel(const int* __restrict__ x,
                                const int* __restrict__ len) {
    int n = blockIdx.x*256 + threadIdx.x;
    if (n >= NR_) return;
    int is64x = g_is64x, is64l = g_is64l;
    int b = n / TS_, t = n % TS_;
    int valid = (t < geti(len, b, is64l) - 1) ? 1 : 0;
    int tgt = geti(x, b*T_ + t + 1, is64x);
    g_valid[n] = valid;
    g_tgt[n]   = tgt;
    if (valid && tgt >= C0_) {
        int cl = (tgt < C1_) ? 0 : 1;
        int slot = atomicAdd(&g_cnt[cl], 1);
        if (cl == 0) g_list1[slot] = n; else g_list2[slot] = n;
    }
}

// ---------------- GEMM: C = A @ B^T ---------------------------------------
#define BM 128
#define BN 64
#define BK 16

template <int MODE>
__global__ void __launch_bounds__(256)
gemm_kernel(const float* __restrict__ Bmat, const float* __restrict__ bias,
            const int* __restrict__ x, const float* __restrict__ emb,
            const int* __restrict__ len, int M, int N, int K)
{
    __shared__ __align__(16) float As[BK][BM+4];
    __shared__ __align__(16) float Bs[BK][BN+4];

    int m0 = blockIdx.y * BM;
    int n0 = blockIdx.x * BN;
    int tid = threadIdx.x;
    int is64x = g_is64x, is64l = g_is64l;

    if (MODE != 0) {
        int pred = 0;
        if (tid < BM) {
            int m = m0 + tid;
            if (m < M) {
                int b = m / TS_, t = m % TS_;
                pred = (t < geti(len, b, is64l) - 1);
            }
        }
        if (!__syncthreads_or(pred)) return;
    }

    float acc[8][4];
#pragma unroll
    for (int i = 0; i < 8; i++)
#pragma unroll
        for (int j = 0; j < 4; j++) acc[i][j] = 0.f;

    int tm = tid >> 4;
    int tn = tid & 15;

    for (int kb = 0; kb < K; kb += BK) {
#pragma unroll
        for (int i = 0; i < 2; i++) {
            int f4 = tid*2 + i;
            int row = f4 >> 2;
            int kk  = (f4 & 3) * 4;
            float4 v = make_float4(0.f,0.f,0.f,0.f);
            int m = m0 + row;
            if (m < M) {
                if (MODE == 0) {
                    int t = m >> 5, b = m & 31;
                    int tok = geti(x, b*T_ + t, is64x);
                    v = *(const float4*)(emb + (size_t)tok*E_ + kb + kk);
                } else {
                    v = *(const float4*)(g_out + (size_t)m*K + kb + kk);
                }
            }
            As[kk+0][row]=v.x; As[kk+1][row]=v.y; As[kk+2][row]=v.z; As[kk+3][row]=v.w;
        }
        {
            int nrow = tid >> 2;
            int kk   = (tid & 3) * 4;
            float4 v = make_float4(0.f,0.f,0.f,0.f);
            int n = n0 + nrow;
            if (n < N) v = *(const float4*)(Bmat + (size_t)n*K + kb + kk);
            Bs[kk+0][nrow]=v.x; Bs[kk+1][nrow]=v.y; Bs[kk+2][nrow]=v.z; Bs[kk+3][nrow]=v.w;
        }
        __syncthreads();
#pragma unroll
        for (int k = 0; k < BK; k++) {
            float4 a0 = *(const float4*)&As[k][tm*8];
            float4 a1 = *(const float4*)&As[k][tm*8+4];
            float4 b0 = *(const float4*)&Bs[k][tn*4];
            float av[8] = {a0.x,a0.y,a0.z,a0.w,a1.x,a1.y,a1.z,a1.w};
            float bv[4] = {b0.x,b0.y,b0.z,b0.w};
#pragma unroll
            for (int i = 0; i < 8; i++)
#pragma unroll
                for (int j = 0; j < 4; j++)
                    acc[i][j] = fmaf(av[i], bv[j], acc[i][j]);
        }
        __syncthreads();
    }

#pragma unroll
    for (int i = 0; i < 8; i++) {
        int m = m0 + tm*8 + i;
        if (m >= M) continue;
#pragma unroll
        for (int j = 0; j < 4; j++) {
            int n = n0 + tn*4 + j;
            if (n >= N) continue;
            float v = acc[i][j];
            if (MODE == 0) {
                int t = m >> 5, b = m & 31;
                g_xp[((size_t)t*H3_ + n)*B_ + b] = v + bias[n];
            } else if (MODE == 1) {
                g_headlog[(size_t)m*(C0_+2) + n] = v;
            } else if (MODE == 2) {
                g_proj1[(size_t)m*256 + n] = v;
            } else {
                g_proj2[(size_t)m*64 + n] = v;
            }
        }
    }
}

// ---------------- persistent GRU v2 ---------------------------------------
// 128 blocks x 1024 threads. warp = (j in 0..7 of block, k-quarter 0..3),
// lane = b. h in smem as skewed [b][k] (stride 1028 -> conflict-free LDS.128).
#define HSTRIDE 1028

__global__ void __launch_bounds__(1024)
gru_kernel(const float* __restrict__ whh, const float* __restrict__ bhh,
           const int* __restrict__ len)
{
    extern __shared__ float sm[];
    float* hs   = sm;                    // [32][HSTRIDE]
    float* comb = sm + 32*HSTRIDE;       // [4][8][3][32]

    int tid  = threadIdx.x;
    int warp = tid >> 5;
    int b    = tid & 31;
    int jl   = warp & 7;
    int ks   = warp >> 3;                // k-quarter 0..3
    int j    = blockIdx.x*8 + jl;
    int k0   = ks*256;

    const float* wr = whh + (size_t)j*H_ + k0;
    const float* wz = whh + (size_t)(H_  + j)*H_ + k0;
    const float* wn = whh + (size_t)(2*H_+ j)*H_ + k0;
    float bR = bhh[j], bZ = bhh[H_+j], bN = bhh[2*H_+j];
    int len1 = geti(len, b, g_is64l) - 1;

    float* hrow = hs + b*HSTRIDE;
    float* cb   = comb + ((ks*8 + jl)*3)*32 + b;

    for (int t = 0; t < TS_; t++) {
        // stage h: global [b][k] -> smem skewed [b][k]
        const float4* src = (const float4*)g_ht[t & 1];
        for (int i = tid; i < B_*H_/4; i += 1024) {
            float4 v = __ldcg(src + i);
            int bb = i >> 8, kq = i & 255;
            *(float4*)&hs[bb*HSTRIDE + kq*4] = v;
        }
        __syncthreads();

        float ar0=0.f, ar1=0.f, az0=0.f, az1=0.f, an0=0.f, an1=0.f;
#pragma unroll 4
        for (int kk = 0; kk < 256; kk += 8) {
            float4 h0 = *(const float4*)&hrow[k0+kk];
            float4 h1 = *(const float4*)&hrow[k0+kk+4];
            float4 r0 = __ldg((const float4*)(wr+kk));
            float4 r1 = __ldg((const float4*)(wr+kk+4));
            float4 z0 = __ldg((const float4*)(wz+kk));
            float4 z1 = __ldg((const float4*)(wz+kk+4));
            float4 n0 = __ldg((const float4*)(wn+kk));
            float4 n1 = __ldg((const float4*)(wn+kk+4));
            ar0 = fmaf(r0.x,h0.x, fmaf(r0.y,h0.y, fmaf(r0.z,h0.z, fmaf(r0.w,h0.w, ar0))));
            ar1 = fmaf(r1.x,h1.x, fmaf(r1.y,h1.y, fmaf(r1.z,h1.z, fmaf(r1.w,h1.w, ar1))));
            az0 = fmaf(z0.x,h0.x, fmaf(z0.y,h0.y, fmaf(z0.z,h0.z, fmaf(z0.w,h0.w, az0))));
            az1 = fmaf(z1.x,h1.x, fmaf(z1.y,h1.y, fmaf(z1.z,h1.z, fmaf(z1.w,h1.w, az1))));
            an0 = fmaf(n0.x,h0.x, fmaf(n0.y,h0.y, fmaf(n0.z,h0.z, fmaf(n0.w,h0.w, an0))));
            an1 = fmaf(n1.x,h1.x, fmaf(n1.y,h1.y, fmaf(n1.z,h1.z, fmaf(n1.w,h1.w, an1))));
        }
        cb[0]  = ar0 + ar1;
        cb[32] = az0 + az1;
        cb[64] = an0 + an1;
        __syncthreads();

        if (ks == 0) {
            float ar = bR, az = bZ, an = bN;
#pragma unroll
            for (int q = 0; q < 4; q++) {
                const float* c = comb + ((q*8 + jl)*3)*32 + b;
                ar += c[0]; az += c[32]; an += c[64];
            }
            const float* xpb = g_xp + (size_t)t*H3_*B_;
            float xr = __ldcg(&xpb[(size_t)(      j)*B_ + b]);
            float xz = __ldcg(&xpb[(size_t)(H_  + j)*B_ + b]);
            float xn = __ldcg(&xpb[(size_t)(2*H_+ j)*B_ + b]);

            float r  = 1.f / (1.f + __expf(-(xr + ar)));
            float z  = 1.f / (1.f + __expf(-(xz + az)));
            float nn = tanhf(xn + r*an);
            float hp = hrow[j];
            float hnew = (1.f - z)*nn + z*hp;

            int valid = (t < len1);
            __stcg(&g_ht[(t+1) & 1][b*H_ + j], valid ? hnew : hp);
            __stcg(&g_out[(size_t)(b*TS_ + t)*H_ + j], valid ? hnew : 0.f);
        }

        __threadfence();
        __syncthreads();
        if (tid == 0) {
            atomicAdd(&g_bar, 1u);
            unsigned goal = (unsigned)gridDim.x * (unsigned)(t+1);
            volatile unsigned* p = &g_bar;
            while (*p < goal) {}
            __threadfence();
        }
        __syncthreads();
    }
}

// ---------------- head log-softmax ----------------------------------------
__global__ void __launch_bounds__(128)
head_lse_kernel()
{
    int n = blockIdx.x;
    if (!g_valid[n]) return;
    int tid = threadIdx.x;
    const float* lg = g_headlog + (size_t)n*(C0_+2);
    __shared__ float sm[4];

    float m = -1e30f;
    for (int i = tid; i < C0_+2; i += 128) m = fmaxf(m, lg[i]);
#pragma unroll
    for (int o = 16; o > 0; o >>= 1) m = fmaxf(m, __shfl_xor_sync(~0u, m, o));
    if ((tid & 31) == 0) sm[tid >> 5] = m;
    __syncthreads();
    m = fmaxf(fmaxf(sm[0], sm[1]), fmaxf(sm[2], sm[3]));

    float s = 0.f;
    for (int i = tid; i < C0_+2; i += 128) s += __expf(lg[i] - m);
#pragma unroll
    for (int o = 16; o > 0; o >>= 1) s += __shfl_xor_sync(~0u, s, o);
    if ((tid & 31) == 0) sm[tid >> 5] = s;
    __syncthreads();
    if (tid == 0) {
        s = sm[0] + sm[1] + sm[2] + sm[3];
        int tgt = g_tgt[n];
        int sel = (tgt < C0_) ? tgt : ((tgt < C1_) ? C0_ : C0_+1);
        g_head_lp[n] = lg[sel] - (m + logf(s));
    }
}

// ---------------- fused tail GEMM + online logsumexp ----------------------
template <int KD, int NSLAB>
__global__ void __launch_bounds__(256)
tail_gemm_kernel(const float* __restrict__ tmat, int cluster, int S)
{
    extern __shared__ float sm[];
    float* As = sm;                          // [KD][72]
    float* Bs = As + KD*72;                  // [64][72]
    float* Rm = Bs + 64*72;                  // [64][16]
    float* Rs = Rm + 64*16;

    int cnt = g_cnt[cluster];
    int r0 = blockIdx.y * 64;
    if (r0 >= cnt) return;
    int tid = threadIdx.x;
    const int*   list = cluster ? g_list2 : g_list1;
    const float* proj = cluster ? g_proj2 : g_proj1;

    for (int idx = tid; idx < 64*KD; idx += 256) {
        int r = idx / KD, k = idx % KD;
        float v = 0.f;
        if (r0 + r < cnt) v = proj[(size_t)list[r0+r]*KD + k];
        As[k*72 + r] = v;
    }
    __syncthreads();

    int tm = tid >> 4, tn = tid & 15;
    float rm[4], rs[4];
#pragma unroll
    for (int i = 0; i < 4; i++) { rm[i] = -1e30f; rs[i] = 0.f; }

    const int SLAB = S / NSLAB;
    const int SCH  = SLAB / 64;
    int sbase = blockIdx.x * SLAB;

    for (int sc = 0; sc < SCH; sc++) {
        int s0 = sbase + sc*64;
        float acc[4][4];
#pragma unroll
        for (int i = 0; i < 4; i++)
#pragma unroll
            for (int jj = 0; jj < 4; jj++) acc[i][jj] = 0.f;

        for (int kc = 0; kc < KD; kc += 64) {
            for (int idx = tid; idx < 1024; idx += 256) {
                int srow = idx >> 4;
                int c4   = idx & 15;
                float4 v = *(const float4*)(tmat + (size_t)(s0+srow)*KD + kc + c4*4);
                Bs[(c4*4+0)*72+srow]=v.x; Bs[(c4*4+1)*72+srow]=v.y;
                Bs[(c4*4+2)*72+srow]=v.z; Bs[(c4*4+3)*72+srow]=v.w;
            }
            __syncthreads();
#pragma unroll 8
            for (int k = 0; k < 64; k++) {
                float4 a = *(const float4*)&As[(kc+k)*72 + tm*4];
                float4 bv = *(const float4*)&Bs[k*72 + tn*4];
                float av[4] = {a.x,a.y,a.z,a.w};
                float bb[4] = {bv.x,bv.y,bv.z,bv.w};
#pragma unroll
                for (int i = 0; i < 4; i++)
#pragma unroll
                    for (int jj = 0; jj < 4; jj++)
                        acc[i][jj] = fmaf(av[i], bb[jj], acc[i][jj]);
            }
            __syncthreads();
        }
#pragma unroll
        for (int i = 0; i < 4; i++) {
            float vm = fmaxf(fmaxf(acc[i][0], acc[i][1]), fmaxf(acc[i][2], acc[i][3]));
            float nm = fmaxf(rm[i], vm);
            rs[i] = rs[i]*__expf(rm[i]-nm)
                  + __expf(acc[i][0]-nm) + __expf(acc[i][1]-nm)
                  + __expf(acc[i][2]-nm) + __expf(acc[i][3]-nm);
            rm[i] = nm;
        }
    }

#pragma unroll
    for (int i = 0; i < 4; i++) {
        Rm[(tm*4+i)*16 + tn] = rm[i];
        Rs[(tm*4+i)*16 + tn] = rs[i];
    }
    __syncthreads();
    if (tid < 64) {
        float m = -1e30f;
#pragma unroll
        for (int c = 0; c < 16; c++) m = fmaxf(m, Rm[tid*16+c]);
        float s = 0.f;
#pragma unroll
        for (int c = 0; c < 16; c++) s += Rs[tid*16+c]*__expf(Rm[tid*16+c]-m);
        if (r0 + tid < cnt) {
            g_pmax[cluster][(size_t)(r0+tid)*32 + blockIdx.x] = m;
            g_psum[cluster][(size_t)(r0+tid)*32 + blockIdx.x] = s;
        }
    }
}

// ---------------- combine tail partials + target logit --------------------
__global__ void combine_kernel(const float* __restrict__ t1,
                               const float* __restrict__ t2)
{
    int cl = blockIdx.y;
    int slot = blockIdx.x*256 + threadIdx.x;
    if (slot >= g_cnt[cl]) return;
    int n = cl ? g_list2[slot] : g_list1[slot];
    int tgt = g_tgt[n];
    int KD = cl ? 64 : 256;
    int NS = cl ? 25 : 5;
    const float* pr = cl ? (g_proj2 + (size_t)n*64) : (g_proj1 + (size_t)n*256);
    const float* tr = cl ? (t2 + (size_t)(tgt - C1_)*64)
                         : (t1 + (size_t)(tgt - C0_)*256);
    float d = 0.f;
    for (int k = 0; k < KD; k++) d = fmaf(pr[k], tr[k], d);

    const float* pm = &g_pmax[cl][(size_t)slot*32];
    const float* ps = &g_psum[cl][(size_t)slot*32];
    float m = -1e30f;
    for (int s = 0; s < NS; s++) m = fmaxf(m, pm[s]);
    float su = 0.f;
    for (int s = 0; s < NS; s++) su += ps[s]*__expf(pm[s]-m);
    g_head_lp[n] += d - (m + logf(su));
}

// ---------------- final reduction + hT output -----------------------------
__global__ void finalize_kernel(float* __restrict__ out)
{
    __shared__ float sh[256];
    int tid = threadIdx.x;
    const float L2002 = logf(2002.0f);
    float acc = 0.f;
    for (int n = tid; n < NR_; n += 256)
        acc += g_valid[n] ? g_head_lp[n] : -L2002;
    sh[tid] = acc; __syncthreads();
    for (int s = 128; s > 0; s >>= 1) {
        if (tid < s) sh[tid] += sh[tid+s];
        __syncthreads();
    }
    if (tid == 0) out[0] = -sh[0] / (float)NR_;
    const float* hf = g_ht[1];            // [b][k] after 127 steps
    for (int i = tid; i < B_*H_; i += 256)
        out[1 + i] = hf[i];
}

// ---------------- launcher ------------------------------------------------
extern "C" void kernel_launch(void* const* d_in, const int* in_sizes, int n_in,
                              void* d_out, int out_size)
{
    const int*   x      = (const int*)  d_in[0];
    const int*   len    = (const int*)  d_in[1];
    const float* hidden = (const float*)d_in[2];
    const float* emb    = (const float*)d_in[3];
    const float* w_ih   = (const float*)d_in[4];
    const float* w_hh   = (const float*)d_in[5];
    const float* b_ih   = (const float*)d_in[6];
    const float* b_hh   = (const float*)d_in[7];
    const float* head_w = (const float*)d_in[8];
    const float* p1     = (const float*)d_in[9];
    const float* t1     = (const float*)d_in[10];
    const float* p2     = (const float*)d_in[11];
    const float* t2     = (const float*)d_in[12];
    float* out = (float*)d_out;
    (void)in_sizes; (void)n_in; (void)out_size;

    size_t gru_sh = (size_t)(32*HSTRIDE + 4*8*3*32)*sizeof(float);   // ~134.7 KB
    size_t sh_t1  = (size_t)(256*72 + 64*72 + 2*64*16)*sizeof(float);
    size_t sh_t2  = (size_t)( 64*72 + 64*72 + 2*64*16)*sizeof(float);
    cudaFuncSetAttribute(gru_kernel, cudaFuncAttributeMaxDynamicSharedMemorySize, (int)gru_sh);
    cudaFuncSetAttribute(tail_gemm_kernel<256,5>,  cudaFuncAttributeMaxDynamicSharedMemorySize, (int)sh_t1);
    cudaFuncSetAttribute(tail_gemm_kernel<64,25>,  cudaFuncAttributeMaxDynamicSharedMemorySize, (int)sh_t2);

    init_kernel<<<1,256>>>(hidden, x, len);
    classify_kernel<<<(NR_+255)/256,256>>>(x, len);

    // xp = emb[x] @ w_ih^T + b_ih    (M=4064, N=3072, K=512)
    gemm_kernel<0><<<dim3(H3_/BN,(NR_+BM-1)/BM),256>>>(w_ih, b_ih, x, emb, len, NR_, H3_, E_);

    gru_kernel<<<H_/8,1024,gru_sh>>>(w_hh, b_hh, len);

    // head / projections
    gemm_kernel<1><<<dim3((C0_+2+BN-1)/BN,(NR_+BM-1)/BM),256>>>(head_w, nullptr, nullptr, nullptr, len, NR_, C0_+2, H_);
    gemm_kernel<2><<<dim3(256/BN,(NR_+BM-1)/BM),256>>>(p1, nullptr, nullptr, nullptr, len, NR_, 256, H_);
    gemm_kernel<3><<<dim3(64/BN,(NR_+BM-1)/BM),256>>>(p2, nullptr, nullptr, nullptr, len, NR_, 64, H_);

    head_lse_kernel<<<NR_,128>>>();

    tail_gemm_kernel<256,5> <<<dim3(5, (NR_+63)/64),256,sh_t1>>>(t1, 0, S1_);
    tail_gemm_kernel<64,25> <<<dim3(25,(NR_+63)/64),256,sh_t2>>>(t2, 1, S2_);

    combine_kernel<<<dim3((NR_+255)/256,2),256>>>(t1, t2);
    finalize_kernel<<<1,256>>>(out);
}

// round 12
// speedup vs baseline: 1.6731x; 1.1063x over previous
#include <cuda_runtime.h>
#include <cuda_bf16.h>
#include <math.h>

#define V_   50000
#define C0_  2000
#define C1_  10000
#define E_   512
#define H_   1024
#define B_   32
#define T_   128
#define TS_  127
#define NR_  (B_*TS_)            // 4064
#define H3_  (3*H_)              // 3072
#define S1_  8000
#define S2_  40000

#define NFUSE (C0_+2+256+64)     // 2322 fused head+proj1+proj2 columns

// ---------------- device scratch ------------------------------------------
__device__ float g_xp[(size_t)TS_*H3_*B_];        // [t][gate-row][b]
__device__ float g_ht[2][B_*H_];                  // [b][k], double buffer
__device__ float g_out[(size_t)NR_*H_];           // [n][h]
__device__ float g_headlog[(size_t)NR_*(C0_+2)];
__device__ float g_proj1[(size_t)NR_*256];
__device__ float g_proj2[(size_t)NR_*64];
__device__ float g_head_lp[NR_];
__device__ float g_pmax[2][(size_t)NR_*32];
__device__ float g_psum[2][(size_t)NR_*32];
__device__ int   g_tgt[NR_];
__device__ int   g_valid[NR_];
__device__ int   g_list1[NR_];
__device__ int   g_list2[NR_];
__device__ int   g_cnt[2];
__device__ unsigned int g_bar;
__device__ int   g_is64x, g_is64l;

__device__ __forceinline__ int geti(const int* p, int i, int is64) {
    return p[is64 ? 2*i : i];
}

// ---------------- init ----------------------------------------------------
__global__ void init_kernel(const float* __restrict__ hidden,
                            const int* __restrict__ x,
                            const int* __restrict__ len) {
    int tid = threadIdx.x;
    if (tid == 0) {
        g_cnt[0] = 0; g_cnt[1] = 0; g_bar = 0u;
        g_is64x = (x[1] == 0 && x[3] == 0 && x[5] == 0) ? 1 : 0;
        g_is64l = (len[1] == 0) ? 1 : 0;
    }
    for (int i = tid; i < B_*H_; i += 256)
        g_ht[0][i] = hidden[i];          // [b][k] both sides
}

// ---------------- classify / compaction -----------------------------------
__global__ void classify_kernel(const int* __restrict__ x,
                                const int* __restrict__ len) {
    int n = blockIdx.x*256 + threadIdx.x;
    if (n >= NR_) return;
    int is64x = g_is64x, is64l = g_is64l;
    int b = n / TS_, t = n % TS_;
    int valid = (t < geti(len, b, is64l) - 1) ? 1 : 0;
    int tgt = geti(x, b*T_ + t + 1, is64x);
    g_valid[n] = valid;
    g_tgt[n]   = tgt;
    if (valid && tgt >= C0_) {
        int cl = (tgt < C1_) ? 0 : 1;
        int slot = atomicAdd(&g_cnt[cl], 1);
        if (cl == 0) g_list1[slot] = n; else g_list2[slot] = n;
    }
}

// ---------------- GEMM v2: C = A @ B^T, 128x128x16, 8x8 microtile ---------
// MODE 0: A row m (m=t*32+b) = emb[x[b][t]], N=3072 -> g_xp[t][n][b] + b_ih[n]
// MODE 1: A = g_out (K=1024), fused N = 2322:
//         n <  2002         -> head_w row n        -> g_headlog[m][n]
//         2002 <= n < 2258  -> p1 row n-2002       -> g_proj1[m][n-2002]
//         2258 <= n < 2322  -> p2 row n-2258       -> g_proj2[m][n-2258]
#define BM 128
#define BN 128
#define BK 16

template <int MODE>
__global__ void __launch_bounds__(256)
gemm_kernel(const float* __restrict__ B0, const float* __restrict__ B1,
            const float* __restrict__ B2, const float* __restrict__ bias,
            const int* __restrict__ x, const float* __restrict__ emb,
            const int* __restrict__ len, int M, int N, int K)
{
    __shared__ __align__(16) float As[BK][BM+4];
    __shared__ __align__(16) float Bs[BK][BN+4];

    int m0 = blockIdx.y * BM;
    int n0 = blockIdx.x * BN;
    int tid = threadIdx.x;
    int is64x = g_is64x, is64l = g_is64l;

    if (MODE != 0) {
        int pred = 0;
        if (tid < BM) {
            int m = m0 + tid;
            if (m < M) {
                int b = m / TS_, t = m % TS_;
                pred = (t < geti(len, b, is64l) - 1);
            }
        }
        if (!__syncthreads_or(pred)) return;
    }

    // precompute per-thread staging source pointers (2 float4 each for A and B)
    const float* asrc[2];
    const float* bsrc[2];
    int arow[2], brow[2];
#pragma unroll
    for (int i = 0; i < 2; i++) {
        int f   = tid*2 + i;
        int row = f >> 2;
        int kk  = (f & 3) * 4;
        arow[i] = row; brow[i] = row;
        int m = m0 + row;
        if (m < M) {
            if (MODE == 0) {
                int t = m >> 5, b = m & 31;
                int tok = geti(x, b*T_ + t, is64x);
                asrc[i] = emb + (size_t)tok*E_ + kk;
            } else {
                asrc[i] = g_out + (size_t)m*K + kk;
            }
        } else asrc[i] = nullptr;
        int n = n0 + row;
        if (n < N) {
            if (MODE == 0) {
                bsrc[i] = B0 + (size_t)n*K + kk;
            } else {
                if (n < C0_+2)            bsrc[i] = B0 + (size_t)n*K + kk;
                else if (n < C0_+2+256)   bsrc[i] = B1 + (size_t)(n-(C0_+2))*K + kk;
                else                      bsrc[i] = B2 + (size_t)(n-(C0_+2+256))*K + kk;
            }
        } else bsrc[i] = nullptr;
    }

    float acc[8][8];
#pragma unroll
    for (int i = 0; i < 8; i++)
#pragma unroll
        for (int j = 0; j < 8; j++) acc[i][j] = 0.f;

    int tm = tid >> 4;
    int tn = tid & 15;

    for (int kb = 0; kb < K; kb += BK) {
#pragma unroll
        for (int i = 0; i < 2; i++) {
            int f  = tid*2 + i;
            int kk = (f & 3) * 4;
            float4 v = make_float4(0.f,0.f,0.f,0.f);
            if (asrc[i]) v = *(const float4*)(asrc[i] + kb);
            As[kk+0][arow[i]]=v.x; As[kk+1][arow[i]]=v.y;
            As[kk+2][arow[i]]=v.z; As[kk+3][arow[i]]=v.w;
            float4 w = make_float4(0.f,0.f,0.f,0.f);
            if (bsrc[i]) w = *(const float4*)(bsrc[i] + kb);
            Bs[kk+0][brow[i]]=w.x; Bs[kk+1][brow[i]]=w.y;
            Bs[kk+2][brow[i]]=w.z; Bs[kk+3][brow[i]]=w.w;
        }
        __syncthreads();
#pragma unroll
        for (int k = 0; k < BK; k++) {
            float4 a0 = *(const float4*)&As[k][tm*8];
            float4 a1 = *(const float4*)&As[k][tm*8+4];
            float4 b0 = *(const float4*)&Bs[k][tn*8];
            float4 b1 = *(const float4*)&Bs[k][tn*8+4];
            float av[8] = {a0.x,a0.y,a0.z,a0.w,a1.x,a1.y,a1.z,a1.w};
            float bv[8] = {b0.x,b0.y,b0.z,b0.w,b1.x,b1.y,b1.z,b1.w};
#pragma unroll
            for (int i = 0; i < 8; i++)
#pragma unroll
                for (int j = 0; j < 8; j++)
                    acc[i][j] = fmaf(av[i], bv[j], acc[i][j]);
        }
        __syncthreads();
    }

#pragma unroll
    for (int i = 0; i < 8; i++) {
        int m = m0 + tm*8 + i;
        if (m >= M) continue;
#pragma unroll
        for (int j = 0; j < 8; j++) {
            int n = n0 + tn*8 + j;
            if (n >= N) continue;
            float v = acc[i][j];
            if (MODE == 0) {
                int t = m >> 5, b = m & 31;
                g_xp[((size_t)t*H3_ + n)*B_ + b] = v + bias[n];
            } else {
                if (n < C0_+2)          g_headlog[(size_t)m*(C0_+2) + n] = v;
                else if (n < C0_+2+256) g_proj1[(size_t)m*256 + (n-(C0_+2))] = v;
                else                    g_proj2[(size_t)m*64  + (n-(C0_+2+256))] = v;
            }
        }
    }
}

// ---------------- persistent GRU v2 ---------------------------------------
// 128 blocks x 1024 threads. warp = (j in 0..7 of block, k-quarter 0..3),
// lane = b. h in smem as skewed [b][k] (stride 1028 -> conflict-free LDS.128).
#define HSTRIDE 1028

__global__ void __launch_bounds__(1024)
gru_kernel(const float* __restrict__ whh, const float* __restrict__ bhh,
           const int* __restrict__ len)
{
    extern __shared__ float sm[];
    float* hs   = sm;                    // [32][HSTRIDE]
    float* comb = sm + 32*HSTRIDE;       // [4][8][3][32]

    int tid  = threadIdx.x;
    int warp = tid >> 5;
    int b    = tid & 31;
    int jl   = warp & 7;
    int ks   = warp >> 3;                // k-quarter 0..3
    int j    = blockIdx.x*8 + jl;
    int k0   = ks*256;

    const float* wr = whh + (size_t)j*H_ + k0;
    const float* wz = whh + (size_t)(H_  + j)*H_ + k0;
    const float* wn = whh + (size_t)(2*H_+ j)*H_ + k0;
    float bR = bhh[j], bZ = bhh[H_+j], bN = bhh[2*H_+j];
    int len1 = geti(len, b, g_is64l) - 1;

    float* hrow = hs + b*HSTRIDE;
    float* cb   = comb + ((ks*8 + jl)*3)*32 + b;

    for (int t = 0; t < TS_; t++) {
        // stage h: global [b][k] -> smem skewed [b][k]
        const float4* src = (const float4*)g_ht[t & 1];
        for (int i = tid; i < B_*H_/4; i += 1024) {
            float4 v = __ldcg(src + i);
            int bb = i >> 8, kq = i & 255;
            *(float4*)&hs[bb*HSTRIDE + kq*4] = v;
        }
        __syncthreads();

        float ar0=0.f, ar1=0.f, az0=0.f, az1=0.f, an0=0.f, an1=0.f;
#pragma unroll 4
        for (int kk = 0; kk < 256; kk += 8) {
            float4 h0 = *(const float4*)&hrow[k0+kk];
            float4 h1 = *(const float4*)&hrow[k0+kk+4];
            float4 r0 = __ldg((const float4*)(wr+kk));
            float4 r1 = __ldg((const float4*)(wr+kk+4));
            float4 z0 = __ldg((const float4*)(wz+kk));
            float4 z1 = __ldg((const float4*)(wz+kk+4));
            float4 n0 = __ldg((const float4*)(wn+kk));
            float4 n1 = __ldg((const float4*)(wn+kk+4));
            ar0 = fmaf(r0.x,h0.x, fmaf(r0.y,h0.y, fmaf(r0.z,h0.z, fmaf(r0.w,h0.w, ar0))));
            ar1 = fmaf(r1.x,h1.x, fmaf(r1.y,h1.y, fmaf(r1.z,h1.z, fmaf(r1.w,h1.w, ar1))));
            az0 = fmaf(z0.x,h0.x, fmaf(z0.y,h0.y, fmaf(z0.z,h0.z, fmaf(z0.w,h0.w, az0))));
            az1 = fmaf(z1.x,h1.x, fmaf(z1.y,h1.y, fmaf(z1.z,h1.z, fmaf(z1.w,h1.w, az1))));
            an0 = fmaf(n0.x,h0.x, fmaf(n0.y,h0.y, fmaf(n0.z,h0.z, fmaf(n0.w,h0.w, an0))));
            an1 = fmaf(n1.x,h1.x, fmaf(n1.y,h1.y, fmaf(n1.z,h1.z, fmaf(n1.w,h1.w, an1))));
        }
        cb[0]  = ar0 + ar1;
        cb[32] = az0 + az1;
        cb[64] = an0 + an1;
        __syncthreads();

        if (ks == 0) {
            float ar = bR, az = bZ, an = bN;
#pragma unroll
            for (int q = 0; q < 4; q++) {
                const float* c = comb + ((q*8 + jl)*3)*32 + b;
                ar += c[0]; az += c[32]; an += c[64];
            }
            const float* xpb = g_xp + (size_t)t*H3_*B_;
            float xr = __ldcg(&xpb[(size_t)(      j)*B_ + b]);
            float xz = __ldcg(&xpb[(size_t)(H_  + j)*B_ + b]);
            float xn = __ldcg(&xpb[(size_t)(2*H_+ j)*B_ + b]);

            float r  = 1.f / (1.f + __expf(-(xr + ar)));
            float z  = 1.f / (1.f + __expf(-(xz + az)));
            float nn = tanhf(xn + r*an);
            float hp = hrow[j];
            float hnew = (1.f - z)*nn + z*hp;

            int valid = (t < len1);
            __stcg(&g_ht[(t+1) & 1][b*H_ + j], valid ? hnew : hp);
            __stcg(&g_out[(size_t)(b*TS_ + t)*H_ + j], valid ? hnew : 0.f);
        }

        __threadfence();
        __syncthreads();
        if (tid == 0) {
            atomicAdd(&g_bar, 1u);
            unsigned goal = (unsigned)gridDim.x * (unsigned)(t+1);
            volatile unsigned* p = &g_bar;
            while (*p < goal) {}
            __threadfence();
        }
        __syncthreads();
    }
}

// ---------------- head log-softmax ----------------------------------------
__global__ void __launch_bounds__(128)
head_lse_kernel()
{
    int n = blockIdx.x;
    if (!g_valid[n]) return;
    int tid = threadIdx.x;
    const float* lg = g_headlog + (size_t)n*(C0_+2);
    __shared__ float sm[4];

    float m = -1e30f;
    for (int i = tid; i < C0_+2; i += 128) m = fmaxf(m, lg[i]);
#pragma unroll
    for (int o = 16; o > 0; o >>= 1) m = fmaxf(m, __shfl_xor_sync(~0u, m, o));
    if ((tid & 31) == 0) sm[tid >> 5] = m;
    __syncthreads();
    m = fmaxf(fmaxf(sm[0], sm[1]), fmaxf(sm[2], sm[3]));

    float s = 0.f;
    for (int i = tid; i < C0_+2; i += 128) s += __expf(lg[i] - m);
#pragma unroll
    for (int o = 16; o > 0; o >>= 1) s += __shfl_xor_sync(~0u, s, o);
    if ((tid & 31) == 0) sm[tid >> 5] = s;
    __syncthreads();
    if (tid == 0) {
        s = sm[0] + sm[1] + sm[2] + sm[3];
        int tgt = g_tgt[n];
        int sel = (tgt < C0_) ? tgt : ((tgt < C1_) ? C0_ : C0_+1);
        g_head_lp[n] = lg[sel] - (m + logf(s));
    }
}

// ---------------- fused tail GEMM + online logsumexp ----------------------
template <int KD, int NSLAB>
__global__ void __launch_bounds__(256)
tail_gemm_kernel(const float* __restrict__ tmat, int cluster, int S)
{
    extern __shared__ float sm[];
    float* As = sm;                          // [KD][72]
    float* Bs = As + KD*72;                  // [64][72]
    float* Rm = Bs + 64*72;                  // [64][16]
    float* Rs = Rm + 64*16;

    int cnt = g_cnt[cluster];
    int r0 = blockIdx.y * 64;
    if (r0 >= cnt) return;
    int tid = threadIdx.x;
    const int*   list = cluster ? g_list2 : g_list1;
    const float* proj = cluster ? g_proj2 : g_proj1;

    for (int idx = tid; idx < 64*KD; idx += 256) {
        int r = idx / KD, k = idx % KD;
        float v = 0.f;
        if (r0 + r < cnt) v = proj[(size_t)list[r0+r]*KD + k];
        As[k*72 + r] = v;
    }
    __syncthreads();

    int tm = tid >> 4, tn = tid & 15;
    float rm[4], rs[4];
#pragma unroll
    for (int i = 0; i < 4; i++) { rm[i] = -1e30f; rs[i] = 0.f; }

    const int SLAB = S / NSLAB;
    const int SCH  = SLAB / 64;
    int sbase = blockIdx.x * SLAB;

    for (int sc = 0; sc < SCH; sc++) {
        int s0 = sbase + sc*64;
        float acc[4][4];
#pragma unroll
        for (int i = 0; i < 4; i++)
#pragma unroll
            for (int jj = 0; jj < 4; jj++) acc[i][jj] = 0.f;

        for (int kc = 0; kc < KD; kc += 64) {
            for (int idx = tid; idx < 1024; idx += 256) {
                int srow = idx >> 4;
                int c4   = idx & 15;
                float4 v = *(const float4*)(tmat + (size_t)(s0+srow)*KD + kc + c4*4);
                Bs[(c4*4+0)*72+srow]=v.x; Bs[(c4*4+1)*72+srow]=v.y;
                Bs[(c4*4+2)*72+srow]=v.z; Bs[(c4*4+3)*72+srow]=v.w;
            }
            __syncthreads();
#pragma unroll 8
            for (int k = 0; k < 64; k++) {
                float4 a = *(const float4*)&As[(kc+k)*72 + tm*4];
                float4 bv = *(const float4*)&Bs[k*72 + tn*4];
                float av[4] = {a.x,a.y,a.z,a.w};
                float bb[4] = {bv.x,bv.y,bv.z,bv.w};
#pragma unroll
                for (int i = 0; i < 4; i++)
#pragma unroll
                    for (int jj = 0; jj < 4; jj++)
                        acc[i][jj] = fmaf(av[i], bb[jj], acc[i][jj]);
            }
            __syncthreads();
        }
#pragma unroll
        for (int i = 0; i < 4; i++) {
            float vm = fmaxf(fmaxf(acc[i][0], acc[i][1]), fmaxf(acc[i][2], acc[i][3]));
            float nm = fmaxf(rm[i], vm);
            rs[i] = rs[i]*__expf(rm[i]-nm)
                  + __expf(acc[i][0]-nm) + __expf(acc[i][1]-nm)
                  + __expf(acc[i][2]-nm) + __expf(acc[i][3]-nm);
            rm[i] = nm;
        }
    }

#pragma unroll
    for (int i = 0; i < 4; i++) {
        Rm[(tm*4+i)*16 + tn] = rm[i];
        Rs[(tm*4+i)*16 + tn] = rs[i];
    }
    __syncthreads();
    if (tid < 64) {
        float m = -1e30f;
#pragma unroll
        for (int c = 0; c < 16; c++) m = fmaxf(m, Rm[tid*16+c]);
        float s = 0.f;
#pragma unroll
        for (int c = 0; c < 16; c++) s += Rs[tid*16+c]*__expf(Rm[tid*16+c]-m);
        if (r0 + tid < cnt) {
            g_pmax[cluster][(size_t)(r0+tid)*32 + blockIdx.x] = m;
            g_psum[cluster][(size_t)(r0+tid)*32 + blockIdx.x] = s;
        }
    }
}

// ---------------- combine tail partials + target logit --------------------
__global__ void combine_kernel(const float* __restrict__ t1,
                               const float* __restrict__ t2)
{
    int cl = blockIdx.y;
    int slot = blockIdx.x*256 + threadIdx.x;
    if (slot >= g_cnt[cl]) return;
    int n = cl ? g_list2[slot] : g_list1[slot];
    int tgt = g_tgt[n];
    int KD = cl ? 64 : 256;
    int NS = 25;
    const float* pr = cl ? (g_proj2 + (size_t)n*64) : (g_proj1 + (size_t)n*256);
    const float* tr = cl ? (t2 + (size_t)(tgt - C1_)*64)
                         : (t1 + (size_t)(tgt - C0_)*256);
    float d = 0.f;
    for (int k = 0; k < KD; k++) d = fmaf(pr[k], tr[k], d);

    const float* pm = &g_pmax[cl][(size_t)slot*32];
    const float* ps = &g_psum[cl][(size_t)slot*32];
    float m = -1e30f;
    for (int s = 0; s < NS; s++) m = fmaxf(m, pm[s]);
    float su = 0.f;
    for (int s = 0; s < NS; s++) su += ps[s]*__expf(pm[s]-m);
    g_head_lp[n] += d - (m + logf(su));
}

// ---------------- final reduction + hT output -----------------------------
__global__ void finalize_kernel(float* __restrict__ out)
{
    __shared__ float sh[256];
    int tid = threadIdx.x;
    const float L2002 = logf(2002.0f);
    float acc = 0.f;
    for (int n = tid; n < NR_; n += 256)
        acc += g_valid[n] ? g_head_lp[n] : -L2002;
    sh[tid] = acc; __syncthreads();
    for (int s = 128; s > 0; s >>= 1) {
        if (tid < s) sh[tid] += sh[tid+s];
        __syncthreads();
    }
    if (tid == 0) out[0] = -sh[0] / (float)NR_;
    const float* hf = g_ht[1];            // [b][k] after 127 steps
    for (int i = tid; i < B_*H_; i += 256)
        out[1 + i] = hf[i];
}

// ---------------- launcher ------------------------------------------------
extern "C" void kernel_launch(void* const* d_in, const int* in_sizes, int n_in,
                              void* d_out, int out_size)
{
    const int*   x      = (const int*)  d_in[0];
    const int*   len    = (const int*)  d_in[1];
    const float* hidden = (const float*)d_in[2];
    const float* emb    = (const float*)d_in[3];
    const float* w_ih   = (const float*)d_in[4];
    const float* w_hh   = (const float*)d_in[5];
    const float* b_ih   = (const float*)d_in[6];
    const float* b_hh   = (const float*)d_in[7];
    const float* head_w = (const float*)d_in[8];
    const float* p1     = (const float*)d_in[9];
    const float* t1     = (const float*)d_in[10];
    const float* p2     = (const float*)d_in[11];
    const float* t2     = (const float*)d_in[12];
    float* out = (float*)d_out;
    (void)in_sizes; (void)n_in; (void)out_size;

    size_t gru_sh = (size_t)(32*HSTRIDE + 4*8*3*32)*sizeof(float);   // ~134.7 KB
    size_t sh_t1  = (size_t)(256*72 + 64*72 + 2*64*16)*sizeof(float);
    size_t sh_t2  = (size_t)( 64*72 + 64*72 + 2*64*16)*sizeof(float);
    cudaFuncSetAttribute(gru_kernel, cudaFuncAttributeMaxDynamicSharedMemorySize, (int)gru_sh);
    cudaFuncSetAttribute(tail_gemm_kernel<256,25>, cudaFuncAttributeMaxDynamicSharedMemorySize, (int)sh_t1);
    cudaFuncSetAttribute(tail_gemm_kernel<64,25>,  cudaFuncAttributeMaxDynamicSharedMemorySize, (int)sh_t2);

    init_kernel<<<1,256>>>(hidden, x, len);
    classify_kernel<<<(NR_+255)/256,256>>>(x, len);

    // xp = emb[x] @ w_ih^T + b_ih    (M=4064, N=3072, K=512)
    gemm_kernel<0><<<dim3(H3_/BN,(NR_+BM-1)/BM),256>>>(
        w_ih, nullptr, nullptr, b_ih, x, emb, len, NR_, H3_, E_);

    gru_kernel<<<H_/8,1024,gru_sh>>>(w_hh, b_hh, len);

    // fused head + proj1 + proj2 (M=4064, N=2322, K=1024)
    gemm_kernel<1><<<dim3((NFUSE+BN-1)/BN,(NR_+BM-1)/BM),256>>>(
        head_w, p1, p2, nullptr, nullptr, nullptr, len, NR_, NFUSE, H_);

    head_lse_kernel<<<NR_,128>>>();

    tail_gemm_kernel<256,25><<<dim3(25, (NR_+63)/64),256,sh_t1>>>(t1, 0, S1_);
    tail_gemm_kernel<64,25> <<<dim3(25, (NR_+63)/64),256,sh_t2>>>(t2, 1, S2_);

    combine_kernel<<<dim3((NR_+255)/256,2),256>>>(t1, t2);
    finalize_kernel<<<1,256>>>(out);
}

// round 13
// speedup vs baseline: 1.7272x; 1.0323x over previous
#include <cuda_runtime.h>
#include <cuda_bf16.h>
#include <math.h>

#define V_   50000
#define C0_  2000
#define C1_  10000
#define E_   512
#define H_   1024
#define B_   32
#define T_   128
#define TS_  127
#define NR_  (B_*TS_)            // 4064
#define H3_  (3*H_)              // 3072
#define S1_  8000
#define S2_  40000

#define NFUSE (C0_+2+256+64)     // 2322 fused head+proj1+proj2 columns

// ---------------- device scratch ------------------------------------------
__device__ float g_xp[(size_t)TS_*H3_*B_];        // [t][gate-row][b]
__device__ float g_ht[2][B_*H_];                  // [b][k], double buffer
__device__ float g_out[(size_t)NR_*H_];           // [n][h]
__device__ float g_headlog[(size_t)NR_*(C0_+2)];
__device__ float g_proj1[(size_t)NR_*256];
__device__ float g_proj2[(size_t)NR_*64];
__device__ float g_head_lp[NR_];
__device__ float g_pmax[2][(size_t)NR_*32];
__device__ float g_psum[2][(size_t)NR_*32];
__device__ int   g_tgt[NR_];
__device__ int   g_valid[NR_];
__device__ int   g_list1[NR_];
__device__ int   g_list2[NR_];
__device__ int   g_cnt[2];
__device__ unsigned int g_bar;
__device__ int   g_is64x, g_is64l;

__device__ __forceinline__ int geti(const int* p, int i, int is64) {
    return p[is64 ? 2*i : i];
}

// ---------------- init ----------------------------------------------------
__global__ void init_kernel(const float* __restrict__ hidden,
                            const int* __restrict__ x,
                            const int* __restrict__ len) {
    int tid = threadIdx.x;
    if (tid == 0) {
        g_cnt[0] = 0; g_cnt[1] = 0; g_bar = 0u;
        g_is64x = (x[1] == 0 && x[3] == 0 && x[5] == 0) ? 1 : 0;
        g_is64l = (len[1] == 0) ? 1 : 0;
    }
    for (int i = tid; i < B_*H_; i += 256)
        g_ht[0][i] = hidden[i];          // [b][k] both sides
}

// ---------------- classify / compaction -----------------------------------
__global__ void classify_kernel(const int* __restrict__ x,
                                const int* __restrict__ len) {
    int n = blockIdx.x*256 + threadIdx.x;
    if (n >= NR_) return;
    int is64x = g_is64x, is64l = g_is64l;
    int b = n / TS_, t = n % TS_;
    int valid = (t < geti(len, b, is64l) - 1) ? 1 : 0;
    int tgt = geti(x, b*T_ + t + 1, is64x);
    g_valid[n] = valid;
    g_tgt[n]   = tgt;
    if (valid && tgt >= C0_) {
        int cl = (tgt < C1_) ? 0 : 1;
        int slot = atomicAdd(&g_cnt[cl], 1);
        if (cl == 0) g_list1[slot] = n; else g_list2[slot] = n;
    }
}

// ---------------- GEMM v2: C = A @ B^T, 128x128x16, 8x8 microtile ---------
#define BM 128
#define BN 128
#define BK 16

template <int MODE>
__global__ void __launch_bounds__(256)
gemm_kernel(const float* __restrict__ B0, const float* __restrict__ B1,
            const float* __restrict__ B2, const float* __restrict__ bias,
            const int* __restrict__ x, const float* __restrict__ emb,
            const int* __restrict__ len, int M, int N, int K)
{
    __shared__ __align__(16) float As[BK][BM+4];
    __shared__ __align__(16) float Bs[BK][BN+4];

    int m0 = blockIdx.y * BM;
    int n0 = blockIdx.x * BN;
    int tid = threadIdx.x;
    int is64x = g_is64x, is64l = g_is64l;

    if (MODE != 0) {
        int pred = 0;
        if (tid < BM) {
            int m = m0 + tid;
            if (m < M) {
                int b = m / TS_, t = m % TS_;
                pred = (t < geti(len, b, is64l) - 1);
            }
        }
        if (!__syncthreads_or(pred)) return;
    }

    const float* asrc[2];
    const float* bsrc[2];
    int arow[2], brow[2];
#pragma unroll
    for (int i = 0; i < 2; i++) {
        int f   = tid*2 + i;
        int row = f >> 2;
        int kk  = (f & 3) * 4;
        arow[i] = row; brow[i] = row;
        int m = m0 + row;
        if (m < M) {
            if (MODE == 0) {
                int t = m >> 5, b = m & 31;
                int tok = geti(x, b*T_ + t, is64x);
                asrc[i] = emb + (size_t)tok*E_ + kk;
            } else {
                asrc[i] = g_out + (size_t)m*K + kk;
            }
        } else asrc[i] = nullptr;
        int n = n0 + row;
        if (n < N) {
            if (MODE == 0) {
                bsrc[i] = B0 + (size_t)n*K + kk;
            } else {
                if (n < C0_+2)            bsrc[i] = B0 + (size_t)n*K + kk;
                else if (n < C0_+2+256)   bsrc[i] = B1 + (size_t)(n-(C0_+2))*K + kk;
                else                      bsrc[i] = B2 + (size_t)(n-(C0_+2+256))*K + kk;
            }
        } else bsrc[i] = nullptr;
    }

    float acc[8][8];
#pragma unroll
    for (int i = 0; i < 8; i++)
#pragma unroll
        for (int j = 0; j < 8; j++) acc[i][j] = 0.f;

    int tm = tid >> 4;
    int tn = tid & 15;

    for (int kb = 0; kb < K; kb += BK) {
#pragma unroll
        for (int i = 0; i < 2; i++) {
            int f  = tid*2 + i;
            int kk = (f & 3) * 4;
            float4 v = make_float4(0.f,0.f,0.f,0.f);
            if (asrc[i]) v = *(const float4*)(asrc[i] + kb);
            As[kk+0][arow[i]]=v.x; As[kk+1][arow[i]]=v.y;
            As[kk+2][arow[i]]=v.z; As[kk+3][arow[i]]=v.w;
            float4 w = make_float4(0.f,0.f,0.f,0.f);
            if (bsrc[i]) w = *(const float4*)(bsrc[i] + kb);
            Bs[kk+0][brow[i]]=w.x; Bs[kk+1][brow[i]]=w.y;
            Bs[kk+2][brow[i]]=w.z; Bs[kk+3][brow[i]]=w.w;
        }
        __syncthreads();
#pragma unroll
        for (int k = 0; k < BK; k++) {
            float4 a0 = *(const float4*)&As[k][tm*8];
            float4 a1 = *(const float4*)&As[k][tm*8+4];
            float4 b0 = *(const float4*)&Bs[k][tn*8];
            float4 b1 = *(const float4*)&Bs[k][tn*8+4];
            float av[8] = {a0.x,a0.y,a0.z,a0.w,a1.x,a1.y,a1.z,a1.w};
            float bv[8] = {b0.x,b0.y,b0.z,b0.w,b1.x,b1.y,b1.z,b1.w};
#pragma unroll
            for (int i = 0; i < 8; i++)
#pragma unroll
                for (int j = 0; j < 8; j++)
                    acc[i][j] = fmaf(av[i], bv[j], acc[i][j]);
        }
        __syncthreads();
    }

#pragma unroll
    for (int i = 0; i < 8; i++) {
        int m = m0 + tm*8 + i;
        if (m >= M) continue;
#pragma unroll
        for (int j = 0; j < 8; j++) {
            int n = n0 + tn*8 + j;
            if (n >= N) continue;
            float v = acc[i][j];
            if (MODE == 0) {
                int t = m >> 5, b = m & 31;
                g_xp[((size_t)t*H3_ + n)*B_ + b] = v + bias[n];
            } else {
                if (n < C0_+2)          g_headlog[(size_t)m*(C0_+2) + n] = v;
                else if (n < C0_+2+256) g_proj1[(size_t)m*256 + (n-(C0_+2))] = v;
                else                    g_proj2[(size_t)m*64  + (n-(C0_+2+256))] = v;
            }
        }
    }
}

// ---------------- persistent GRU v3 ---------------------------------------
// 128 blocks x 512 threads. Each warp covers ALL 8 j-columns of its block and
// a 64-wide k-slice (16 warps x 64k = 1024). Lanes = b. h is read from skewed
// smem ONCE per SM per step (was 8x redundant). Partials reduced via smem.
#define HSTRIDE 1028
#define GRU_RED (32*HSTRIDE)     // red[16][8][3][32] floats after h

__global__ void __launch_bounds__(512)
gru_kernel(const float* __restrict__ whh, const float* __restrict__ bhh,
           const int* __restrict__ len)
{
    extern __shared__ float sm[];
    float* hs  = sm;                     // [32][HSTRIDE]
    float* red = sm + GRU_RED;           // [16][8][3][32]

    int tid = threadIdx.x;
    int ws  = tid >> 5;                  // k-slice 0..15
    int b   = tid & 31;
    int j0  = blockIdx.x*8;
    int k0  = ws*64;

    const float* wr = whh + (size_t)(          j0)*H_ + k0;
    const float* wz = whh + (size_t)(H_   +    j0)*H_ + k0;
    const float* wn = whh + (size_t)(2*H_ +    j0)*H_ + k0;

    // finisher thread mapping (tid < 256): jl = tid>>5, b = tid&31
    int fjl  = tid >> 5;                 // valid when tid<256
    float bR = bhh[j0 + (fjl & 7)];
    float bZ = bhh[H_   + j0 + (fjl & 7)];
    float bN = bhh[2*H_ + j0 + (fjl & 7)];
    int len1 = geti(len, b, g_is64l) - 1;

    for (int t = 0; t < TS_; t++) {
        // stage h: global [b][k] -> smem skewed [b][k]
        const float4* src = (const float4*)g_ht[t & 1];
        for (int i = tid; i < B_*H_/4; i += 512) {
            float4 v = __ldcg(src + i);
            int bb = i >> 8, kq = i & 255;
            *(float4*)&hs[bb*HSTRIDE + kq*4] = v;
        }
        __syncthreads();

        float acc[8][3];
#pragma unroll
        for (int j = 0; j < 8; j++)
#pragma unroll
            for (int g = 0; g < 3; g++) acc[j][g] = 0.f;

        const float* hb = hs + b*HSTRIDE + k0;
#pragma unroll 2
        for (int kk = 0; kk < 64; kk += 8) {
            float4 h0 = *(const float4*)&hb[kk];
            float4 h1 = *(const float4*)&hb[kk+4];
#pragma unroll
            for (int j = 0; j < 8; j++) {
                float4 r0 = __ldg((const float4*)(wr + (size_t)j*H_ + kk));
                float4 r1 = __ldg((const float4*)(wr + (size_t)j*H_ + kk + 4));
                float4 z0 = __ldg((const float4*)(wz + (size_t)j*H_ + kk));
                float4 z1 = __ldg((const float4*)(wz + (size_t)j*H_ + kk + 4));
                float4 n0 = __ldg((const float4*)(wn + (size_t)j*H_ + kk));
                float4 n1 = __ldg((const float4*)(wn + (size_t)j*H_ + kk + 4));
                acc[j][0] = fmaf(r0.x,h0.x, fmaf(r0.y,h0.y, fmaf(r0.z,h0.z, fmaf(r0.w,h0.w, acc[j][0]))));
                acc[j][0] = fmaf(r1.x,h1.x, fmaf(r1.y,h1.y, fmaf(r1.z,h1.z, fmaf(r1.w,h1.w, acc[j][0]))));
                acc[j][1] = fmaf(z0.x,h0.x, fmaf(z0.y,h0.y, fmaf(z0.z,h0.z, fmaf(z0.w,h0.w, acc[j][1]))));
                acc[j][1] = fmaf(z1.x,h1.x, fmaf(z1.y,h1.y, fmaf(z1.z,h1.z, fmaf(z1.w,h1.w, acc[j][1]))));
                acc[j][2] = fmaf(n0.x,h0.x, fmaf(n0.y,h0.y, fmaf(n0.z,h0.z, fmaf(n0.w,h0.w, acc[j][2]))));
                acc[j][2] = fmaf(n1.x,h1.x, fmaf(n1.y,h1.y, fmaf(n1.z,h1.z, fmaf(n1.w,h1.w, acc[j][2]))));
            }
        }

        // write partials red[ws][j][g][b]
#pragma unroll
        for (int j = 0; j < 8; j++)
#pragma unroll
            for (int g = 0; g < 3; g++)
                red[(((ws*8 + j)*3) + g)*32 + b] = acc[j][g];
        __syncthreads();

        if (tid < 256) {
            int jl = fjl;               // 0..7
            float ar = bR, az = bZ, an = bN;
#pragma unroll
            for (int w2 = 0; w2 < 16; w2++) {
                const float* c = red + ((w2*8 + jl)*3)*32 + b;
                ar += c[0]; az += c[32]; an += c[64];
            }
            int j = j0 + jl;
            const float* xpb = g_xp + (size_t)t*H3_*B_;
            float xr = __ldcg(&xpb[(size_t)(      j)*B_ + b]);
            float xz = __ldcg(&xpb[(size_t)(H_  + j)*B_ + b]);
            float xn = __ldcg(&xpb[(size_t)(2*H_+ j)*B_ + b]);

            float r  = 1.f / (1.f + __expf(-(xr + ar)));
            float z  = 1.f / (1.f + __expf(-(xz + az)));
            float nn = tanhf(xn + r*an);
            float hp = hs[b*HSTRIDE + j];
            float hnew = (1.f - z)*nn + z*hp;

            int valid = (t < len1);
            __stcg(&g_ht[(t+1) & 1][b*H_ + j], valid ? hnew : hp);
            __stcg(&g_out[(size_t)(b*TS_ + t)*H_ + j], valid ? hnew : 0.f);
        }

        __threadfence();
        __syncthreads();
        if (tid == 0) {
            atomicAdd(&g_bar, 1u);
            unsigned goal = (unsigned)gridDim.x * (unsigned)(t+1);
            volatile unsigned* p = &g_bar;
            while (*p < goal) {}
            __threadfence();
        }
        __syncthreads();
    }
}

// ---------------- head log-softmax ----------------------------------------
__global__ void __launch_bounds__(128)
head_lse_kernel()
{
    int n = blockIdx.x;
    if (!g_valid[n]) return;
    int tid = threadIdx.x;
    const float* lg = g_headlog + (size_t)n*(C0_+2);
    __shared__ float sm[4];

    float m = -1e30f;
    for (int i = tid; i < C0_+2; i += 128) m = fmaxf(m, lg[i]);
#pragma unroll
    for (int o = 16; o > 0; o >>= 1) m = fmaxf(m, __shfl_xor_sync(~0u, m, o));
    if ((tid & 31) == 0) sm[tid >> 5] = m;
    __syncthreads();
    m = fmaxf(fmaxf(sm[0], sm[1]), fmaxf(sm[2], sm[3]));

    float s = 0.f;
    for (int i = tid; i < C0_+2; i += 128) s += __expf(lg[i] - m);
#pragma unroll
    for (int o = 16; o > 0; o >>= 1) s += __shfl_xor_sync(~0u, s, o);
    if ((tid & 31) == 0) sm[tid >> 5] = s;
    __syncthreads();
    if (tid == 0) {
        s = sm[0] + sm[1] + sm[2] + sm[3];
        int tgt = g_tgt[n];
        int sel = (tgt < C0_) ? tgt : ((tgt < C1_) ? C0_ : C0_+1);
        g_head_lp[n] = lg[sel] - (m + logf(s));
    }
}

// ---------------- fused tail GEMM + online logsumexp ----------------------
template <int KD, int NSLAB>
__global__ void __launch_bounds__(256)
tail_gemm_kernel(const float* __restrict__ tmat, int cluster, int S)
{
    extern __shared__ float sm[];
    float* As = sm;                          // [KD][72]
    float* Bs = As + KD*72;                  // [64][72]
    float* Rm = Bs + 64*72;                  // [64][16]
    float* Rs = Rm + 64*16;

    int cnt = g_cnt[cluster];
    int r0 = blockIdx.y * 64;
    if (r0 >= cnt) return;
    int tid = threadIdx.x;
    const int*   list = cluster ? g_list2 : g_list1;
    const float* proj = cluster ? g_proj2 : g_proj1;

    for (int idx = tid; idx < 64*KD; idx += 256) {
        int r = idx / KD, k = idx % KD;
        float v = 0.f;
        if (r0 + r < cnt) v = proj[(size_t)list[r0+r]*KD + k];
        As[k*72 + r] = v;
    }
    __syncthreads();

    int tm = tid >> 4, tn = tid & 15;
    float rm[4], rs[4];
#pragma unroll
    for (int i = 0; i < 4; i++) { rm[i] = -1e30f; rs[i] = 0.f; }

    const int SLAB = S / NSLAB;
    const int SCH  = SLAB / 64;
    int sbase = blockIdx.x * SLAB;

    for (int sc = 0; sc < SCH; sc++) {
        int s0 = sbase + sc*64;
        float acc[4][4];
#pragma unroll
        for (int i = 0; i < 4; i++)
#pragma unroll
            for (int jj = 0; jj < 4; jj++) acc[i][jj] = 0.f;

        for (int kc = 0; kc < KD; kc += 64) {
            for (int idx = tid; idx < 1024; idx += 256) {
                int srow = idx >> 4;
                int c4   = idx & 15;
                float4 v = *(const float4*)(tmat + (size_t)(s0+srow)*KD + kc + c4*4);
                Bs[(c4*4+0)*72+srow]=v.x; Bs[(c4*4+1)*72+srow]=v.y;
                Bs[(c4*4+2)*72+srow]=v.z; Bs[(c4*4+3)*72+srow]=v.w;
            }
            __syncthreads();
#pragma unroll 8
            for (int k = 0; k < 64; k++) {
                float4 a = *(const float4*)&As[(kc+k)*72 + tm*4];
                float4 bv = *(const float4*)&Bs[k*72 + tn*4];
                float av[4] = {a.x,a.y,a.z,a.w};
                float bb[4] = {bv.x,bv.y,bv.z,bv.w};
#pragma unroll
                for (int i = 0; i < 4; i++)
#pragma unroll
                    for (int jj = 0; jj < 4; jj++)
                        acc[i][jj] = fmaf(av[i], bb[jj], acc[i][jj]);
            }
            __syncthreads();
        }
#pragma unroll
        for (int i = 0; i < 4; i++) {
            float vm = fmaxf(fmaxf(acc[i][0], acc[i][1]), fmaxf(acc[i][2], acc[i][3]));
            float nm = fmaxf(rm[i], vm);
            rs[i] = rs[i]*__expf(rm[i]-nm)
                  + __expf(acc[i][0]-nm) + __expf(acc[i][1]-nm)
                  + __expf(acc[i][2]-nm) + __expf(acc[i][3]-nm);
            rm[i] = nm;
        }
    }

#pragma unroll
    for (int i = 0; i < 4; i++) {
        Rm[(tm*4+i)*16 + tn] = rm[i];
        Rs[(tm*4+i)*16 + tn] = rs[i];
    }
    __syncthreads();
    if (tid < 64) {
        float m = -1e30f;
#pragma unroll
        for (int c = 0; c < 16; c++) m = fmaxf(m, Rm[tid*16+c]);
        float s = 0.f;
#pragma unroll
        for (int c = 0; c < 16; c++) s += Rs[tid*16+c]*__expf(Rm[tid*16+c]-m);
        if (r0 + tid < cnt) {
            g_pmax[cluster][(size_t)(r0+tid)*32 + blockIdx.x] = m;
            g_psum[cluster][(size_t)(r0+tid)*32 + blockIdx.x] = s;
        }
    }
}

// ---------------- combine tail partials + target logit --------------------
__global__ void combine_kernel(const float* __restrict__ t1,
                               const float* __restrict__ t2)
{
    int cl = blockIdx.y;
    int slot = blockIdx.x*256 + threadIdx.x;
    if (slot >= g_cnt[cl]) return;
    int n = cl ? g_list2[slot] : g_list1[slot];
    int tgt = g_tgt[n];
    int KD = cl ? 64 : 256;
    int NS = 25;
    const float* pr = cl ? (g_proj2 + (size_t)n*64) : (g_proj1 + (size_t)n*256);
    const float* tr = cl ? (t2 + (size_t)(tgt - C1_)*64)
                         : (t1 + (size_t)(tgt - C0_)*256);
    float d = 0.f;
    for (int k = 0; k < KD; k++) d = fmaf(pr[k], tr[k], d);

    const float* pm = &g_pmax[cl][(size_t)slot*32];
    const float* ps = &g_psum[cl][(size_t)slot*32];
    float m = -1e30f;
    for (int s = 0; s < NS; s++) m = fmaxf(m, pm[s]);
    float su = 0.f;
    for (int s = 0; s < NS; s++) su += ps[s]*__expf(pm[s]-m);
    g_head_lp[n] += d - (m + logf(su));
}

// ---------------- final reduction + hT output -----------------------------
__global__ void finalize_kernel(float* __restrict__ out)
{
    __shared__ float sh[256];
    int tid = threadIdx.x;
    const float L2002 = logf(2002.0f);
    float acc = 0.f;
    for (int n = tid; n < NR_; n += 256)
        acc += g_valid[n] ? g_head_lp[n] : -L2002;
    sh[tid] = acc; __syncthreads();
    for (int s = 128; s > 0; s >>= 1) {
        if (tid < s) sh[tid] += sh[tid+s];
        __syncthreads();
    }
    if (tid == 0) out[0] = -sh[0] / (float)NR_;
    const float* hf = g_ht[1];            // [b][k] after 127 steps
    for (int i = tid; i < B_*H_; i += 256)
        out[1 + i] = hf[i];
}

// ---------------- launcher ------------------------------------------------
extern "C" void kernel_launch(void* const* d_in, const int* in_sizes, int n_in,
                              void* d_out, int out_size)
{
    const int*   x      = (const int*)  d_in[0];
    const int*   len    = (const int*)  d_in[1];
    const float* hidden = (const float*)d_in[2];
    const float* emb    = (const float*)d_in[3];
    const float* w_ih   = (const float*)d_in[4];
    const float* w_hh   = (const float*)d_in[5];
    const float* b_ih   = (const float*)d_in[6];
    const float* b_hh   = (const float*)d_in[7];
    const float* head_w = (const float*)d_in[8];
    const float* p1     = (const float*)d_in[9];
    const float* t1     = (const float*)d_in[10];
    const float* p2     = (const float*)d_in[11];
    const float* t2     = (const float*)d_in[12];
    float* out = (float*)d_out;
    (void)in_sizes; (void)n_in; (void)out_size;

    size_t gru_sh = (size_t)(32*HSTRIDE + 16*8*3*32)*sizeof(float);  // ~180.7 KB
    size_t sh_t1  = (size_t)(256*72 + 64*72 + 2*64*16)*sizeof(float);
    size_t sh_t2  = (size_t)( 64*72 + 64*72 + 2*64*16)*sizeof(float);
    cudaFuncSetAttribute(gru_kernel, cudaFuncAttributeMaxDynamicSharedMemorySize, (int)gru_sh);
    cudaFuncSetAttribute(tail_gemm_kernel<256,25>, cudaFuncAttributeMaxDynamicSharedMemorySize, (int)sh_t1);
    cudaFuncSetAttribute(tail_gemm_kernel<64,25>,  cudaFuncAttributeMaxDynamicSharedMemorySize, (int)sh_t2);

    init_kernel<<<1,256>>>(hidden, x, len);
    classify_kernel<<<(NR_+255)/256,256>>>(x, len);

    // xp = emb[x] @ w_ih^T + b_ih    (M=4064, N=3072, K=512)
    gemm_kernel<0><<<dim3(H3_/BN,(NR_+BM-1)/BM),256>>>(
        w_ih, nullptr, nullptr, b_ih, x, emb, len, NR_, H3_, E_);

    gru_kernel<<<H_/8,512,gru_sh>>>(w_hh, b_hh, len);

    // fused head + proj1 + proj2 (M=4064, N=2322, K=1024)
    gemm_kernel<1><<<dim3((NFUSE+BN-1)/BN,(NR_+BM-1)/BM),256>>>(
        head_w, p1, p2, nullptr, nullptr, nullptr, len, NR_, NFUSE, H_);

    head_lse_kernel<<<NR_,128>>>();

    tail_gemm_kernel<256,25><<<dim3(25, (NR_+63)/64),256,sh_t1>>>(t1, 0, S1_);
    tail_gemm_kernel<64,25> <<<dim3(25, (NR_+63)/64),256,sh_t2>>>(t2, 1, S2_);

    combine_kernel<<<dim3((NR_+255)/256,2),256>>>(t1, t2);
    finalize_kernel<<<1,256>>>(out);
}

// round 15
// speedup vs baseline: 1.8312x; 1.0602x over previous
#include <cuda_runtime.h>
#include <cuda_bf16.h>
#include <stdint.h>
#include <cstdint>
#include <math.h>

#define V_   50000
#define C0_  2000
#define C1_  10000
#define E_   512
#define H_   1024
#define B_   32
#define T_   128
#define TS_  127
#define NR_  (B_*TS_)            // 4064
#define H3_  (3*H_)              // 3072
#define S1_  8000
#define S2_  40000

#define NFUSE (C0_+2+256+64)     // 2322 fused head+proj1+proj2 columns

// ---------------- device scratch ------------------------------------------
__device__ float g_xp[(size_t)TS_*H3_*B_];        // [t][gate-row][b]
__device__ float g_ht[2][B_*H_];                  // [b][k], double buffer
__device__ float g_out[(size_t)NR_*H_];           // [n][h]
__device__ float g_headlog[(size_t)NR_*(C0_+2)];
__device__ float g_proj1[(size_t)NR_*256];
__device__ float g_proj2[(size_t)NR_*64];
__device__ float g_head_lp[NR_];
__device__ float g_pmax[2][(size_t)NR_*32];
__device__ float g_psum[2][(size_t)NR_*32];
__device__ int   g_tgt[NR_];
__device__ int   g_valid[NR_];
__device__ int   g_list1[NR_];
__device__ int   g_list2[NR_];
__device__ int   g_cnt[2];
__device__ unsigned int g_bar;
__device__ int   g_is64x, g_is64l;

__device__ __forceinline__ int geti(const int* p, int i, int is64) {
    return p[is64 ? 2*i : i];
}

__device__ __forceinline__ uint32_t f2tf(float f) {
    uint32_t u;
    asm("cvt.rna.tf32.f32 %0, %1;" : "=r"(u) : "f"(f));
    return u;
}

__device__ __forceinline__ void mma_tf32(float& d0, float& d1, float& d2, float& d3,
                                         uint32_t a0, uint32_t a1, uint32_t a2, uint32_t a3,
                                         uint32_t b0, uint32_t b1) {
    asm volatile(
        "mma.sync.aligned.m16n8k8.row.col.f32.tf32.tf32.f32 "
        "{%0,%1,%2,%3},{%4,%5,%6,%7},{%8,%9},{%0,%1,%2,%3};"
        : "+f"(d0), "+f"(d1), "+f"(d2), "+f"(d3)
        : "r"(a0), "r"(a1), "r"(a2), "r"(a3), "r"(b0), "r"(b1));
}

// ---------------- init ----------------------------------------------------
__global__ void init_kernel(const float* __restrict__ hidden,
                            const int* __restrict__ x,
                            const int* __restrict__ len) {
    int tid = threadIdx.x;
    if (tid == 0) {
        g_cnt[0] = 0; g_cnt[1] = 0; g_bar = 0u;
        g_is64x = (x[1] == 0 && x[3] == 0 && x[5] == 0) ? 1 : 0;
        g_is64l = (len[1] == 0) ? 1 : 0;
    }
    for (int i = tid; i < B_*H_; i += 256)
        g_ht[0][i] = hidden[i];          // [b][k] both sides
}

// ---------------- classify / compaction -----------------------------------
__global__ void classify_kernel(const int* __restrict__ x,
                                const int* __restrict__ len) {
    int n = blockIdx.x*256 + threadIdx.x;
    if (n >= NR_) return;
    int is64x = g_is64x, is64l = g_is64l;
    int b = n / TS_, t = n % TS_;
    int valid = (t < geti(len, b, is64l) - 1) ? 1 : 0;
    int tgt = geti(x, b*T_ + t + 1, is64x);
    g_valid[n] = valid;
    g_tgt[n]   = tgt;
    if (valid && tgt >= C0_) {
        int cl = (tgt < C1_) ? 0 : 1;
        int slot = atomicAdd(&g_cnt[cl], 1);
        if (cl == 0) g_list1[slot] = n; else g_list2[slot] = n;
    }
}

// ---------------- GEMM (fp32) for xp --------------------------------------
#define BM 128
#define BN 128
#define BK 16

template <int MODE>
__global__ void __launch_bounds__(256)
gemm_kernel(const float* __restrict__ B0, const float* __restrict__ bias,
            const int* __restrict__ x, const float* __restrict__ emb,
            const int* __restrict__ len, int M, int N, int K)
{
    __shared__ __align__(16) float As[BK][BM+4];
    __shared__ __align__(16) float Bs[BK][BN+4];

    int m0 = blockIdx.y * BM;
    int n0 = blockIdx.x * BN;
    int tid = threadIdx.x;
    int is64x = g_is64x;

    const float* asrc[2];
    const float* bsrc[2];
    int arow[2], brow[2];
#pragma unroll
    for (int i = 0; i < 2; i++) {
        int f   = tid*2 + i;
        int row = f >> 2;
        int kk  = (f & 3) * 4;
        arow[i] = row; brow[i] = row;
        int m = m0 + row;
        if (m < M) {
            int t = m >> 5, b = m & 31;
            int tok = geti(x, b*T_ + t, is64x);
            asrc[i] = emb + (size_t)tok*E_ + kk;
        } else asrc[i] = nullptr;
        int n = n0 + row;
        bsrc[i] = (n < N) ? (B0 + (size_t)n*K + kk) : nullptr;
    }

    float acc[8][8];
#pragma unroll
    for (int i = 0; i < 8; i++)
#pragma unroll
        for (int j = 0; j < 8; j++) acc[i][j] = 0.f;

    int tm = tid >> 4;
    int tn = tid & 15;

    for (int kb = 0; kb < K; kb += BK) {
#pragma unroll
        for (int i = 0; i < 2; i++) {
            int f  = tid*2 + i;
            int kk = (f & 3) * 4;
            float4 v = make_float4(0.f,0.f,0.f,0.f);
            if (asrc[i]) v = *(const float4*)(asrc[i] + kb);
            As[kk+0][arow[i]]=v.x; As[kk+1][arow[i]]=v.y;
            As[kk+2][arow[i]]=v.z; As[kk+3][arow[i]]=v.w;
            float4 w = make_float4(0.f,0.f,0.f,0.f);
            if (bsrc[i]) w = *(const float4*)(bsrc[i] + kb);
            Bs[kk+0][brow[i]]=w.x; Bs[kk+1][brow[i]]=w.y;
            Bs[kk+2][brow[i]]=w.z; Bs[kk+3][brow[i]]=w.w;
        }
        __syncthreads();
#pragma unroll
        for (int k = 0; k < BK; k++) {
            float4 a0 = *(const float4*)&As[k][tm*8];
            float4 a1 = *(const float4*)&As[k][tm*8+4];
            float4 b0 = *(const float4*)&Bs[k][tn*8];
            float4 b1 = *(const float4*)&Bs[k][tn*8+4];
            float av[8] = {a0.x,a0.y,a0.z,a0.w,a1.x,a1.y,a1.z,a1.w};
            float bv[8] = {b0.x,b0.y,b0.z,b0.w,b1.x,b1.y,b1.z,b1.w};
#pragma unroll
            for (int i = 0; i < 8; i++)
#pragma unroll
                for (int j = 0; j < 8; j++)
                    acc[i][j] = fmaf(av[i], bv[j], acc[i][j]);
        }
        __syncthreads();
    }

#pragma unroll
    for (int i = 0; i < 8; i++) {
        int m = m0 + tm*8 + i;
        if (m >= M) continue;
        int t = m >> 5, b = m & 31;
#pragma unroll
        for (int j = 0; j < 8; j++) {
            int n = n0 + tn*8 + j;
            if (n >= N) continue;
            g_xp[((size_t)t*H3_ + n)*B_ + b] = acc[i][j] + bias[n];
        }
    }
}

// ---------------- fused head+proj GEMM in tf32 mma ------------------------
// C = A @ B^T, A = g_out [4064,1024], fused N = 2322 (head 2002 | p1 256 | p2 64)
// block 256 thr = 8 warps (4 M x 2 N), block tile 128x64, BK=16.
#define ASTR 136
#define BSTR 72

__device__ __forceinline__ void fused_store(int m, int n, float v) {
    if (n < C0_+2)          g_headlog[(size_t)m*(C0_+2) + n] = v;
    else if (n < C0_+2+256) g_proj1[(size_t)m*256 + (n-(C0_+2))] = v;
    else                    g_proj2[(size_t)m*64  + (n-(C0_+2+256))] = v;
}

__global__ void __launch_bounds__(256)
gemm_tf32_fused(const float* __restrict__ B0, const float* __restrict__ B1,
                const float* __restrict__ B2, const int* __restrict__ len,
                int M, int N, int K)
{
    __shared__ uint32_t As[BK][ASTR];
    __shared__ uint32_t Bs[BK][BSTR];

    int m0 = blockIdx.y * 128;
    int n0 = blockIdx.x * 64;
    int tid = threadIdx.x;
    int is64l = g_is64l;

    // tile-skip: all-padding row tiles produce exactly-zero outputs elsewhere
    {
        int pred = 0;
        if (tid < 128) {
            int m = m0 + tid;
            if (m < M) {
                int b = m / TS_, t = m % TS_;
                pred = (t < geti(len, b, is64l) - 1);
            }
        }
        if (!__syncthreads_or(pred)) return;
    }

    // staging sources
    const float* asrc[2];
    int arow[2];
#pragma unroll
    for (int i = 0; i < 2; i++) {
        int f   = tid*2 + i;
        int row = f >> 2;            // 0..127
        int kk  = (f & 3) * 4;
        arow[i] = row;
        int m = m0 + row;
        asrc[i] = (m < M) ? (g_out + (size_t)m*K + kk) : nullptr;
    }
    const float* bsrc;
    int brow = tid >> 2;             // 0..63
    {
        int kk = (tid & 3) * 4;
        int n = n0 + brow;
        if (n < N) {
            if (n < C0_+2)            bsrc = B0 + (size_t)n*K + kk;
            else if (n < C0_+2+256)   bsrc = B1 + (size_t)(n-(C0_+2))*K + kk;
            else                      bsrc = B2 + (size_t)(n-(C0_+2+256))*K + kk;
        } else bsrc = nullptr;
    }

    int lane = tid & 31;
    int warp = tid >> 5;
    int wm = warp & 3;               // 0..3 -> M offset 32*wm
    int wn = warp >> 2;              // 0..1 -> N offset 32*wn
    int gr = lane >> 2;              // groupID 0..7
    int gc = lane & 3;               // thread-in-group 0..3

    float acc[2][4][4];
#pragma unroll
    for (int mt = 0; mt < 2; mt++)
#pragma unroll
        for (int nt = 0; nt < 4; nt++)
#pragma unroll
            for (int e = 0; e < 4; e++) acc[mt][nt][e] = 0.f;

    for (int kb = 0; kb < K; kb += BK) {
        // stage A (128x16) as tf32
#pragma unroll
        for (int i = 0; i < 2; i++) {
            int f  = tid*2 + i;
            int kk = (f & 3) * 4;
            float4 v = make_float4(0.f,0.f,0.f,0.f);
            if (asrc[i]) v = *(const float4*)(asrc[i] + kb);
            As[kk+0][arow[i]] = f2tf(v.x);
            As[kk+1][arow[i]] = f2tf(v.y);
            As[kk+2][arow[i]] = f2tf(v.z);
            As[kk+3][arow[i]] = f2tf(v.w);
        }
        // stage B (64x16) as tf32
        {
            int kk = (tid & 3) * 4;
            float4 v = make_float4(0.f,0.f,0.f,0.f);
            if (bsrc) v = *(const float4*)(bsrc + kb);
            Bs[kk+0][brow] = f2tf(v.x);
            Bs[kk+1][brow] = f2tf(v.y);
            Bs[kk+2][brow] = f2tf(v.z);
            Bs[kk+3][brow] = f2tf(v.w);
        }
        __syncthreads();

#pragma unroll
        for (int ks = 0; ks < BK; ks += 8) {
            uint32_t a[2][4], bfr[4][2];
#pragma unroll
            for (int mt = 0; mt < 2; mt++) {
                int mr = wm*32 + mt*16 + gr;
                a[mt][0] = As[ks+gc  ][mr];
                a[mt][1] = As[ks+gc  ][mr+8];
                a[mt][2] = As[ks+gc+4][mr];
                a[mt][3] = As[ks+gc+4][mr+8];
            }
#pragma unroll
            for (int nt = 0; nt < 4; nt++) {
                int nc = wn*32 + nt*8 + gr;
                bfr[nt][0] = Bs[ks+gc  ][nc];
                bfr[nt][1] = Bs[ks+gc+4][nc];
            }
#pragma unroll
            for (int mt = 0; mt < 2; mt++)
#pragma unroll
                for (int nt = 0; nt < 4; nt++)
                    mma_tf32(acc[mt][nt][0], acc[mt][nt][1], acc[mt][nt][2], acc[mt][nt][3],
                             a[mt][0], a[mt][1], a[mt][2], a[mt][3],
                             bfr[nt][0], bfr[nt][1]);
        }
        __syncthreads();
    }

    // epilogue: d0:(r,c0) d1:(r,c0+1) d2:(r+8,c0) d3:(r+8,c0+1)
#pragma unroll
    for (int mt = 0; mt < 2; mt++) {
        int r0 = m0 + wm*32 + mt*16 + gr;
        int r1 = r0 + 8;
#pragma unroll
        for (int nt = 0; nt < 4; nt++) {
            int c0 = n0 + wn*32 + nt*8 + gc*2;
            if (r0 < M) {
                if (c0   < N) fused_store(r0, c0,   acc[mt][nt][0]);
                if (c0+1 < N) fused_store(r0, c0+1, acc[mt][nt][1]);
            }
            if (r1 < M) {
                if (c0   < N) fused_store(r1, c0,   acc[mt][nt][2]);
                if (c0+1 < N) fused_store(r1, c0+1, acc[mt][nt][3]);
            }
        }
    }
}

// ---------------- persistent GRU v3 ---------------------------------------
#define HSTRIDE 1028
#define GRU_RED (32*HSTRIDE)

__global__ void __launch_bounds__(512)
gru_kernel(const float* __restrict__ whh, const float* __restrict__ bhh,
           const int* __restrict__ len)
{
    extern __shared__ float sm[];
    float* hs  = sm;                     // [32][HSTRIDE]
    float* red = sm + GRU_RED;           // [16][8][3][32]

    int tid = threadIdx.x;
    int ws  = tid >> 5;                  // k-slice 0..15
    int b   = tid & 31;
    int j0  = blockIdx.x*8;
    int k0  = ws*64;

    const float* wr = whh + (size_t)(          j0)*H_ + k0;
    const float* wz = whh + (size_t)(H_   +    j0)*H_ + k0;
    const float* wn = whh + (size_t)(2*H_ +    j0)*H_ + k0;

    int fjl  = tid >> 5;                 // finisher j (tid<256)
    float bR = bhh[j0 + (fjl & 7)];
    float bZ = bhh[H_   + j0 + (fjl & 7)];
    float bN = bhh[2*H_ + j0 + (fjl & 7)];
    int len1 = geti(len, b, g_is64l) - 1;

    for (int t = 0; t < TS_; t++) {
        const float4* src = (const float4*)g_ht[t & 1];
        for (int i = tid; i < B_*H_/4; i += 512) {
            float4 v = __ldcg(src + i);
            int bb = i >> 8, kq = i & 255;
            *(float4*)&hs[bb*HSTRIDE + kq*4] = v;
        }
        __syncthreads();

        float acc[8][3];
#pragma unroll
        for (int j = 0; j < 8; j++)
#pragma unroll
            for (int g = 0; g < 3; g++) acc[j][g] = 0.f;

        const float* hb = hs + b*HSTRIDE + k0;
#pragma unroll 2
        for (int kk = 0; kk < 64; kk += 8) {
            float4 h0 = *(const float4*)&hb[kk];
            float4 h1 = *(const float4*)&hb[kk+4];
#pragma unroll
            for (int j = 0; j < 8; j++) {
                float4 r0 = __ldg((const float4*)(wr + (size_t)j*H_ + kk));
                float4 r1 = __ldg((const float4*)(wr + (size_t)j*H_ + kk + 4));
                float4 z0 = __ldg((const float4*)(wz + (size_t)j*H_ + kk));
                float4 z1 = __ldg((const float4*)(wz + (size_t)j*H_ + kk + 4));
                float4 n0 = __ldg((const float4*)(wn + (size_t)j*H_ + kk));
                float4 n1 = __ldg((const float4*)(wn + (size_t)j*H_ + kk + 4));
                acc[j][0] = fmaf(r0.x,h0.x, fmaf(r0.y,h0.y, fmaf(r0.z,h0.z, fmaf(r0.w,h0.w, acc[j][0]))));
                acc[j][0] = fmaf(r1.x,h1.x, fmaf(r1.y,h1.y, fmaf(r1.z,h1.z, fmaf(r1.w,h1.w, acc[j][0]))));
                acc[j][1] = fmaf(z0.x,h0.x, fmaf(z0.y,h0.y, fmaf(z0.z,h0.z, fmaf(z0.w,h0.w, acc[j][1]))));
                acc[j][1] = fmaf(z1.x,h1.x, fmaf(z1.y,h1.y, fmaf(z1.z,h1.z, fmaf(z1.w,h1.w, acc[j][1]))));
                acc[j][2] = fmaf(n0.x,h0.x, fmaf(n0.y,h0.y, fmaf(n0.z,h0.z, fmaf(n0.w,h0.w, acc[j][2]))));
                acc[j][2] = fmaf(n1.x,h1.x, fmaf(n1.y,h1.y, fmaf(n1.z,h1.z, fmaf(n1.w,h1.w, acc[j][2]))));
            }
        }

#pragma unroll
        for (int j = 0; j < 8; j++)
#pragma unroll
            for (int g = 0; g < 3; g++)
                red[(((ws*8 + j)*3) + g)*32 + b] = acc[j][g];
        __syncthreads();

        if (tid < 256) {
            int jl = fjl;
            float ar = bR, az = bZ, an = bN;
#pragma unroll
            for (int w2 = 0; w2 < 16; w2++) {
                const float* c = red + ((w2*8 + jl)*3)*32 + b;
                ar += c[0]; az += c[32]; an += c[64];
            }
            int j = j0 + jl;
            const float* xpb = g_xp + (size_t)t*H3_*B_;
            float xr = __ldcg(&xpb[(size_t)(      j)*B_ + b]);
            float xz = __ldcg(&xpb[(size_t)(H_  + j)*B_ + b]);
            float xn = __ldcg(&xpb[(size_t)(2*H_+ j)*B_ + b]);

            float r  = 1.f / (1.f + __expf(-(xr + ar)));
            float z  = 1.f / (1.f + __expf(-(xz + az)));
            float nn = tanhf(xn + r*an);
            float hp = hs[b*HSTRIDE + j];
            float hnew = (1.f - z)*nn + z*hp;

            int valid = (t < len1);
            __stcg(&g_ht[(t+1) & 1][b*H_ + j], valid ? hnew : hp);
            __stcg(&g_out[(size_t)(b*TS_ + t)*H_ + j], valid ? hnew : 0.f);
        }

        __threadfence();
        __syncthreads();
        if (tid == 0) {
            atomicAdd(&g_bar, 1u);
            unsigned goal = (unsigned)gridDim.x * (unsigned)(t+1);
            volatile unsigned* p = &g_bar;
            while (*p < goal) {}
            __threadfence();
        }
        __syncthreads();
    }
}

// ---------------- head log-softmax ----------------------------------------
__global__ void __launch_bounds__(128)
head_lse_kernel()
{
    int n = blockIdx.x;
    if (!g_valid[n]) return;
    int tid = threadIdx.x;
    const float* lg = g_headlog + (size_t)n*(C0_+2);
    __shared__ float sm[4];

    float m = -1e30f;
    for (int i = tid; i < C0_+2; i += 128) m = fmaxf(m, lg[i]);
#pragma unroll
    for (int o = 16; o > 0; o >>= 1) m = fmaxf(m, __shfl_xor_sync(~0u, m, o));
    if ((tid & 31) == 0) sm[tid >> 5] = m;
    __syncthreads();
    m = fmaxf(fmaxf(sm[0], sm[1]), fmaxf(sm[2], sm[3]));

    float s = 0.f;
    for (int i = tid; i < C0_+2; i += 128) s += __expf(lg[i] - m);
#pragma unroll
    for (int o = 16; o > 0; o >>= 1) s += __shfl_xor_sync(~0u, s, o);
    if ((tid & 31) == 0) sm[tid >> 5] = s;
    __syncthreads();
    if (tid == 0) {
        s = sm[0] + sm[1] + sm[2] + sm[3];
        int tgt = g_tgt[n];
        int sel = (tgt < C0_) ? tgt : ((tgt < C1_) ? C0_ : C0_+1);
        g_head_lp[n] = lg[sel] - (m + logf(s));
    }
}

// ---------------- fused tail GEMM + online logsumexp ----------------------
template <int KD, int NSLAB>
__global__ void __launch_bounds__(256)
tail_gemm_kernel(const float* __restrict__ tmat, int cluster, int S)
{
    extern __shared__ float sm[];
    float* As = sm;                          // [KD][72]
    float* Bs = As + KD*72;                  // [64][72]
    float* Rm = Bs + 64*72;                  // [64][16]
    float* Rs = Rm + 64*16;

    int cnt = g_cnt[cluster];
    int r0 = blockIdx.y * 64;
    if (r0 >= cnt) return;
    int tid = threadIdx.x;
    const int*   list = cluster ? g_list2 : g_list1;
    const float* proj = cluster ? g_proj2 : g_proj1;

    for (int idx = tid; idx < 64*KD; idx += 256) {
        int r = idx / KD, k = idx % KD;
        float v = 0.f;
        if (r0 + r < cnt) v = proj[(size_t)list[r0+r]*KD + k];
        As[k*72 + r] = v;
    }
    __syncthreads();

    int tm = tid >> 4, tn = tid & 15;
    float rm[4], rs[4];
#pragma unroll
    for (int i = 0; i < 4; i++) { rm[i] = -1e30f; rs[i] = 0.f; }

    const int SLAB = S / NSLAB;
    const int SCH  = SLAB / 64;
    int sbase = blockIdx.x * SLAB;

    for (int sc = 0; sc < SCH; sc++) {
        int s0 = sbase + sc*64;
        float acc[4][4];
#pragma unroll
        for (int i = 0; i < 4; i++)
#pragma unroll
            for (int jj = 0; jj < 4; jj++) acc[i][jj] = 0.f;

        for (int kc = 0; kc < KD; kc += 64) {
            for (int idx = tid; idx < 1024; idx += 256) {
                int srow = idx >> 4;
                int c4   = idx & 15;
                float4 v = *(const float4*)(tmat + (size_t)(s0+srow)*KD + kc + c4*4);
                Bs[(c4*4+0)*72+srow]=v.x; Bs[(c4*4+1)*72+srow]=v.y;
                Bs[(c4*4+2)*72+srow]=v.z; Bs[(c4*4+3)*72+srow]=v.w;
            }
            __syncthreads();
#pragma unroll 8
            for (int k = 0; k < 64; k++) {
                float4 a = *(const float4*)&As[(kc+k)*72 + tm*4];
                float4 bv = *(const float4*)&Bs[k*72 + tn*4];
                float av[4] = {a.x,a.y,a.z,a.w};
                float bb[4] = {bv.x,bv.y,bv.z,bv.w};
#pragma unroll
                for (int i = 0; i < 4; i++)
#pragma unroll
                    for (int jj = 0; jj < 4; jj++)
                        acc[i][jj] = fmaf(av[i], bb[jj], acc[i][jj]);
            }
            __syncthreads();
        }
#pragma unroll
        for (int i = 0; i < 4; i++) {
            float vm = fmaxf(fmaxf(acc[i][0], acc[i][1]), fmaxf(acc[i][2], acc[i][3]));
            float nm = fmaxf(rm[i], vm);
            rs[i] = rs[i]*__expf(rm[i]-nm)
                  + __expf(acc[i][0]-nm) + __expf(acc[i][1]-nm)
                  + __expf(acc[i][2]-nm) + __expf(acc[i][3]-nm);
            rm[i] = nm;
        }
    }

#pragma unroll
    for (int i = 0; i < 4; i++) {
        Rm[(tm*4+i)*16 + tn] = rm[i];
        Rs[(tm*4+i)*16 + tn] = rs[i];
    }
    __syncthreads();
    if (tid < 64) {
        float m = -1e30f;
#pragma unroll
        for (int c = 0; c < 16; c++) m = fmaxf(m, Rm[tid*16+c]);
        float s = 0.f;
#pragma unroll
        for (int c = 0; c < 16; c++) s += Rs[tid*16+c]*__expf(Rm[tid*16+c]-m);
        if (r0 + tid < cnt) {
            g_pmax[cluster][(size_t)(r0+tid)*32 + blockIdx.x] = m;
            g_psum[cluster][(size_t)(r0+tid)*32 + blockIdx.x] = s;
        }
    }
}

// ---------------- combine tail partials + target logit --------------------
__global__ void combine_kernel(const float* __restrict__ t1,
                               const float* __restrict__ t2)
{
    int cl = blockIdx.y;
    int slot = blockIdx.x*256 + threadIdx.x;
    if (slot >= g_cnt[cl]) return;
    int n = cl ? g_list2[slot] : g_list1[slot];
    int tgt = g_tgt[n];
    int KD = cl ? 64 : 256;
    int NS = 25;
    const float* pr = cl ? (g_proj2 + (size_t)n*64) : (g_proj1 + (size_t)n*256);
    const float* tr = cl ? (t2 + (size_t)(tgt - C1_)*64)
                         : (t1 + (size_t)(tgt - C0_)*256);
    float d = 0.f;
    for (int k = 0; k < KD; k++) d = fmaf(pr[k], tr[k], d);

    const float* pm = &g_pmax[cl][(size_t)slot*32];
    const float* ps = &g_psum[cl][(size_t)slot*32];
    float m = -1e30f;
    for (int s = 0; s < NS; s++) m = fmaxf(m, pm[s]);
    float su = 0.f;
    for (int s = 0; s < NS; s++) su += ps[s]*__expf(pm[s]-m);
    g_head_lp[n] += d - (m + logf(su));
}

// ---------------- final reduction + hT output -----------------------------
__global__ void finalize_kernel(float* __restrict__ out)
{
    __shared__ float sh[256];
    int tid = threadIdx.x;
    const float L2002 = logf(2002.0f);
    float acc = 0.f;
    for (int n = tid; n < NR_; n += 256)
        acc += g_valid[n] ? g_head_lp[n] : -L2002;
    sh[tid] = acc; __syncthreads();
    for (int s = 128; s > 0; s >>= 1) {
        if (tid < s) sh[tid] += sh[tid+s];
        __syncthreads();
    }
    if (tid == 0) out[0] = -sh[0] / (float)NR_;
    const float* hf = g_ht[1];            // [b][k] after 127 steps
    for (int i = tid; i < B_*H_; i += 256)
        out[1 + i] = hf[i];
}

// ---------------- launcher ------------------------------------------------
extern "C" void kernel_launch(void* const* d_in, const int* in_sizes, int n_in,
                              void* d_out, int out_size)
{
    const int*   x      = (const int*)  d_in[0];
    const int*   len    = (const int*)  d_in[1];
    const float* hidden = (const float*)d_in[2];
    const float* emb    = (const float*)d_in[3];
    const float* w_ih   = (const float*)d_in[4];
    const float* w_hh   = (const float*)d_in[5];
    const float* b_ih   = (const float*)d_in[6];
    const float* b_hh   = (const float*)d_in[7];
    const float* head_w = (const float*)d_in[8];
    const float* p1     = (const float*)d_in[9];
    const float* t1     = (const float*)d_in[10];
    const float* p2     = (const float*)d_in[11];
    const float* t2     = (const float*)d_in[12];
    float* out = (float*)d_out;
    (void)in_sizes; (void)n_in; (void)out_size;

    size_t gru_sh = (size_t)(32*HSTRIDE + 16*8*3*32)*sizeof(float);  // ~180.7 KB
    size_t sh_t1  = (size_t)(256*72 + 64*72 + 2*64*16)*sizeof(float);
    size_t sh_t2  = (size_t)( 64*72 + 64*72 + 2*64*16)*sizeof(float);
    cudaFuncSetAttribute(gru_kernel, cudaFuncAttributeMaxDynamicSharedMemorySize, (int)gru_sh);
    cudaFuncSetAttribute(tail_gemm_kernel<256,25>, cudaFuncAttributeMaxDynamicSharedMemorySize, (int)sh_t1);
    cudaFuncSetAttribute(tail_gemm_kernel<64,25>,  cudaFuncAttributeMaxDynamicSharedMemorySize, (int)sh_t2);

    init_kernel<<<1,256>>>(hidden, x, len);
    classify_kernel<<<(NR_+255)/256,256>>>(x, len);

    // xp = emb[x] @ w_ih^T + b_ih    (M=4064, N=3072, K=512)
    gemm_kernel<0><<<dim3(H3_/BN,(NR_+BM-1)/BM),256>>>(
        w_ih, b_ih, x, emb, len, NR_, H3_, E_);

    gru_kernel<<<H_/8,512,gru_sh>>>(w_hh, b_hh, len);

    // fused head + proj1 + proj2 (M=4064, N=2322, K=1024) — tf32 tensor cores
    gemm_tf32_fused<<<dim3((NFUSE+63)/64,(NR_+127)/128),256>>>(
        head_w, p1, p2, len, NR_, NFUSE, H_);

    head_lse_kernel<<<NR_,128>>>();

    tail_gemm_kernel<256,25><<<dim3(25, (NR_+63)/64),256,sh_t1>>>(t1, 0, S1_);
    tail_gemm_kernel<64,25> <<<dim3(25, (NR_+63)/64),256,sh_t2>>>(t2, 1, S2_);

    combine_kernel<<<dim3((NR_+255)/256,2),256>>>(t1, t2);
    finalize_kernel<<<1,256>>>(out);
}

// round 16
// speedup vs baseline: 2.0026x; 1.0936x over previous
#include <cuda_runtime.h>
#include <cuda_bf16.h>
#include <stdint.h>
#include <cstdint>
#include <math.h>

#define V_   50000
#define C0_  2000
#define C1_  10000
#define E_   512
#define H_   1024
#define B_   32
#define T_   128
#define TS_  127
#define NR_  (B_*TS_)            // 4064
#define H3_  (3*H_)              // 3072
#define S1_  8000
#define S2_  40000

#define NFUSE (C0_+2+256+64)     // 2322 fused head+proj1+proj2 columns

// ---------------- device scratch ------------------------------------------
__device__ float g_xp[(size_t)TS_*H3_*B_];        // [t][gate-row][b]
__device__ float g_ht[2][B_*H_];                  // [b][k], double buffer
__device__ float g_out[(size_t)NR_*H_];           // [n][h]
__device__ float g_headlog[(size_t)NR_*(C0_+2)];
__device__ float g_proj1[(size_t)NR_*256];
__device__ float g_proj2[(size_t)NR_*64];
__device__ float g_head_lp[NR_];
__device__ float g_pmax[2][(size_t)NR_*32];
__device__ float g_psum[2][(size_t)NR_*32];
__device__ int   g_tgt[NR_];
__device__ int   g_valid[NR_];
__device__ int   g_list1[NR_];
__device__ int   g_list2[NR_];
__device__ int   g_cnt[2];
__device__ unsigned int g_bar;
__device__ int   g_is64x, g_is64l;

__device__ __forceinline__ int geti(const int* p, int i, int is64) {
    return p[is64 ? 2*i : i];
}

__device__ __forceinline__ uint32_t f2tf(float f) {
    uint32_t u;
    asm("cvt.rna.tf32.f32 %0, %1;" : "=r"(u) : "f"(f));
    return u;
}

__device__ __forceinline__ void mma_tf32(float& d0, float& d1, float& d2, float& d3,
                                         uint32_t a0, uint32_t a1, uint32_t a2, uint32_t a3,
                                         uint32_t b0, uint32_t b1) {
    asm volatile(
        "mma.sync.aligned.m16n8k8.row.col.f32.tf32.tf32.f32 "
        "{%0,%1,%2,%3},{%4,%5,%6,%7},{%8,%9},{%0,%1,%2,%3};"
        : "+f"(d0), "+f"(d1), "+f"(d2), "+f"(d3)
        : "r"(a0), "r"(a1), "r"(a2), "r"(a3), "r"(b0), "r"(b1));
}

// ---------------- init ----------------------------------------------------
__global__ void init_kernel(const float* __restrict__ hidden,
                            const int* __restrict__ x,
                            const int* __restrict__ len) {
    int tid = threadIdx.x;
    if (tid == 0) {
        g_cnt[0] = 0; g_cnt[1] = 0; g_bar = 0u;
        g_is64x = (x[1] == 0 && x[3] == 0 && x[5] == 0) ? 1 : 0;
        g_is64l = (len[1] == 0) ? 1 : 0;
    }
    for (int i = tid; i < B_*H_; i += 256)
        g_ht[0][i] = hidden[i];          // [b][k] both sides
}

// ---------------- classify / compaction -----------------------------------
__global__ void classify_kernel(const int* __restrict__ x,
                                const int* __restrict__ len) {
    int n = blockIdx.x*256 + threadIdx.x;
    if (n >= NR_) return;
    int is64x = g_is64x, is64l = g_is64l;
    int b = n / TS_, t = n % TS_;
    int valid = (t < geti(len, b, is64l) - 1) ? 1 : 0;
    int tgt = geti(x, b*T_ + t + 1, is64x);
    g_valid[n] = valid;
    g_tgt[n]   = tgt;
    if (valid && tgt >= C0_) {
        int cl = (tgt < C1_) ? 0 : 1;
        int slot = atomicAdd(&g_cnt[cl], 1);
        if (cl == 0) g_list1[slot] = n; else g_list2[slot] = n;
    }
}

// ---------------- GEMM (fp32) for xp --------------------------------------
#define BM 128
#define BN 128
#define BK 16

template <int MODE>
__global__ void __launch_bounds__(256)
gemm_kernel(const float* __restrict__ B0, const float* __restrict__ bias,
            const int* __restrict__ x, const float* __restrict__ emb,
            const int* __restrict__ len, int M, int N, int K)
{
    __shared__ __align__(16) float As[BK][BM+4];
    __shared__ __align__(16) float Bs[BK][BN+4];

    int m0 = blockIdx.y * BM;
    int n0 = blockIdx.x * BN;
    int tid = threadIdx.x;
    int is64x = g_is64x;

    const float* asrc[2];
    const float* bsrc[2];
    int arow[2], brow[2];
#pragma unroll
    for (int i = 0; i < 2; i++) {
        int f   = tid*2 + i;
        int row = f >> 2;
        int kk  = (f & 3) * 4;
        arow[i] = row; brow[i] = row;
        int m = m0 + row;
        if (m < M) {
            int t = m >> 5, b = m & 31;
            int tok = geti(x, b*T_ + t, is64x);
            asrc[i] = emb + (size_t)tok*E_ + kk;
        } else asrc[i] = nullptr;
        int n = n0 + row;
        bsrc[i] = (n < N) ? (B0 + (size_t)n*K + kk) : nullptr;
    }

    float acc[8][8];
#pragma unroll
    for (int i = 0; i < 8; i++)
#pragma unroll
        for (int j = 0; j < 8; j++) acc[i][j] = 0.f;

    int tm = tid >> 4;
    int tn = tid & 15;

    for (int kb = 0; kb < K; kb += BK) {
#pragma unroll
        for (int i = 0; i < 2; i++) {
            int f  = tid*2 + i;
            int kk = (f & 3) * 4;
            float4 v = make_float4(0.f,0.f,0.f,0.f);
            if (asrc[i]) v = *(const float4*)(asrc[i] + kb);
            As[kk+0][arow[i]]=v.x; As[kk+1][arow[i]]=v.y;
            As[kk+2][arow[i]]=v.z; As[kk+3][arow[i]]=v.w;
            float4 w = make_float4(0.f,0.f,0.f,0.f);
            if (bsrc[i]) w = *(const float4*)(bsrc[i] + kb);
            Bs[kk+0][brow[i]]=w.x; Bs[kk+1][brow[i]]=w.y;
            Bs[kk+2][brow[i]]=w.z; Bs[kk+3][brow[i]]=w.w;
        }
        __syncthreads();
#pragma unroll
        for (int k = 0; k < BK; k++) {
            float4 a0 = *(const float4*)&As[k][tm*8];
            float4 a1 = *(const float4*)&As[k][tm*8+4];
            float4 b0 = *(const float4*)&Bs[k][tn*8];
            float4 b1 = *(const float4*)&Bs[k][tn*8+4];
            float av[8] = {a0.x,a0.y,a0.z,a0.w,a1.x,a1.y,a1.z,a1.w};
            float bv[8] = {b0.x,b0.y,b0.z,b0.w,b1.x,b1.y,b1.z,b1.w};
#pragma unroll
            for (int i = 0; i < 8; i++)
#pragma unroll
                for (int j = 0; j < 8; j++)
                    acc[i][j] = fmaf(av[i], bv[j], acc[i][j]);
        }
        __syncthreads();
    }

#pragma unroll
    for (int i = 0; i < 8; i++) {
        int m = m0 + tm*8 + i;
        if (m >= M) continue;
        int t = m >> 5, b = m & 31;
#pragma unroll
        for (int j = 0; j < 8; j++) {
            int n = n0 + tn*8 + j;
            if (n >= N) continue;
            g_xp[((size_t)t*H3_ + n)*B_ + b] = acc[i][j] + bias[n];
        }
    }
}

// ---------------- fused head+proj GEMM in tf32 mma ------------------------
#define ASTR 136
#define BSTR 72

__device__ __forceinline__ void fused_store(int m, int n, float v) {
    if (n < C0_+2)          g_headlog[(size_t)m*(C0_+2) + n] = v;
    else if (n < C0_+2+256) g_proj1[(size_t)m*256 + (n-(C0_+2))] = v;
    else                    g_proj2[(size_t)m*64  + (n-(C0_+2+256))] = v;
}

__global__ void __launch_bounds__(256)
gemm_tf32_fused(const float* __restrict__ B0, const float* __restrict__ B1,
                const float* __restrict__ B2, const int* __restrict__ len,
                int M, int N, int K)
{
    __shared__ uint32_t As[BK][ASTR];
    __shared__ uint32_t Bs[BK][BSTR];

    int m0 = blockIdx.y * 128;
    int n0 = blockIdx.x * 64;
    int tid = threadIdx.x;
    int is64l = g_is64l;

    {
        int pred = 0;
        if (tid < 128) {
            int m = m0 + tid;
            if (m < M) {
                int b = m / TS_, t = m % TS_;
                pred = (t < geti(len, b, is64l) - 1);
            }
        }
        if (!__syncthreads_or(pred)) return;
    }

    const float* asrc[2];
    int arow[2];
#pragma unroll
    for (int i = 0; i < 2; i++) {
        int f   = tid*2 + i;
        int row = f >> 2;
        int kk  = (f & 3) * 4;
        arow[i] = row;
        int m = m0 + row;
        asrc[i] = (m < M) ? (g_out + (size_t)m*K + kk) : nullptr;
    }
    const float* bsrc;
    int brow = tid >> 2;
    {
        int kk = (tid & 3) * 4;
        int n = n0 + brow;
        if (n < N) {
            if (n < C0_+2)            bsrc = B0 + (size_t)n*K + kk;
            else if (n < C0_+2+256)   bsrc = B1 + (size_t)(n-(C0_+2))*K + kk;
            else                      bsrc = B2 + (size_t)(n-(C0_+2+256))*K + kk;
        } else bsrc = nullptr;
    }

    int lane = tid & 31;
    int warp = tid >> 5;
    int wm = warp & 3;
    int wn = warp >> 2;
    int gr = lane >> 2;
    int gc = lane & 3;

    float acc[2][4][4];
#pragma unroll
    for (int mt = 0; mt < 2; mt++)
#pragma unroll
        for (int nt = 0; nt < 4; nt++)
#pragma unroll
            for (int e = 0; e < 4; e++) acc[mt][nt][e] = 0.f;

    for (int kb = 0; kb < K; kb += BK) {
#pragma unroll
        for (int i = 0; i < 2; i++) {
            int f  = tid*2 + i;
            int kk = (f & 3) * 4;
            float4 v = make_float4(0.f,0.f,0.f,0.f);
            if (asrc[i]) v = *(const float4*)(asrc[i] + kb);
            As[kk+0][arow[i]] = f2tf(v.x);
            As[kk+1][arow[i]] = f2tf(v.y);
            As[kk+2][arow[i]] = f2tf(v.z);
            As[kk+3][arow[i]] = f2tf(v.w);
        }
        {
            int kk = (tid & 3) * 4;
            float4 v = make_float4(0.f,0.f,0.f,0.f);
            if (bsrc) v = *(const float4*)(bsrc + kb);
            Bs[kk+0][brow] = f2tf(v.x);
            Bs[kk+1][brow] = f2tf(v.y);
            Bs[kk+2][brow] = f2tf(v.z);
            Bs[kk+3][brow] = f2tf(v.w);
        }
        __syncthreads();

#pragma unroll
        for (int ks = 0; ks < BK; ks += 8) {
            uint32_t a[2][4], bfr[4][2];
#pragma unroll
            for (int mt = 0; mt < 2; mt++) {
                int mr = wm*32 + mt*16 + gr;
                a[mt][0] = As[ks+gc  ][mr];
                a[mt][1] = As[ks+gc  ][mr+8];
                a[mt][2] = As[ks+gc+4][mr];
                a[mt][3] = As[ks+gc+4][mr+8];
            }
#pragma unroll
            for (int nt = 0; nt < 4; nt++) {
                int nc = wn*32 + nt*8 + gr;
                bfr[nt][0] = Bs[ks+gc  ][nc];
                bfr[nt][1] = Bs[ks+gc+4][nc];
            }
#pragma unroll
            for (int mt = 0; mt < 2; mt++)
#pragma unroll
                for (int nt = 0; nt < 4; nt++)
                    mma_tf32(acc[mt][nt][0], acc[mt][nt][1], acc[mt][nt][2], acc[mt][nt][3],
                             a[mt][0], a[mt][1], a[mt][2], a[mt][3],
                             bfr[nt][0], bfr[nt][1]);
        }
        __syncthreads();
    }

#pragma unroll
    for (int mt = 0; mt < 2; mt++) {
        int r0 = m0 + wm*32 + mt*16 + gr;
        int r1 = r0 + 8;
#pragma unroll
        for (int nt = 0; nt < 4; nt++) {
            int c0 = n0 + wn*32 + nt*8 + gc*2;
            if (r0 < M) {
                if (c0   < N) fused_store(r0, c0,   acc[mt][nt][0]);
                if (c0+1 < N) fused_store(r0, c0+1, acc[mt][nt][1]);
            }
            if (r1 < M) {
                if (c0   < N) fused_store(r1, c0,   acc[mt][nt][2]);
                if (c0+1 < N) fused_store(r1, c0+1, acc[mt][nt][3]);
            }
        }
    }
}

// ---------------- persistent GRU v3 ---------------------------------------
#define HSTRIDE 1028
#define GRU_RED (32*HSTRIDE)

__global__ void __launch_bounds__(512)
gru_kernel(const float* __restrict__ whh, const float* __restrict__ bhh,
           const int* __restrict__ len)
{
    extern __shared__ float sm[];
    float* hs  = sm;                     // [32][HSTRIDE]
    float* red = sm + GRU_RED;           // [16][8][3][32]

    int tid = threadIdx.x;
    int ws  = tid >> 5;
    int b   = tid & 31;
    int j0  = blockIdx.x*8;
    int k0  = ws*64;

    const float* wr = whh + (size_t)(          j0)*H_ + k0;
    const float* wz = whh + (size_t)(H_   +    j0)*H_ + k0;
    const float* wn = whh + (size_t)(2*H_ +    j0)*H_ + k0;

    int fjl  = tid >> 5;
    float bR = bhh[j0 + (fjl & 7)];
    float bZ = bhh[H_   + j0 + (fjl & 7)];
    float bN = bhh[2*H_ + j0 + (fjl & 7)];
    int len1 = geti(len, b, g_is64l) - 1;

    for (int t = 0; t < TS_; t++) {
        const float4* src = (const float4*)g_ht[t & 1];
        for (int i = tid; i < B_*H_/4; i += 512) {
            float4 v = __ldcg(src + i);
            int bb = i >> 8, kq = i & 255;
            *(float4*)&hs[bb*HSTRIDE + kq*4] = v;
        }
        __syncthreads();

        float acc[8][3];
#pragma unroll
        for (int j = 0; j < 8; j++)
#pragma unroll
            for (int g = 0; g < 3; g++) acc[j][g] = 0.f;

        const float* hb = hs + b*HSTRIDE + k0;
#pragma unroll 2
        for (int kk = 0; kk < 64; kk += 8) {
            float4 h0 = *(const float4*)&hb[kk];
            float4 h1 = *(const float4*)&hb[kk+4];
#pragma unroll
            for (int j = 0; j < 8; j++) {
                float4 r0 = __ldg((const float4*)(wr + (size_t)j*H_ + kk));
                float4 r1 = __ldg((const float4*)(wr + (size_t)j*H_ + kk + 4));
                float4 z0 = __ldg((const float4*)(wz + (size_t)j*H_ + kk));
                float4 z1 = __ldg((const float4*)(wz + (size_t)j*H_ + kk + 4));
                float4 n0 = __ldg((const float4*)(wn + (size_t)j*H_ + kk));
                float4 n1 = __ldg((const float4*)(wn + (size_t)j*H_ + kk + 4));
                acc[j][0] = fmaf(r0.x,h0.x, fmaf(r0.y,h0.y, fmaf(r0.z,h0.z, fmaf(r0.w,h0.w, acc[j][0]))));
                acc[j][0] = fmaf(r1.x,h1.x, fmaf(r1.y,h1.y, fmaf(r1.z,h1.z, fmaf(r1.w,h1.w, acc[j][0]))));
                acc[j][1] = fmaf(z0.x,h0.x, fmaf(z0.y,h0.y, fmaf(z0.z,h0.z, fmaf(z0.w,h0.w, acc[j][1]))));
                acc[j][1] = fmaf(z1.x,h1.x, fmaf(z1.y,h1.y, fmaf(z1.z,h1.z, fmaf(z1.w,h1.w, acc[j][1]))));
                acc[j][2] = fmaf(n0.x,h0.x, fmaf(n0.y,h0.y, fmaf(n0.z,h0.z, fmaf(n0.w,h0.w, acc[j][2]))));
                acc[j][2] = fmaf(n1.x,h1.x, fmaf(n1.y,h1.y, fmaf(n1.z,h1.z, fmaf(n1.w,h1.w, acc[j][2]))));
            }
        }

#pragma unroll
        for (int j = 0; j < 8; j++)
#pragma unroll
            for (int g = 0; g < 3; g++)
                red[(((ws*8 + j)*3) + g)*32 + b] = acc[j][g];
        __syncthreads();

        if (tid < 256) {
            int jl = fjl;
            float ar = bR, az = bZ, an = bN;
#pragma unroll
            for (int w2 = 0; w2 < 16; w2++) {
                const float* c = red + ((w2*8 + jl)*3)*32 + b;
                ar += c[0]; az += c[32]; an += c[64];
            }
            int j = j0 + jl;
            const float* xpb = g_xp + (size_t)t*H3_*B_;
            float xr = __ldcg(&xpb[(size_t)(      j)*B_ + b]);
            float xz = __ldcg(&xpb[(size_t)(H_  + j)*B_ + b]);
            float xn = __ldcg(&xpb[(size_t)(2*H_+ j)*B_ + b]);

            float r  = 1.f / (1.f + __expf(-(xr + ar)));
            float z  = 1.f / (1.f + __expf(-(xz + az)));
            float nn = tanhf(xn + r*an);
            float hp = hs[b*HSTRIDE + j];
            float hnew = (1.f - z)*nn + z*hp;

            int valid = (t < len1);
            __stcg(&g_ht[(t+1) & 1][b*H_ + j], valid ? hnew : hp);
            __stcg(&g_out[(size_t)(b*TS_ + t)*H_ + j], valid ? hnew : 0.f);
        }

        __threadfence();
        __syncthreads();
        if (tid == 0) {
            atomicAdd(&g_bar, 1u);
            unsigned goal = (unsigned)gridDim.x * (unsigned)(t+1);
            volatile unsigned* p = &g_bar;
            while (*p < goal) {}
            __threadfence();
        }
        __syncthreads();
    }
}

// ---------------- head log-softmax ----------------------------------------
__global__ void __launch_bounds__(128)
head_lse_kernel()
{
    int n = blockIdx.x;
    if (!g_valid[n]) return;
    int tid = threadIdx.x;
    const float* lg = g_headlog + (size_t)n*(C0_+2);
    __shared__ float sm[4];

    float m = -1e30f;
    for (int i = tid; i < C0_+2; i += 128) m = fmaxf(m, lg[i]);
#pragma unroll
    for (int o = 16; o > 0; o >>= 1) m = fmaxf(m, __shfl_xor_sync(~0u, m, o));
    if ((tid & 31) == 0) sm[tid >> 5] = m;
    __syncthreads();
    m = fmaxf(fmaxf(sm[0], sm[1]), fmaxf(sm[2], sm[3]));

    float s = 0.f;
    for (int i = tid; i < C0_+2; i += 128) s += __expf(lg[i] - m);
#pragma unroll
    for (int o = 16; o > 0; o >>= 1) s += __shfl_xor_sync(~0u, s, o);
    if ((tid & 31) == 0) sm[tid >> 5] = s;
    __syncthreads();
    if (tid == 0) {
        s = sm[0] + sm[1] + sm[2] + sm[3];
        int tgt = g_tgt[n];
        int sel = (tgt < C0_) ? tgt : ((tgt < C1_) ? C0_ : C0_+1);
        g_head_lp[n] = lg[sel] - (m + logf(s));
    }
}

// ---------------- tail GEMM in tf32 mma + online logsumexp ----------------
// 64 compacted rows x one s-slab. A = proj rows (tf32 in smem), B = tmat.
// 8 warps: wm 0..3 (16 rows), wn 0..1 (32 of each 64-col chunk).
#define TAST 72

template <int KD, int NSLAB>
__global__ void __launch_bounds__(256)
tail_tf32_kernel(const float* __restrict__ tmat, int cluster, int S)
{
    extern __shared__ float smf[];
    uint32_t* As = (uint32_t*)smf;               // [KD][72]
    uint32_t* Bsm = As + KD*TAST;                // [64][72]
    float* Rm = (float*)(Bsm + 64*TAST);         // [64][2]
    float* Rs = Rm + 128;                        // [64][2]

    int cnt = g_cnt[cluster];
    int r0 = blockIdx.y * 64;
    if (r0 >= cnt) return;
    int tid = threadIdx.x;
    const int*   list = cluster ? g_list2 : g_list1;
    const float* proj = cluster ? g_proj2 : g_proj1;

    // stage A: As[k][r] = tf32(proj[list[r0+r]][k])
    for (int idx = tid; idx < 64*(KD/4); idx += 256) {
        int r  = idx / (KD/4);
        int k4 = idx % (KD/4);
        float4 v = make_float4(0.f,0.f,0.f,0.f);
        if (r0 + r < cnt) v = *(const float4*)(proj + (size_t)list[r0+r]*KD + k4*4);
        As[(k4*4+0)*TAST + r] = f2tf(v.x);
        As[(k4*4+1)*TAST + r] = f2tf(v.y);
        As[(k4*4+2)*TAST + r] = f2tf(v.z);
        As[(k4*4+3)*TAST + r] = f2tf(v.w);
    }
    __syncthreads();

    int lane = tid & 31, warp = tid >> 5;
    int wm = warp & 3, wn = warp >> 2;
    int gr = lane >> 2, gc = lane & 3;
    int mr = wm*16 + gr;

    float rm0 = -1e30f, rs0 = 0.f, rm1 = -1e30f, rs1 = 0.f;

    const int SLAB = S / NSLAB;
    const int SCH  = SLAB / 64;
    int sbase = blockIdx.x * SLAB;

    int bsrow = tid >> 2;               // 0..63 (s row within chunk)
    int bc4   = tid & 3;                // 4 float4 per row

    for (int sc = 0; sc < SCH; sc++) {
        int s0 = sbase + sc*64;
        float acc[4][4];
#pragma unroll
        for (int nt = 0; nt < 4; nt++)
#pragma unroll
            for (int e = 0; e < 4; e++) acc[nt][e] = 0.f;

        for (int kc = 0; kc < KD; kc += 64) {
            // stage B panel: Bsm[kk][srow] for kk in [0,64), srow in [0,64)
#pragma unroll
            for (int u = 0; u < 4; u++) {
                int k4 = bc4*4 + u;     // 0..15
                float4 v = *(const float4*)(tmat + (size_t)(s0+bsrow)*KD + kc + k4*4);
                Bsm[(k4*4+0)*TAST + bsrow] = f2tf(v.x);
                Bsm[(k4*4+1)*TAST + bsrow] = f2tf(v.y);
                Bsm[(k4*4+2)*TAST + bsrow] = f2tf(v.z);
                Bsm[(k4*4+3)*TAST + bsrow] = f2tf(v.w);
            }
            __syncthreads();
#pragma unroll
            for (int ks = 0; ks < 64; ks += 8) {
                uint32_t a0 = As[(kc+ks+gc  )*TAST + mr];
                uint32_t a1 = As[(kc+ks+gc  )*TAST + mr + 8];
                uint32_t a2 = As[(kc+ks+gc+4)*TAST + mr];
                uint32_t a3 = As[(kc+ks+gc+4)*TAST + mr + 8];
#pragma unroll
                for (int nt = 0; nt < 4; nt++) {
                    int nc = wn*32 + nt*8 + gr;
                    uint32_t b0 = Bsm[(ks+gc  )*TAST + nc];
                    uint32_t b1 = Bsm[(ks+gc+4)*TAST + nc];
                    mma_tf32(acc[nt][0], acc[nt][1], acc[nt][2], acc[nt][3],
                             a0, a1, a2, a3, b0, b1);
                }
            }
            __syncthreads();
        }

        // chunk LSE: row mr (d0,d1) and row mr+8 (d2,d3), 4-lane groups share a row
        float vm0 = -1e30f, vm1 = -1e30f;
#pragma unroll
        for (int nt = 0; nt < 4; nt++) {
            vm0 = fmaxf(vm0, fmaxf(acc[nt][0], acc[nt][1]));
            vm1 = fmaxf(vm1, fmaxf(acc[nt][2], acc[nt][3]));
        }
        vm0 = fmaxf(vm0, __shfl_xor_sync(~0u, vm0, 1));
        vm0 = fmaxf(vm0, __shfl_xor_sync(~0u, vm0, 2));
        vm1 = fmaxf(vm1, __shfl_xor_sync(~0u, vm1, 1));
        vm1 = fmaxf(vm1, __shfl_xor_sync(~0u, vm1, 2));
        float vs0 = 0.f, vs1 = 0.f;
#pragma unroll
        for (int nt = 0; nt < 4; nt++) {
            vs0 += __expf(acc[nt][0]-vm0) + __expf(acc[nt][1]-vm0);
            vs1 += __expf(acc[nt][2]-vm1) + __expf(acc[nt][3]-vm1);
        }
        vs0 += __shfl_xor_sync(~0u, vs0, 1);
        vs0 += __shfl_xor_sync(~0u, vs0, 2);
        vs1 += __shfl_xor_sync(~0u, vs1, 1);
        vs1 += __shfl_xor_sync(~0u, vs1, 2);

        float nm0 = fmaxf(rm0, vm0);
        rs0 = rs0*__expf(rm0-nm0) + vs0*__expf(vm0-nm0);
        rm0 = nm0;
        float nm1 = fmaxf(rm1, vm1);
        rs1 = rs1*__expf(rm1-nm1) + vs1*__expf(vm1-nm1);
        rm1 = nm1;
    }

    // combine the two wn halves via smem
    if (gc == 0) {
        Rm[mr*2 + wn] = rm0;       Rs[mr*2 + wn] = rs0;
        Rm[(mr+8)*2 + wn] = rm1;   Rs[(mr+8)*2 + wn] = rs1;
    }
    __syncthreads();
    if (tid < 64 && r0 + tid < cnt) {
        float m0 = Rm[tid*2], m1 = Rm[tid*2+1];
        float m = fmaxf(m0, m1);
        float s = Rs[tid*2]*__expf(m0-m) + Rs[tid*2+1]*__expf(m1-m);
        g_pmax[cluster][(size_t)(r0+tid)*32 + blockIdx.x] = m;
        g_psum[cluster][(size_t)(r0+tid)*32 + blockIdx.x] = s;
    }
}

// ---------------- combine tail partials + target logit --------------------
__global__ void combine_kernel(const float* __restrict__ t1,
                               const float* __restrict__ t2)
{
    int cl = blockIdx.y;
    int slot = blockIdx.x*256 + threadIdx.x;
    if (slot >= g_cnt[cl]) return;
    int n = cl ? g_list2[slot] : g_list1[slot];
    int tgt = g_tgt[n];
    int KD = cl ? 64 : 256;
    int NS = 25;
    const float* pr = cl ? (g_proj2 + (size_t)n*64) : (g_proj1 + (size_t)n*256);
    const float* tr = cl ? (t2 + (size_t)(tgt - C1_)*64)
                         : (t1 + (size_t)(tgt - C0_)*256);
    float d = 0.f;
    for (int k = 0; k < KD; k++) d = fmaf(pr[k], tr[k], d);

    const float* pm = &g_pmax[cl][(size_t)slot*32];
    const float* ps = &g_psum[cl][(size_t)slot*32];
    float m = -1e30f;
    for (int s = 0; s < NS; s++) m = fmaxf(m, pm[s]);
    float su = 0.f;
    for (int s = 0; s < NS; s++) su += ps[s]*__expf(pm[s]-m);
    g_head_lp[n] += d - (m + logf(su));
}

// ---------------- final reduction + hT output -----------------------------
__global__ void finalize_kernel(float* __restrict__ out)
{
    __shared__ float sh[256];
    int tid = threadIdx.x;
    const float L2002 = logf(2002.0f);
    float acc = 0.f;
    for (int n = tid; n < NR_; n += 256)
        acc += g_valid[n] ? g_head_lp[n] : -L2002;
    sh[tid] = acc; __syncthreads();
    for (int s = 128; s > 0; s >>= 1) {
        if (tid < s) sh[tid] += sh[tid+s];
        __syncthreads();
    }
    if (tid == 0) out[0] = -sh[0] / (float)NR_;
    const float* hf = g_ht[1];            // [b][k] after 127 steps
    for (int i = tid; i < B_*H_; i += 256)
        out[1 + i] = hf[i];
}

// ---------------- launcher ------------------------------------------------
extern "C" void kernel_launch(void* const* d_in, const int* in_sizes, int n_in,
                              void* d_out, int out_size)
{
    const int*   x      = (const int*)  d_in[0];
    const int*   len    = (const int*)  d_in[1];
    const float* hidden = (const float*)d_in[2];
    const float* emb    = (const float*)d_in[3];
    const float* w_ih   = (const float*)d_in[4];
    const float* w_hh   = (const float*)d_in[5];
    const float* b_ih   = (const float*)d_in[6];
    const float* b_hh   = (const float*)d_in[7];
    const float* head_w = (const float*)d_in[8];
    const float* p1     = (const float*)d_in[9];
    const float* t1     = (const float*)d_in[10];
    const float* p2     = (const float*)d_in[11];
    const float* t2     = (const float*)d_in[12];
    float* out = (float*)d_out;
    (void)in_sizes; (void)n_in; (void)out_size;

    size_t gru_sh = (size_t)(32*HSTRIDE + 16*8*3*32)*sizeof(float);  // ~180.7 KB
    size_t sh_t1  = (size_t)(256*TAST + 64*TAST + 256)*sizeof(uint32_t); // ~93 KB
    size_t sh_t2  = (size_t)( 64*TAST + 64*TAST + 256)*sizeof(uint32_t); // ~38 KB
    cudaFuncSetAttribute(gru_kernel, cudaFuncAttributeMaxDynamicSharedMemorySize, (int)gru_sh);
    cudaFuncSetAttribute(tail_tf32_kernel<256,25>, cudaFuncAttributeMaxDynamicSharedMemorySize, (int)sh_t1);
    cudaFuncSetAttribute(tail_tf32_kernel<64,25>,  cudaFuncAttributeMaxDynamicSharedMemorySize, (int)sh_t2);

    init_kernel<<<1,256>>>(hidden, x, len);
    classify_kernel<<<(NR_+255)/256,256>>>(x, len);

    // xp = emb[x] @ w_ih^T + b_ih    (M=4064, N=3072, K=512)
    gemm_kernel<0><<<dim3(H3_/BN,(NR_+BM-1)/BM),256>>>(
        w_ih, b_ih, x, emb, len, NR_, H3_, E_);

    gru_kernel<<<H_/8,512,gru_sh>>>(w_hh, b_hh, len);

    // fused head + proj1 + proj2 (M=4064, N=2322, K=1024) — tf32 tensor cores
    gemm_tf32_fused<<<dim3((NFUSE+63)/64,(NR_+127)/128),256>>>(
        head_w, p1, p2, len, NR_, NFUSE, H_);

    head_lse_kernel<<<NR_,128>>>();

    tail_tf32_kernel<256,25><<<dim3(25, (NR_+63)/64),256,sh_t1>>>(t1, 0, S1_);
    tail_tf32_kernel<64,25> <<<dim3(25, (NR_+63)/64),256,sh_t2>>>(t2, 1, S2_);

    combine_kernel<<<dim3((NR_+255)/256,2),256>>>(t1, t2);
    finalize_kernel<<<1,256>>>(out);
}

// round 17
// speedup vs baseline: 2.2865x; 1.1417x over previous
#include <cuda_runtime.h>
#include <cuda_bf16.h>
#include <stdint.h>
#include <cstdint>
#include <math.h>

#define V_   50000
#define C0_  2000
#define C1_  10000
#define E_   512
#define H_   1024
#define B_   32
#define T_   128
#define TS_  127
#define NR_  (B_*TS_)            // 4064
#define H3_  (3*H_)              // 3072
#define S1_  8000
#define S2_  40000

#define NFUSE (C0_+2+256+64)     // 2322 fused head+proj1+proj2 columns

// ---------------- device scratch ------------------------------------------
__device__ float g_xp[(size_t)TS_*H3_*B_];        // [t][gate-row][b]
__device__ float g_ht[2][H_*B_];                  // [k][b], double buffer
__device__ float g_out[(size_t)NR_*H_];           // [n][h]
__device__ float g_headlog[(size_t)NR_*(C0_+2)];
__device__ float g_proj1[(size_t)NR_*256];
__device__ float g_proj2[(size_t)NR_*64];
__device__ float g_head_lp[NR_];
__device__ float g_pmax[2][(size_t)NR_*32];
__device__ float g_psum[2][(size_t)NR_*32];
__device__ int   g_tgt[NR_];
__device__ int   g_valid[NR_];
__device__ int   g_list1[NR_];
__device__ int   g_list2[NR_];
__device__ int   g_cnt[2];
__device__ unsigned int g_bar;
__device__ int   g_is64x, g_is64l;

__device__ __forceinline__ int geti(const int* p, int i, int is64) {
    return p[is64 ? 2*i : i];
}

__device__ __forceinline__ uint32_t f2tf(float f) {
    uint32_t u;
    asm("cvt.rna.tf32.f32 %0, %1;" : "=r"(u) : "f"(f));
    return u;
}

__device__ __forceinline__ void mma_tf32(float& d0, float& d1, float& d2, float& d3,
                                         uint32_t a0, uint32_t a1, uint32_t a2, uint32_t a3,
                                         uint32_t b0, uint32_t b1) {
    asm volatile(
        "mma.sync.aligned.m16n8k8.row.col.f32.tf32.tf32.f32 "
        "{%0,%1,%2,%3},{%4,%5,%6,%7},{%8,%9},{%0,%1,%2,%3};"
        : "+f"(d0), "+f"(d1), "+f"(d2), "+f"(d3)
        : "r"(a0), "r"(a1), "r"(a2), "r"(a3), "r"(b0), "r"(b1));
}

// ---------------- init ----------------------------------------------------
__global__ void init_kernel(const float* __restrict__ hidden,
                            const int* __restrict__ x,
                            const int* __restrict__ len) {
    int tid = threadIdx.x;
    if (tid == 0) {
        g_cnt[0] = 0; g_cnt[1] = 0; g_bar = 0u;
        g_is64x = (x[1] == 0 && x[3] == 0 && x[5] == 0) ? 1 : 0;
        g_is64l = (len[1] == 0) ? 1 : 0;
    }
    for (int i = tid; i < B_*H_; i += 256) {
        int k = i >> 5, b = i & 31;
        g_ht[0][i] = hidden[b*H_ + k];   // [k][b]
    }
}

// ---------------- classify / compaction -----------------------------------
__global__ void classify_kernel(const int* __restrict__ x,
                                const int* __restrict__ len) {
    int n = blockIdx.x*256 + threadIdx.x;
    if (n >= NR_) return;
    int is64x = g_is64x, is64l = g_is64l;
    int b = n / TS_, t = n % TS_;
    int valid = (t < geti(len, b, is64l) - 1) ? 1 : 0;
    int tgt = geti(x, b*T_ + t + 1, is64x);
    g_valid[n] = valid;
    g_tgt[n]   = tgt;
    if (valid && tgt >= C0_) {
        int cl = (tgt < C1_) ? 0 : 1;
        int slot = atomicAdd(&g_cnt[cl], 1);
        if (cl == 0) g_list1[slot] = n; else g_list2[slot] = n;
    }
}

// ---------------- GEMM (fp32) for xp --------------------------------------
#define BM 128
#define BN 128
#define BK 16

template <int MODE>
__global__ void __launch_bounds__(256)
gemm_kernel(const float* __restrict__ B0, const float* __restrict__ bias,
            const int* __restrict__ x, const float* __restrict__ emb,
            const int* __restrict__ len, int M, int N, int K)
{
    __shared__ __align__(16) float As[BK][BM+4];
    __shared__ __align__(16) float Bs[BK][BN+4];

    int m0 = blockIdx.y * BM;
    int n0 = blockIdx.x * BN;
    int tid = threadIdx.x;
    int is64x = g_is64x;

    const float* asrc[2];
    const float* bsrc[2];
    int arow[2], brow[2];
#pragma unroll
    for (int i = 0; i < 2; i++) {
        int f   = tid*2 + i;
        int row = f >> 2;
        int kk  = (f & 3) * 4;
        arow[i] = row; brow[i] = row;
        int m = m0 + row;
        if (m < M) {
            int t = m >> 5, b = m & 31;
            int tok = geti(x, b*T_ + t, is64x);
            asrc[i] = emb + (size_t)tok*E_ + kk;
        } else asrc[i] = nullptr;
        int n = n0 + row;
        bsrc[i] = (n < N) ? (B0 + (size_t)n*K + kk) : nullptr;
    }

    float acc[8][8];
#pragma unroll
    for (int i = 0; i < 8; i++)
#pragma unroll
        for (int j = 0; j < 8; j++) acc[i][j] = 0.f;

    int tm = tid >> 4;
    int tn = tid & 15;

    for (int kb = 0; kb < K; kb += BK) {
#pragma unroll
        for (int i = 0; i < 2; i++) {
            int f  = tid*2 + i;
            int kk = (f & 3) * 4;
            float4 v = make_float4(0.f,0.f,0.f,0.f);
            if (asrc[i]) v = *(const float4*)(asrc[i] + kb);
            As[kk+0][arow[i]]=v.x; As[kk+1][arow[i]]=v.y;
            As[kk+2][arow[i]]=v.z; As[kk+3][arow[i]]=v.w;
            float4 w = make_float4(0.f,0.f,0.f,0.f);
            if (bsrc[i]) w = *(const float4*)(bsrc[i] + kb);
            Bs[kk+0][brow[i]]=w.x; Bs[kk+1][brow[i]]=w.y;
            Bs[kk+2][brow[i]]=w.z; Bs[kk+3][brow[i]]=w.w;
        }
        __syncthreads();
#pragma unroll
        for (int k = 0; k < BK; k++) {
            float4 a0 = *(const float4*)&As[k][tm*8];
            float4 a1 = *(const float4*)&As[k][tm*8+4];
            float4 b0 = *(const float4*)&Bs[k][tn*8];
            float4 b1 = *(const float4*)&Bs[k][tn*8+4];
            float av[8] = {a0.x,a0.y,a0.z,a0.w,a1.x,a1.y,a1.z,a1.w};
            float bv[8] = {b0.x,b0.y,b0.z,b0.w,b1.x,b1.y,b1.z,b1.w};
#pragma unroll
            for (int i = 0; i < 8; i++)
#pragma unroll
                for (int j = 0; j < 8; j++)
                    acc[i][j] = fmaf(av[i], bv[j], acc[i][j]);
        }
        __syncthreads();
    }

#pragma unroll
    for (int i = 0; i < 8; i++) {
        int m = m0 + tm*8 + i;
        if (m >= M) continue;
        int t = m >> 5, b = m & 31;
#pragma unroll
        for (int j = 0; j < 8; j++) {
            int n = n0 + tn*8 + j;
            if (n >= N) continue;
            g_xp[((size_t)t*H3_ + n)*B_ + b] = acc[i][j] + bias[n];
        }
    }
}

// ---------------- fused head+proj GEMM in tf32 mma ------------------------
#define ASTR 136
#define BSTR 72

__device__ __forceinline__ void fused_store(int m, int n, float v) {
    if (n < C0_+2)          g_headlog[(size_t)m*(C0_+2) + n] = v;
    else if (n < C0_+2+256) g_proj1[(size_t)m*256 + (n-(C0_+2))] = v;
    else                    g_proj2[(size_t)m*64  + (n-(C0_+2+256))] = v;
}

__global__ void __launch_bounds__(256)
gemm_tf32_fused(const float* __restrict__ B0, const float* __restrict__ B1,
                const float* __restrict__ B2, const int* __restrict__ len,
                int M, int N, int K)
{
    __shared__ uint32_t As[BK][ASTR];
    __shared__ uint32_t Bs[BK][BSTR];

    int m0 = blockIdx.y * 128;
    int n0 = blockIdx.x * 64;
    int tid = threadIdx.x;
    int is64l = g_is64l;

    {
        int pred = 0;
        if (tid < 128) {
            int m = m0 + tid;
            if (m < M) {
                int b = m / TS_, t = m % TS_;
                pred = (t < geti(len, b, is64l) - 1);
            }
        }
        if (!__syncthreads_or(pred)) return;
    }

    const float* asrc[2];
    int arow[2];
#pragma unroll
    for (int i = 0; i < 2; i++) {
        int f   = tid*2 + i;
        int row = f >> 2;
        int kk  = (f & 3) * 4;
        arow[i] = row;
        int m = m0 + row;
        asrc[i] = (m < M) ? (g_out + (size_t)m*K + kk) : nullptr;
    }
    const float* bsrc;
    int brow = tid >> 2;
    {
        int kk = (tid & 3) * 4;
        int n = n0 + brow;
        if (n < N) {
            if (n < C0_+2)            bsrc = B0 + (size_t)n*K + kk;
            else if (n < C0_+2+256)   bsrc = B1 + (size_t)(n-(C0_+2))*K + kk;
            else                      bsrc = B2 + (size_t)(n-(C0_+2+256))*K + kk;
        } else bsrc = nullptr;
    }

    int lane = tid & 31;
    int warp = tid >> 5;
    int wm = warp & 3;
    int wn = warp >> 2;
    int gr = lane >> 2;
    int gc = lane & 3;

    float acc[2][4][4];
#pragma unroll
    for (int mt = 0; mt < 2; mt++)
#pragma unroll
        for (int nt = 0; nt < 4; nt++)
#pragma unroll
            for (int e = 0; e < 4; e++) acc[mt][nt][e] = 0.f;

    for (int kb = 0; kb < K; kb += BK) {
#pragma unroll
        for (int i = 0; i < 2; i++) {
            int f  = tid*2 + i;
            int kk = (f & 3) * 4;
            float4 v = make_float4(0.f,0.f,0.f,0.f);
            if (asrc[i]) v = *(const float4*)(asrc[i] + kb);
            As[kk+0][arow[i]] = f2tf(v.x);
            As[kk+1][arow[i]] = f2tf(v.y);
            As[kk+2][arow[i]] = f2tf(v.z);
            As[kk+3][arow[i]] = f2tf(v.w);
        }
        {
            int kk = (tid & 3) * 4;
            float4 v = make_float4(0.f,0.f,0.f,0.f);
            if (bsrc) v = *(const float4*)(bsrc + kb);
            Bs[kk+0][brow] = f2tf(v.x);
            Bs[kk+1][brow] = f2tf(v.y);
            Bs[kk+2][brow] = f2tf(v.z);
            Bs[kk+3][brow] = f2tf(v.w);
        }
        __syncthreads();

#pragma unroll
        for (int ks = 0; ks < BK; ks += 8) {
            uint32_t a[2][4], bfr[4][2];
#pragma unroll
            for (int mt = 0; mt < 2; mt++) {
                int mr = wm*32 + mt*16 + gr;
                a[mt][0] = As[ks+gc  ][mr];
                a[mt][1] = As[ks+gc  ][mr+8];
                a[mt][2] = As[ks+gc+4][mr];
                a[mt][3] = As[ks+gc+4][mr+8];
            }
#pragma unroll
            for (int nt = 0; nt < 4; nt++) {
                int nc = wn*32 + nt*8 + gr;
                bfr[nt][0] = Bs[ks+gc  ][nc];
                bfr[nt][1] = Bs[ks+gc+4][nc];
            }
#pragma unroll
            for (int mt = 0; mt < 2; mt++)
#pragma unroll
                for (int nt = 0; nt < 4; nt++)
                    mma_tf32(acc[mt][nt][0], acc[mt][nt][1], acc[mt][nt][2], acc[mt][nt][3],
                             a[mt][0], a[mt][1], a[mt][2], a[mt][3],
                             bfr[nt][0], bfr[nt][1]);
        }
        __syncthreads();
    }

#pragma unroll
    for (int mt = 0; mt < 2; mt++) {
        int r0 = m0 + wm*32 + mt*16 + gr;
        int r1 = r0 + 8;
#pragma unroll
        for (int nt = 0; nt < 4; nt++) {
            int c0 = n0 + wn*32 + nt*8 + gc*2;
            if (r0 < M) {
                if (c0   < N) fused_store(r0, c0,   acc[mt][nt][0]);
                if (c0+1 < N) fused_store(r0, c0+1, acc[mt][nt][1]);
            }
            if (r1 < M) {
                if (c0   < N) fused_store(r1, c0,   acc[mt][nt][2]);
                if (c0+1 < N) fused_store(r1, c0+1, acc[mt][nt][3]);
            }
        }
    }
}

// ---------------- persistent GRU v4: tf32 tensor-core matvec ---------------
// 128 blocks x 512 threads. Per block: 8 j-cols -> 24 gate-cols (N), M=32 (b),
// K=1024 per step. w slice pre-split to tf32 hi/lo in smem ([k][24], conflict-
// free B frags). h staged per 64-k panel (double-buffered, [k][34]) as hi/lo.
// 8 mma warps: (mt in 2) x (kphase in 4); 3-pass split mma (hh+lh+hl).
#define WSZ   24576              // 1024*24 u32 per w array
#define HPAN  2176               // 64*34 u32 per hi/lo panel
#define HBUF  (2*HPAN)           // hi+lo per buffer
#define REDP  33

__global__ void __launch_bounds__(512)
gru_kernel(const float* __restrict__ whh, const float* __restrict__ bhh,
           const int* __restrict__ len)
{
    extern __shared__ uint32_t smu[];
    uint32_t* whi = smu;                 // [1024][24]
    uint32_t* wlo = smu + WSZ;
    uint32_t* hsb = smu + 2*WSZ;         // 2 x (hi[64][34] + lo[64][34])
    float*    red = (float*)hsb;         // aliased: [4*24][33] (consumed pre-barrier)

    int tid  = threadIdx.x;
    int wid  = tid >> 5;
    int lane = tid & 31;
    int gr   = lane >> 2;
    int gc   = lane & 3;
    int b    = lane;                     // for staging/finisher lanes
    int j0   = blockIdx.x*8;

    // ---- one-time: convert w slice to tf32 hi/lo in smem ----
    for (int idx = tid; idx < WSZ; idx += 512) {
        int n = idx >> 10;               // 0..23
        int k = idx & 1023;
        int gate = n >> 3, jl = n & 7;
        float w = whh[((size_t)(gate*H_ + j0 + jl))*H_ + k];
        uint32_t hi = f2tf(w);
        whi[k*24 + n] = hi;
        wlo[k*24 + n] = f2tf(w - __uint_as_float(hi));
    }
    __syncthreads();

    int mt = wid >> 2;                   // 0..1 (valid for wid<8)
    int kp = wid & 3;                    // k-phase 0..3

    int fjl = tid >> 5;                  // finisher j (tid<256): 0..7
    float bR = bhh[j0 + (fjl & 7)];
    float bZ = bhh[H_   + j0 + (fjl & 7)];
    float bN = bhh[2*H_ + j0 + (fjl & 7)];
    int len1 = geti(len, b, g_is64l) - 1;

    int skr = tid >> 5;                  // staging k row base 0..15

    for (int t = 0; t < TS_; t++) {
        const float* hsrc = g_ht[t & 1];

        // prefetch finisher inputs (independent of this step's compute)
        float xr = 0.f, xz = 0.f, xn = 0.f, hp = 0.f;
        if (tid < 256) {
            int j = j0 + fjl;
            const float* xpb = g_xp + (size_t)t*H3_*B_;
            xr = __ldcg(&xpb[(size_t)(      j)*B_ + b]);
            xz = __ldcg(&xpb[(size_t)(H_  + j)*B_ + b]);
            xn = __ldcg(&xpb[(size_t)(2*H_+ j)*B_ + b]);
            hp = __ldcg(&hsrc[j*32 + b]);
        }

        float acc[3][4];
#pragma unroll
        for (int nt = 0; nt < 3; nt++)
#pragma unroll
            for (int e = 0; e < 4; e++) acc[nt][e] = 0.f;

        // prestage panel 0 into buf 0
        {
            uint32_t* hi = hsb;
            uint32_t* lo = hsb + HPAN;
#pragma unroll
            for (int u = 0; u < 4; u++) {
                int kk = skr + u*16;
                float h = __ldcg(&hsrc[kk*32 + b]);
                uint32_t hv = f2tf(h);
                hi[kk*34 + b] = hv;
                lo[kk*34 + b] = f2tf(h - __uint_as_float(hv));
            }
        }
        __syncthreads();

        for (int p = 0; p < 16; p++) {
            if (p + 1 < 16) {
                int buf = (p+1) & 1;
                uint32_t* hi = hsb + buf*HBUF;
                uint32_t* lo = hi + HPAN;
                int k0n = (p+1)*64;
#pragma unroll
                for (int u = 0; u < 4; u++) {
                    int kk = skr + u*16;
                    float h = __ldcg(&hsrc[(k0n + kk)*32 + b]);
                    uint32_t hv = f2tf(h);
                    hi[kk*34 + b] = hv;
                    lo[kk*34 + b] = f2tf(h - __uint_as_float(hv));
                }
            }
            if (wid < 8) {
                int buf = p & 1;
                const uint32_t* hi = hsb + buf*HBUF;
                const uint32_t* lo = hi + HPAN;
                int k0 = p*64;
                int m = mt*16 + gr;
#pragma unroll
                for (int ph = 0; ph < 2; ph++) {
                    int kk = (kp + ph*4) * 8;
                    uint32_t ah0 = hi[(kk+gc  )*34 + m];
                    uint32_t ah1 = hi[(kk+gc  )*34 + m + 8];
                    uint32_t ah2 = hi[(kk+gc+4)*34 + m];
                    uint32_t ah3 = hi[(kk+gc+4)*34 + m + 8];
                    uint32_t al0 = lo[(kk+gc  )*34 + m];
                    uint32_t al1 = lo[(kk+gc  )*34 + m + 8];
                    uint32_t al2 = lo[(kk+gc+4)*34 + m];
                    uint32_t al3 = lo[(kk+gc+4)*34 + m + 8];
#pragma unroll
                    for (int nt = 0; nt < 3; nt++) {
                        int nc = nt*8 + gr;
                        uint32_t bh0 = whi[(k0+kk+gc  )*24 + nc];
                        uint32_t bh1 = whi[(k0+kk+gc+4)*24 + nc];
                        uint32_t bl0 = wlo[(k0+kk+gc  )*24 + nc];
                        uint32_t bl1 = wlo[(k0+kk+gc+4)*24 + nc];
                        mma_tf32(acc[nt][0],acc[nt][1],acc[nt][2],acc[nt][3],
                                 ah0,ah1,ah2,ah3, bh0,bh1);
                        mma_tf32(acc[nt][0],acc[nt][1],acc[nt][2],acc[nt][3],
                                 al0,al1,al2,al3, bh0,bh1);
                        mma_tf32(acc[nt][0],acc[nt][1],acc[nt][2],acc[nt][3],
                                 ah0,ah1,ah2,ah3, bl0,bl1);
                    }
                }
            }
            __syncthreads();
        }

        // epilogue: write partials red[kp*24 + n][m]
        if (wid < 8) {
#pragma unroll
            for (int nt = 0; nt < 3; nt++) {
                int n0 = nt*8 + gc*2;
                int m = mt*16 + gr;
                red[(kp*24 + n0    )*REDP + m    ] = acc[nt][0];
                red[(kp*24 + n0 + 1)*REDP + m    ] = acc[nt][1];
                red[(kp*24 + n0    )*REDP + m + 8] = acc[nt][2];
                red[(kp*24 + n0 + 1)*REDP + m + 8] = acc[nt][3];
            }
        }
        __syncthreads();

        if (tid < 256) {
            int jl = fjl;
            float ar = bR, az = bZ, an = bN;
#pragma unroll
            for (int q = 0; q < 4; q++) {
                ar += red[(q*24 +      jl)*REDP + b];
                az += red[(q*24 +  8 + jl)*REDP + b];
                an += red[(q*24 + 16 + jl)*REDP + b];
            }
            float r  = 1.f / (1.f + __expf(-(xr + ar)));
            float z  = 1.f / (1.f + __expf(-(xz + az)));
            float nn = tanhf(xn + r*an);
            float hnew = (1.f - z)*nn + z*hp;

            int j = j0 + jl;
            int valid = (t < len1);
            __stcg(&g_ht[(t+1) & 1][j*32 + b], valid ? hnew : hp);
            __stcg(&g_out[(size_t)(b*TS_ + t)*H_ + j], valid ? hnew : 0.f);
            __threadfence();
        }
        __syncthreads();
        if (tid == 0) {
            atomicAdd(&g_bar, 1u);
            unsigned goal = (unsigned)gridDim.x * (unsigned)(t+1);
            volatile unsigned* pb = &g_bar;
            while (*pb < goal) {}
            __threadfence();
        }
        __syncthreads();
    }
}

// ---------------- head log-softmax ----------------------------------------
__global__ void __launch_bounds__(128)
head_lse_kernel()
{
    int n = blockIdx.x;
    if (!g_valid[n]) return;
    int tid = threadIdx.x;
    const float* lg = g_headlog + (size_t)n*(C0_+2);
    __shared__ float sm[4];

    float m = -1e30f;
    for (int i = tid; i < C0_+2; i += 128) m = fmaxf(m, lg[i]);
#pragma unroll
    for (int o = 16; o > 0; o >>= 1) m = fmaxf(m, __shfl_xor_sync(~0u, m, o));
    if ((tid & 31) == 0) sm[tid >> 5] = m;
    __syncthreads();
    m = fmaxf(fmaxf(sm[0], sm[1]), fmaxf(sm[2], sm[3]));

    float s = 0.f;
    for (int i = tid; i < C0_+2; i += 128) s += __expf(lg[i] - m);
#pragma unroll
    for (int o = 16; o > 0; o >>= 1) s += __shfl_xor_sync(~0u, s, o);
    if ((tid & 31) == 0) sm[tid >> 5] = s;
    __syncthreads();
    if (tid == 0) {
        s = sm[0] + sm[1] + sm[2] + sm[3];
        int tgt = g_tgt[n];
        int sel = (tgt < C0_) ? tgt : ((tgt < C1_) ? C0_ : C0_+1);
        g_head_lp[n] = lg[sel] - (m + logf(s));
    }
}

// ---------------- tail GEMM in tf32 mma + online logsumexp ----------------
#define TAST 72

template <int KD, int NSLAB>
__global__ void __launch_bounds__(256)
tail_tf32_kernel(const float* __restrict__ tmat, int cluster, int S)
{
    extern __shared__ float smf[];
    uint32_t* As = (uint32_t*)smf;               // [KD][72]
    uint32_t* Bsm = As + KD*TAST;                // [64][72]
    float* Rm = (float*)(Bsm + 64*TAST);         // [64][2]
    float* Rs = Rm + 128;                        // [64][2]

    int cnt = g_cnt[cluster];
    int r0 = blockIdx.y * 64;
    if (r0 >= cnt) return;
    int tid = threadIdx.x;
    const int*   list = cluster ? g_list2 : g_list1;
    const float* proj = cluster ? g_proj2 : g_proj1;

    for (int idx = tid; idx < 64*(KD/4); idx += 256) {
        int r  = idx / (KD/4);
        int k4 = idx % (KD/4);
        float4 v = make_float4(0.f,0.f,0.f,0.f);
        if (r0 + r < cnt) v = *(const float4*)(proj + (size_t)list[r0+r]*KD + k4*4);
        As[(k4*4+0)*TAST + r] = f2tf(v.x);
        As[(k4*4+1)*TAST + r] = f2tf(v.y);
        As[(k4*4+2)*TAST + r] = f2tf(v.z);
        As[(k4*4+3)*TAST + r] = f2tf(v.w);
    }
    __syncthreads();

    int lane = tid & 31, warp = tid >> 5;
    int wm = warp & 3, wn = warp >> 2;
    int gr = lane >> 2, gc = lane & 3;
    int mr = wm*16 + gr;

    float rm0 = -1e30f, rs0 = 0.f, rm1 = -1e30f, rs1 = 0.f;

    const int SLAB = S / NSLAB;
    const int SCH  = SLAB / 64;
    int sbase = blockIdx.x * SLAB;

    int bsrow = tid >> 2;
    int bc4   = tid & 3;

    for (int sc = 0; sc < SCH; sc++) {
        int s0 = sbase + sc*64;
        float acc[4][4];
#pragma unroll
        for (int nt = 0; nt < 4; nt++)
#pragma unroll
            for (int e = 0; e < 4; e++) acc[nt][e] = 0.f;

        for (int kc = 0; kc < KD; kc += 64) {
#pragma unroll
            for (int u = 0; u < 4; u++) {
                int k4 = bc4*4 + u;
                float4 v = *(const float4*)(tmat + (size_t)(s0+bsrow)*KD + kc + k4*4);
                Bsm[(k4*4+0)*TAST + bsrow] = f2tf(v.x);
                Bsm[(k4*4+1)*TAST + bsrow] = f2tf(v.y);
                Bsm[(k4*4+2)*TAST + bsrow] = f2tf(v.z);
                Bsm[(k4*4+3)*TAST + bsrow] = f2tf(v.w);
            }
            __syncthreads();
#pragma unroll
            for (int ks = 0; ks < 64; ks += 8) {
                uint32_t a0 = As[(kc+ks+gc  )*TAST + mr];
                uint32_t a1 = As[(kc+ks+gc  )*TAST + mr + 8];
                uint32_t a2 = As[(kc+ks+gc+4)*TAST + mr];
                uint32_t a3 = As[(kc+ks+gc+4)*TAST + mr + 8];
#pragma unroll
                for (int nt = 0; nt < 4; nt++) {
                    int nc = wn*32 + nt*8 + gr;
                    uint32_t b0 = Bsm[(ks+gc  )*TAST + nc];
                    uint32_t b1 = Bsm[(ks+gc+4)*TAST + nc];
                    mma_tf32(acc[nt][0], acc[nt][1], acc[nt][2], acc[nt][3],
                             a0, a1, a2, a3, b0, b1);
                }
            }
            __syncthreads();
        }

        float vm0 = -1e30f, vm1 = -1e30f;
#pragma unroll
        for (int nt = 0; nt < 4; nt++) {
            vm0 = fmaxf(vm0, fmaxf(acc[nt][0], acc[nt][1]));
            vm1 = fmaxf(vm1, fmaxf(acc[nt][2], acc[nt][3]));
        }
        vm0 = fmaxf(vm0, __shfl_xor_sync(~0u, vm0, 1));
        vm0 = fmaxf(vm0, __shfl_xor_sync(~0u, vm0, 2));
        vm1 = fmaxf(vm1, __shfl_xor_sync(~0u, vm1, 1));
        vm1 = fmaxf(vm1, __shfl_xor_sync(~0u, vm1, 2));
        float vs0 = 0.f, vs1 = 0.f;
#pragma unroll
        for (int nt = 0; nt < 4; nt++) {
            vs0 += __expf(acc[nt][0]-vm0) + __expf(acc[nt][1]-vm0);
            vs1 += __expf(acc[nt][2]-vm1) + __expf(acc[nt][3]-vm1);
        }
        vs0 += __shfl_xor_sync(~0u, vs0, 1);
        vs0 += __shfl_xor_sync(~0u, vs0, 2);
        vs1 += __shfl_xor_sync(~0u, vs1, 1);
        vs1 += __shfl_xor_sync(~0u, vs1, 2);

        float nm0 = fmaxf(rm0, vm0);
        rs0 = rs0*__expf(rm0-nm0) + vs0*__expf(vm0-nm0);
        rm0 = nm0;
        float nm1 = fmaxf(rm1, vm1);
        rs1 = rs1*__expf(rm1-nm1) + vs1*__expf(vm1-nm1);
        rm1 = nm1;
    }

    if (gc == 0) {
        Rm[mr*2 + wn] = rm0;       Rs[mr*2 + wn] = rs0;
        Rm[(mr+8)*2 + wn] = rm1;   Rs[(mr+8)*2 + wn] = rs1;
    }
    __syncthreads();
    if (tid < 64 && r0 + tid < cnt) {
        float m0 = Rm[tid*2], m1 = Rm[tid*2+1];
        float m = fmaxf(m0, m1);
        float s = Rs[tid*2]*__expf(m0-m) + Rs[tid*2+1]*__expf(m1-m);
        g_pmax[cluster][(size_t)(r0+tid)*32 + blockIdx.x] = m;
        g_psum[cluster][(size_t)(r0+tid)*32 + blockIdx.x] = s;
    }
}

// ---------------- combine tail partials + target logit --------------------
__global__ void combine_kernel(const float* __restrict__ t1,
                               const float* __restrict__ t2)
{
    int cl = blockIdx.y;
    int slot = blockIdx.x*256 + threadIdx.x;
    if (slot >= g_cnt[cl]) return;
    int n = cl ? g_list2[slot] : g_list1[slot];
    int tgt = g_tgt[n];
    int KD = cl ? 64 : 256;
    int NS = 25;
    const float* pr = cl ? (g_proj2 + (size_t)n*64) : (g_proj1 + (size_t)n*256);
    const float* tr = cl ? (t2 + (size_t)(tgt - C1_)*64)
                         : (t1 + (size_t)(tgt - C0_)*256);
    float d = 0.f;
    for (int k = 0; k < KD; k++) d = fmaf(pr[k], tr[k], d);

    const float* pm = &g_pmax[cl][(size_t)slot*32];
    const float* ps = &g_psum[cl][(size_t)slot*32];
    float m = -1e30f;
    for (int s = 0; s < NS; s++) m = fmaxf(m, pm[s]);
    float su = 0.f;
    for (int s = 0; s < NS; s++) su += ps[s]*__expf(pm[s]-m);
    g_head_lp[n] += d - (m + logf(su));
}

// ---------------- final reduction + hT output -----------------------------
__global__ void finalize_kernel(float* __restrict__ out)
{
    __shared__ float sh[256];
    int tid = threadIdx.x;
    const float L2002 = logf(2002.0f);
    float acc = 0.f;
    for (int n = tid; n < NR_; n += 256)
        acc += g_valid[n] ? g_head_lp[n] : -L2002;
    sh[tid] = acc; __syncthreads();
    for (int s = 128; s > 0; s >>= 1) {
        if (tid < s) sh[tid] += sh[tid+s];
        __syncthreads();
    }
    if (tid == 0) out[0] = -sh[0] / (float)NR_;
    const float* hf = g_ht[1];            // [k][b] after 127 steps
    for (int i = tid; i < B_*H_; i += 256) {
        int k = i >> 5, b = i & 31;
        out[1 + b*H_ + k] = hf[i];
    }
}

// ---------------- launcher ------------------------------------------------
extern "C" void kernel_launch(void* const* d_in, const int* in_sizes, int n_in,
                              void* d_out, int out_size)
{
    const int*   x      = (const int*)  d_in[0];
    const int*   len    = (const int*)  d_in[1];
    const float* hidden = (const float*)d_in[2];
    const float* emb    = (const float*)d_in[3];
    const float* w_ih   = (const float*)d_in[4];
    const float* w_hh   = (const float*)d_in[5];
    const float* b_ih   = (const float*)d_in[6];
    const float* b_hh   = (const float*)d_in[7];
    const float* head_w = (const float*)d_in[8];
    const float* p1     = (const float*)d_in[9];
    const float* t1     = (const float*)d_in[10];
    const float* p2     = (const float*)d_in[11];
    const float* t2     = (const float*)d_in[12];
    float* out = (float*)d_out;
    (void)in_sizes; (void)n_in; (void)out_size;

    size_t gru_sh = (size_t)(2*WSZ + 2*HBUF)*sizeof(uint32_t);       // 231424 B
    size_t sh_t1  = (size_t)(256*TAST + 64*TAST + 256)*sizeof(uint32_t);
    size_t sh_t2  = (size_t)( 64*TAST + 64*TAST + 256)*sizeof(uint32_t);
    cudaFuncSetAttribute(gru_kernel, cudaFuncAttributeMaxDynamicSharedMemorySize, (int)gru_sh);
    cudaFuncSetAttribute(tail_tf32_kernel<256,25>, cudaFuncAttributeMaxDynamicSharedMemorySize, (int)sh_t1);
    cudaFuncSetAttribute(tail_tf32_kernel<64,25>,  cudaFuncAttributeMaxDynamicSharedMemorySize, (int)sh_t2);

    init_kernel<<<1,256>>>(hidden, x, len);
    classify_kernel<<<(NR_+255)/256,256>>>(x, len);

    // xp = emb[x] @ w_ih^T + b_ih    (M=4064, N=3072, K=512)
    gemm_kernel<0><<<dim3(H3_/BN,(NR_+BM-1)/BM),256>>>(
        w_ih, b_ih, x, emb, len, NR_, H3_, E_);

    gru_kernel<<<H_/8,512,gru_sh>>>(w_hh, b_hh, len);

    // fused head + proj1 + proj2 (M=4064, N=2322, K=1024) — tf32 tensor cores
    gemm_tf32_fused<<<dim3((NFUSE+63)/64,(NR_+127)/128),256>>>(
        head_w, p1, p2, len, NR_, NFUSE, H_);

    head_lse_kernel<<<NR_,128>>>();

    tail_tf32_kernel<256,25><<<dim3(25, (NR_+63)/64),256,sh_t1>>>(t1, 0, S1_);
    tail_tf32_kernel<64,25> <<<dim3(25, (NR_+63)/64),256,sh_t2>>>(t2, 1, S2_);

    combine_kernel<<<dim3((NR_+255)/256,2),256>>>(t1, t2);
    finalize_kernel<<<1,256>>>(out);
}